// round 5
// baseline (speedup 1.0000x reference)
#include <cuda_runtime.h>
#include <cuda_bf16.h>
#include <math.h>
#include <cstdint>

// ---------------------------------------------------------------------------
// Problem constants
// ---------------------------------------------------------------------------
static constexpr int Bb   = 4;
static constexpr int Nn   = 2304;      // 48*48
static constexpr int Cc   = 256;
static constexpr int NH   = 8;
static constexpr int HD   = 32;
static constexpr int HS   = 48;
static constexpr int HID  = 4 * Cc;    // 1024
static constexpr int ROWS = Bb * Nn;   // 9216
static constexpr float SCALE = 0.17677669529663687f; // 32^-0.5

// Neighbor offsets with dy*dy+dx*dx <= 9  (29 of them)
__constant__ int c_dy[29] = {-3,-2,-2,-2,-2,-2,-1,-1,-1,-1,-1, 0,0,0,0,0,0,0, 1,1,1,1,1, 2,2,2,2,2, 3};
__constant__ int c_dx[29] = { 0,-2,-1, 0, 1, 2,-2,-1, 0, 1, 2,-3,-2,-1,0,1,2,3,-2,-1,0,1,2,-2,-1,0,1,2, 0};

// ---------------------------------------------------------------------------
// Scratch (no cudaMalloc allowed)
// ---------------------------------------------------------------------------
using bf = __nv_bfloat16;
__device__ __align__(16) bf g_h_hi  [ROWS * Cc];
__device__ __align__(16) bf g_h_lo  [ROWS * Cc];
__device__ __align__(16) bf g_hk_hi [ROWS * Cc];
__device__ __align__(16) bf g_hk_lo [ROWS * Cc];
__device__ __align__(16) float g_q  [ROWS * Cc];
__device__ __align__(16) float g_kv [ROWS * 2 * Cc];     // fused K|V, stride 512
__device__ __align__(16) bf g_at_hi [ROWS * Cc];
__device__ __align__(16) bf g_at_lo [ROWS * Cc];
__device__ __align__(16) float g_x2 [ROWS * Cc];
__device__ __align__(16) bf g_m_hi  [ROWS * Cc];
__device__ __align__(16) bf g_m_lo  [ROWS * Cc];
__device__ __align__(16) bf g_t_hi  [ROWS * HID];
__device__ __align__(16) bf g_t_lo  [ROWS * HID];
// transposed + split weights: [N, K] layout
__device__ __align__(16) bf g_wq_hi [Cc * Cc];
__device__ __align__(16) bf g_wq_lo [Cc * Cc];
__device__ __align__(16) bf g_wkv_hi[2 * Cc * Cc];       // rows 0..255 = Wk^T, 256..511 = Wv^T
__device__ __align__(16) bf g_wkv_lo[2 * Cc * Cc];
__device__ __align__(16) bf g_wp_hi [Cc * Cc];
__device__ __align__(16) bf g_wp_lo [Cc * Cc];
__device__ __align__(16) bf g_w1_hi [HID * Cc];
__device__ __align__(16) bf g_w1_lo [HID * Cc];
__device__ __align__(16) bf g_w2_hi [Cc * HID];
__device__ __align__(16) bf g_w2_lo [Cc * HID];
__device__ __align__(16) float g_bkv[2 * Cc];            // bk | bv

// ---------------------------------------------------------------------------
// PTX helpers (base-ISA only: mma.sync / ldmatrix / cp.async)
// ---------------------------------------------------------------------------
__device__ __forceinline__ uint32_t smem_u32(const void* p) {
    uint32_t a;
    asm("{ .reg .u64 t; cvta.to.shared.u64 t, %1; cvt.u32.u64 %0, t; }" : "=r"(a) : "l"(p));
    return a;
}
__device__ __forceinline__ void ldsm_x4(uint32_t* r, uint32_t addr) {
    asm volatile("ldmatrix.sync.aligned.m8n8.x4.shared.b16 {%0,%1,%2,%3}, [%4];"
        : "=r"(r[0]), "=r"(r[1]), "=r"(r[2]), "=r"(r[3]) : "r"(addr));
}
__device__ __forceinline__ void mma16816(float* d, const uint32_t* a, uint32_t b0, uint32_t b1) {
    asm volatile("mma.sync.aligned.m16n8k16.row.col.f32.bf16.bf16.f32 "
        "{%0,%1,%2,%3}, {%4,%5,%6,%7}, {%8,%9}, {%0,%1,%2,%3};"
        : "+f"(d[0]), "+f"(d[1]), "+f"(d[2]), "+f"(d[3])
        : "r"(a[0]), "r"(a[1]), "r"(a[2]), "r"(a[3]), "r"(b0), "r"(b1));
}
#define CP16(dst, src) \
    asm volatile("cp.async.cg.shared.global [%0], [%1], 16;" :: "r"(dst), "l"(src))
#define CP_COMMIT()  asm volatile("cp.async.commit_group;" ::: "memory")
#define CP_WAITG(n)  asm volatile("cp.async.wait_group %0;" :: "n"(n) : "memory")

// ---------------------------------------------------------------------------
// All-in-one weight transpose + bf16 hi/lo split (coalesced, smem-tiled).
// W[K,N] f32 -> T_hi/T_lo [N,K] bf16.  One 32x32 tile per block.
// ---------------------------------------------------------------------------
__global__ void __launch_bounds__(256) convw_all(
    const float* __restrict__ Wq, const float* __restrict__ Wk,
    const float* __restrict__ Wv, const float* __restrict__ Wp,
    const float* __restrict__ W1, const float* __restrict__ W2,
    bf* qh, bf* ql, bf* kh, bf* kl, bf* vh, bf* vl,
    bf* ph, bf* pl, bf* h1h, bf* h1l, bf* h2h, bf* h2l)
{
    __shared__ float t[32][33];
    int bid = blockIdx.x;
    const float* W; bf* Th; bf* Tl; int K, N, tile;
    if (bid < 256) {
        int w = bid >> 6; tile = bid & 63; K = 256; N = 256;
        if      (w == 0) { W = Wq; Th = qh; Tl = ql; }
        else if (w == 1) { W = Wk; Th = kh; Tl = kl; }
        else if (w == 2) { W = Wv; Th = vh; Tl = vl; }
        else             { W = Wp; Th = ph; Tl = pl; }
    } else if (bid < 512) {
        W = W1; Th = h1h; Tl = h1l; K = 256; N = 1024; tile = bid - 256;
    } else {
        W = W2; Th = h2h; Tl = h2l; K = 1024; N = 256; tile = bid - 512;
    }
    int ntn = N >> 5;
    int tk = tile / ntn, tn = tile % ntn;
    int tx = threadIdx.x & 31, ty = threadIdx.x >> 5;
#pragma unroll
    for (int i = 0; i < 4; i++) {
        int r = ty + i * 8;
        t[r][tx] = W[(size_t)(tk * 32 + r) * N + tn * 32 + tx];
    }
    __syncthreads();
#pragma unroll
    for (int i = 0; i < 4; i++) {
        int r = ty + i * 8;
        float wv = t[tx][r];
        size_t o = (size_t)(tn * 32 + r) * K + tk * 32 + tx;
        bf h = __float2bfloat16(wv);
        Th[o] = h;
        Tl[o] = __float2bfloat16(wv - __bfloat162float(h));
    }
}

// ---------------------------------------------------------------------------
// LayerNorm: one warp per row of 256; emits bf16 hi/lo
// ---------------------------------------------------------------------------
__global__ void ln_kernel(const float* __restrict__ x,
                          const float* __restrict__ g,
                          const float* __restrict__ b,
                          bf* __restrict__ oh, bf* __restrict__ ol, int rows)
{
    int gw   = (blockIdx.x * blockDim.x + threadIdx.x) >> 5;
    int lane = threadIdx.x & 31;
    if (gw >= rows) return;
    const float* xr = x + (size_t)gw * Cc;
    float f[8], s = 0.f, ss = 0.f;
#pragma unroll
    for (int i = 0; i < 8; i++) {
        f[i] = xr[lane + 32 * i];
        s  += f[i];
        ss += f[i] * f[i];
    }
#pragma unroll
    for (int off = 16; off; off >>= 1) {
        s  += __shfl_xor_sync(0xffffffffu, s,  off);
        ss += __shfl_xor_sync(0xffffffffu, ss, off);
    }
    float mu  = s * (1.f / 256.f);
    float var = ss * (1.f / 256.f) - mu * mu;
    float inv = rsqrtf(var + 1e-6f);
    size_t base = (size_t)gw * Cc;
#pragma unroll
    for (int i = 0; i < 8; i++) {
        int c = lane + 32 * i;
        float v = (f[i] - mu) * inv * g[c] + b[c];
        bf hv = __float2bfloat16(v);
        oh[base + c] = hv;
        ol[base + c] = __float2bfloat16(v - __bfloat162float(hv));
    }
}

// ---------------------------------------------------------------------------
// Sparse (radius-3) attention: one warp per (b, n, head); emits bf16 hi/lo.
// k/v come fused from the KV GEMM: row stride 512, k at +0, v at +256.
// ---------------------------------------------------------------------------
__global__ void attn_kernel(const float* __restrict__ q,
                            const float* __restrict__ kv,
                            bf* __restrict__ oh, bf* __restrict__ ol)
{
    int gw   = (blockIdx.x * blockDim.x + threadIdx.x) >> 5;
    int lane = threadIdx.x & 31;
    if (gw >= Bb * Nn * NH) return;

    int h = gw & (NH - 1);
    int n = (gw >> 3) % Nn;
    int b = gw / (NH * Nn);
    int y = n / HS, xq = n % HS;

    size_t qoff = ((size_t)(b * Nn + n)) * Cc + h * HD + lane;
    float qv = q[qoff];

    float mx = -1e30f, l = 0.f, acc = 0.f;
#pragma unroll
    for (int j = 0; j < 29; j++) {
        int ny = y + c_dy[j];
        int nx = xq + c_dx[j];
        if ((unsigned)ny < (unsigned)HS && (unsigned)nx < (unsigned)HS) {
            size_t base = ((size_t)(b * Nn + ny * HS + nx)) * (2 * Cc) + h * HD + lane;
            float s = qv * kv[base];
#pragma unroll
            for (int off = 16; off; off >>= 1)
                s += __shfl_xor_sync(0xffffffffu, s, off);
            s *= SCALE;
            float nm = fmaxf(mx, s);
            float corr = expf(mx - nm);
            float p = expf(s - nm);
            l = l * corr + p;
            acc = acc * corr + p * kv[base + Cc];
            mx = nm;
        }
    }
    float res = acc / l;
    bf hv = __float2bfloat16(res);
    oh[qoff] = hv;
    ol[qoff] = __float2bfloat16(res - __bfloat162float(hv));
}

// ---------------------------------------------------------------------------
// Split-bf16 GEMM via mma.sync (HMMA).
// C[M,N] = (Ah+Al)[M,K] @ (Bh+Bl)^T[N,K]   (Al*Bl dropped)
// CTA tile 128x128, 8 warps (2x4), warp tile 64x32, BK=32,
// 3-stage cp.async pipeline, hi/lo packed in one 128B swizzled row.
// smem = 3 x 32KB = 96KB -> 2 CTAs/SM.
// Row layout: granule g in [0,8): g<4 = hi k-granule g, g>=4 = lo k-granule g-4.
// EPI: 0 -> Co = acc+bias ; 1 -> Co = acc+bias+res ; 2 -> gelu -> bf16 hi/lo
// ---------------------------------------------------------------------------
static constexpr int STGB  = 32768;       // A 16K | B 16K per stage
static constexpr int SMTOT = 3 * STGB;    // 96 KB

template <int EPI>
__global__ void __launch_bounds__(256, 2) mma_gemm(
    const bf* __restrict__ Ah, const bf* __restrict__ Al,
    const bf* __restrict__ Bh, const bf* __restrict__ Bl,
    const float* __restrict__ bias, const float* __restrict__ res,
    float* __restrict__ Co, bf* __restrict__ oH, bf* __restrict__ oL,
    int M, int N, int K)
{
    extern __shared__ __align__(1024) char smc[];
    const uint32_t sbase = smem_u32(smc);
    const int tid  = threadIdx.x;
    const int lane = tid & 31;
    const int wid  = tid >> 5;
    const int tm = blockIdx.y, tn = blockIdx.x;
    const int wm = wid >> 2, wn = wid & 3;   // 2 x 4 warp grid, warp tile 64x32

    const size_t strK = (size_t)K * 2;       // bytes per row
    const char* pAh = (const char*)Ah + ((size_t)tm * 128) * strK;
    const char* pAl = (const char*)Al + ((size_t)tm * 128) * strK;
    const char* pBh = (const char*)Bh + ((size_t)tn * 128) * strK;
    const char* pBl = (const char*)Bl + ((size_t)tn * 128) * strK;

    const int nCh = K >> 5;                  // chunks of 32

    // ---- async stage loader: A and B each 128 rows x 8 granules (hi|lo packed)
    auto load_stage = [&](int stg, int ch) {
        uint32_t d0 = sbase + stg * STGB;
        size_t koff = (size_t)ch * 64;       // 32 bf16 = 64 B
#pragma unroll
        for (int i = 0; i < 4; i++) {
            int g = i * 256 + tid;
            int r = g >> 3, c = g & 7;
            const char* src = (c < 4) ? (pAh + (size_t)r * strK + koff + (c << 4))
                                      : (pAl + (size_t)r * strK + koff + ((c - 4) << 4));
            uint32_t dst = d0 + (r << 7) + ((c ^ (r & 7)) << 4);
            CP16(dst, src);
        }
#pragma unroll
        for (int i = 0; i < 4; i++) {
            int g = i * 256 + tid;
            int r = g >> 3, c = g & 7;
            const char* src = (c < 4) ? (pBh + (size_t)r * strK + koff + (c << 4))
                                      : (pBl + (size_t)r * strK + koff + ((c - 4) << 4));
            uint32_t dst = d0 + 16384 + (r << 7) + ((c ^ (r & 7)) << 4);
            CP16(dst, src);
        }
        CP_COMMIT();
    };

    const int rl = lane & 15;       // row within 16-row group
    const int kc = lane >> 4;       // k half (0/1) within k16

    float acc[4][4][4] = {};

    load_stage(0, 0);
    load_stage(1, 1);

    int stg = 0;
    for (int ch = 0; ch < nCh; ch++) {
        if (ch + 2 < nCh) { load_stage((stg + 2) % 3, ch + 2); CP_WAITG(2); }
        else if (ch + 1 < nCh) { CP_WAITG(1); }
        else { CP_WAITG(0); }
        __syncthreads();

        uint32_t aB = sbase + stg * STGB;
        uint32_t bB = aB + 16384;

#pragma unroll
        for (int k16 = 0; k16 < 2; k16++) {
            const int gh = k16 * 2 + kc;       // hi granule
            const int gl = 4 + k16 * 2 + kc;   // lo granule
            uint32_t ah[4][4], al[4][4], bh[2][4], bl[2][4];
#pragma unroll
            for (int f = 0; f < 4; f++) {
                int rA = wm * 64 + f * 16 + rl;
                uint32_t rb = aB + (rA << 7);
                int rx = rA & 7;
                ldsm_x4(ah[f], rb + ((gh ^ rx) << 4));
                ldsm_x4(al[f], rb + ((gl ^ rx) << 4));
            }
            {
                int rB0 = wn * 32 + rl, rB1 = wn * 32 + 16 + rl;
                uint32_t rb0 = bB + (rB0 << 7), rb1 = bB + (rB1 << 7);
                int rx0 = rB0 & 7, rx1 = rB1 & 7;
                ldsm_x4(bh[0], rb0 + ((gh ^ rx0) << 4));
                ldsm_x4(bh[1], rb1 + ((gh ^ rx1) << 4));
                ldsm_x4(bl[0], rb0 + ((gl ^ rx0) << 4));
                ldsm_x4(bl[1], rb1 + ((gl ^ rx1) << 4));
            }
#pragma unroll
            for (int f = 0; f < 4; f++)
#pragma unroll
                for (int j = 0; j < 4; j++)
                    mma16816(acc[f][j], ah[f], bh[j >> 1][j & 1], bh[j >> 1][2 + (j & 1)]);
#pragma unroll
            for (int f = 0; f < 4; f++)
#pragma unroll
                for (int j = 0; j < 4; j++)
                    mma16816(acc[f][j], al[f], bh[j >> 1][j & 1], bh[j >> 1][2 + (j & 1)]);
#pragma unroll
            for (int f = 0; f < 4; f++)
#pragma unroll
                for (int j = 0; j < 4; j++)
                    mma16816(acc[f][j], ah[f], bl[j >> 1][j & 1], bl[j >> 1][2 + (j & 1)]);
        }
        __syncthreads();
        stg = (stg + 1) % 3;
    }

    // ---- epilogue -----------------------------------------------------------
    const int rbase = tm * 128 + wm * 64 + (lane >> 2);
    const int cbase = tn * 128 + wn * 32 + (lane & 3) * 2;
#pragma unroll
    for (int f = 0; f < 4; f++) {
#pragma unroll
        for (int j = 0; j < 4; j++) {
            int row0 = rbase + f * 16;
            int col  = cbase + j * 8;
            float b0 = bias[col], b1 = bias[col + 1];
            float v00 = acc[f][j][0] + b0;
            float v01 = acc[f][j][1] + b1;
            float v10 = acc[f][j][2] + b0;
            float v11 = acc[f][j][3] + b1;
            size_t i0 = (size_t)row0 * N + col;
            size_t i1 = (size_t)(row0 + 8) * N + col;
            if (EPI == 0) {
                *(float2*)(Co + i0) = make_float2(v00, v01);
                *(float2*)(Co + i1) = make_float2(v10, v11);
            } else if (EPI == 1) {
                float2 r0 = *(const float2*)(res + i0);
                float2 r1 = *(const float2*)(res + i1);
                *(float2*)(Co + i0) = make_float2(v00 + r0.x, v01 + r0.y);
                *(float2*)(Co + i1) = make_float2(v10 + r1.x, v11 + r1.y);
            } else {
                const float IS2 = 0.70710678118654752f;
                v00 = 0.5f * v00 * (1.f + erff(v00 * IS2));
                v01 = 0.5f * v01 * (1.f + erff(v01 * IS2));
                v10 = 0.5f * v10 * (1.f + erff(v10 * IS2));
                v11 = 0.5f * v11 * (1.f + erff(v11 * IS2));
                bf h00 = __float2bfloat16(v00), h01 = __float2bfloat16(v01);
                bf h10 = __float2bfloat16(v10), h11 = __float2bfloat16(v11);
                __nv_bfloat162 hh0; hh0.x = h00; hh0.y = h01;
                __nv_bfloat162 hh1; hh1.x = h10; hh1.y = h11;
                *(__nv_bfloat162*)(oH + i0) = hh0;
                *(__nv_bfloat162*)(oH + i1) = hh1;
                __nv_bfloat162 ll0, ll1;
                ll0.x = __float2bfloat16(v00 - __bfloat162float(h00));
                ll0.y = __float2bfloat16(v01 - __bfloat162float(h01));
                ll1.x = __float2bfloat16(v10 - __bfloat162float(h10));
                ll1.y = __float2bfloat16(v11 - __bfloat162float(h11));
                *(__nv_bfloat162*)(oL + i0) = ll0;
                *(__nv_bfloat162*)(oL + i1) = ll1;
            }
        }
    }
}

// ---------------------------------------------------------------------------
// Launch
// ---------------------------------------------------------------------------
template <typename T>
static T* symaddr(const void* sym)
{
    void* p = nullptr;
    cudaGetSymbolAddress(&p, sym);
    return (T*)p;
}

extern "C" void kernel_launch(void* const* d_in, const int* in_sizes, int n_in,
                              void* d_out, int out_size)
{
    const float* x    = (const float*)d_in[0];
    const float* x_kv = (const float*)d_in[1];
    const float* Wq   = (const float*)d_in[2];
    const float* bq   = (const float*)d_in[3];
    const float* Wk   = (const float*)d_in[4];
    const float* bk   = (const float*)d_in[5];
    const float* Wv   = (const float*)d_in[6];
    const float* bv   = (const float*)d_in[7];
    const float* Wp   = (const float*)d_in[8];
    const float* bp   = (const float*)d_in[9];
    const float* g1   = (const float*)d_in[10];
    const float* b1   = (const float*)d_in[11];
    const float* g2   = (const float*)d_in[12];
    const float* b2   = (const float*)d_in[13];
    const float* W1   = (const float*)d_in[14];
    const float* bm1  = (const float*)d_in[15];
    const float* W2   = (const float*)d_in[16];
    const float* bm2  = (const float*)d_in[17];
    float* out = (float*)d_out;

    bf* h_hi  = symaddr<bf>(g_h_hi);   bf* h_lo  = symaddr<bf>(g_h_lo);
    bf* hk_hi = symaddr<bf>(g_hk_hi);  bf* hk_lo = symaddr<bf>(g_hk_lo);
    float* qb  = symaddr<float>(g_q);
    float* kvb = symaddr<float>(g_kv);
    bf* at_hi = symaddr<bf>(g_at_hi);  bf* at_lo = symaddr<bf>(g_at_lo);
    float* x2 = symaddr<float>(g_x2);
    bf* m_hi  = symaddr<bf>(g_m_hi);   bf* m_lo  = symaddr<bf>(g_m_lo);
    bf* t_hi  = symaddr<bf>(g_t_hi);   bf* t_lo  = symaddr<bf>(g_t_lo);
    bf* wq_hi  = symaddr<bf>(g_wq_hi);  bf* wq_lo  = symaddr<bf>(g_wq_lo);
    bf* wkv_hi = symaddr<bf>(g_wkv_hi); bf* wkv_lo = symaddr<bf>(g_wkv_lo);
    bf* wp_hi  = symaddr<bf>(g_wp_hi);  bf* wp_lo  = symaddr<bf>(g_wp_lo);
    bf* w1_hi  = symaddr<bf>(g_w1_hi);  bf* w1_lo  = symaddr<bf>(g_w1_lo);
    bf* w2_hi  = symaddr<bf>(g_w2_hi);  bf* w2_lo  = symaddr<bf>(g_w2_lo);
    float* bkv = symaddr<float>(g_bkv);

    static bool attrSet = false;
    if (!attrSet) {
        cudaFuncSetAttribute(mma_gemm<0>, cudaFuncAttributeMaxDynamicSharedMemorySize, SMTOT);
        cudaFuncSetAttribute(mma_gemm<1>, cudaFuncAttributeMaxDynamicSharedMemorySize, SMTOT);
        cudaFuncSetAttribute(mma_gemm<2>, cudaFuncAttributeMaxDynamicSharedMemorySize, SMTOT);
        attrSet = true;
    }

    // Concatenated KV bias (capturable D2D copies)
    cudaMemcpyAsync(bkv,      bk, Cc * sizeof(float), cudaMemcpyDeviceToDevice);
    cudaMemcpyAsync(bkv + Cc, bv, Cc * sizeof(float), cudaMemcpyDeviceToDevice);

    // Weight transpose + split: one launch; Wk/Wv go into fused [512,256] buffer
    convw_all<<<768, 256>>>(Wq, Wk, Wv, Wp, W1, W2,
                            wq_hi, wq_lo,
                            wkv_hi, wkv_lo,                        // Wk -> rows 0..255
                            wkv_hi + Cc * Cc, wkv_lo + Cc * Cc,    // Wv -> rows 256..511
                            wp_hi, wp_lo, w1_hi, w1_lo, w2_hi, w2_lo);

    // LN1 on x and x_kv (-> bf16 hi/lo)
    {
        int blocks = ROWS / 8;
        ln_kernel<<<blocks, 256>>>(x,    g1, b1, h_hi,  h_lo,  ROWS);
        ln_kernel<<<blocks, 256>>>(x_kv, g1, b1, hk_hi, hk_lo, ROWS);
    }

    // Q projection (N=256) and fused KV projection (N=512)
    {
        dim3 gq(Cc / 128, ROWS / 128);
        mma_gemm<0><<<gq, 256, SMTOT>>>(h_hi, h_lo, wq_hi, wq_lo, bq, nullptr, qb, nullptr, nullptr, ROWS, Cc, Cc);
        dim3 gkv(2 * Cc / 128, ROWS / 128);
        mma_gemm<0><<<gkv, 256, SMTOT>>>(hk_hi, hk_lo, wkv_hi, wkv_lo, bkv, nullptr, kvb, nullptr, nullptr, ROWS, 2 * Cc, Cc);
    }

    // Sparse local attention (-> bf16 hi/lo)
    {
        int totalWarps = Bb * Nn * NH;  // 73728
        attn_kernel<<<totalWarps / 8, 256>>>(qb, kvb, at_hi, at_lo);
    }

    // x2 = x + att @ Wp + bp
    {
        dim3 grid(Cc / 128, ROWS / 128);
        mma_gemm<1><<<grid, 256, SMTOT>>>(at_hi, at_lo, wp_hi, wp_lo, bp, x, x2, nullptr, nullptr, ROWS, Cc, Cc);
    }

    // LN2 (-> bf16 hi/lo)
    ln_kernel<<<ROWS / 8, 256>>>(x2, g2, b2, m_hi, m_lo, ROWS);

    // MLP: t = gelu(m @ W1 + bm1) (-> bf16 hi/lo); out = x2 + t @ W2 + bm2
    {
        dim3 grid1(HID / 128, ROWS / 128);
        mma_gemm<2><<<grid1, 256, SMTOT>>>(m_hi, m_lo, w1_hi, w1_lo, bm1, nullptr, nullptr, t_hi, t_lo, ROWS, HID, Cc);
        dim3 grid2(Cc / 128, ROWS / 128);
        mma_gemm<1><<<grid2, 256, SMTOT>>>(t_hi, t_lo, w2_hi, w2_lo, bm2, x2, out, nullptr, nullptr, ROWS, Cc, HID);
    }
}

// round 6
// speedup vs baseline: 1.1205x; 1.1205x over previous
#include <cuda_runtime.h>
#include <cuda_bf16.h>
#include <math.h>
#include <cstdint>

// ---------------------------------------------------------------------------
// Problem constants
// ---------------------------------------------------------------------------
static constexpr int Bb   = 4;
static constexpr int Nn   = 2304;      // 48*48
static constexpr int Cc   = 256;
static constexpr int NH   = 8;
static constexpr int HD   = 32;
static constexpr int HS   = 48;
static constexpr int HID  = 4 * Cc;    // 1024
static constexpr int ROWS = Bb * Nn;   // 9216
static constexpr float SCALE = 0.17677669529663687f; // 32^-0.5

// Neighbor offsets with dy*dy+dx*dx <= 9  (29 of them)
__constant__ int c_dy[29] = {-3,-2,-2,-2,-2,-2,-1,-1,-1,-1,-1, 0,0,0,0,0,0,0, 1,1,1,1,1, 2,2,2,2,2, 3};
__constant__ int c_dx[29] = { 0,-2,-1, 0, 1, 2,-2,-1, 0, 1, 2,-3,-2,-1,0,1,2,3,-2,-1,0,1,2,-2,-1,0,1,2, 0};

// ---------------------------------------------------------------------------
// Scratch (no cudaMalloc allowed)
// ---------------------------------------------------------------------------
using bf = __nv_bfloat16;
__device__ __align__(16) bf g_h_hi  [ROWS * Cc];
__device__ __align__(16) bf g_h_lo  [ROWS * Cc];
__device__ __align__(16) bf g_hk_hi [ROWS * Cc];
__device__ __align__(16) bf g_hk_lo [ROWS * Cc];
__device__ __align__(16) float g_q  [ROWS * Cc];
__device__ __align__(16) float g_kv [ROWS * 2 * Cc];     // fused K|V, stride 512
__device__ __align__(16) bf g_at_hi [ROWS * Cc];
__device__ __align__(16) bf g_at_lo [ROWS * Cc];
__device__ __align__(16) float g_x2 [ROWS * Cc];
__device__ __align__(16) bf g_m_hi  [ROWS * Cc];
__device__ __align__(16) bf g_m_lo  [ROWS * Cc];
__device__ __align__(16) bf g_t_hi  [ROWS * HID];
__device__ __align__(16) bf g_t_lo  [ROWS * HID];
// transposed + split weights: [N, K] layout
__device__ __align__(16) bf g_wq_hi [Cc * Cc];
__device__ __align__(16) bf g_wq_lo [Cc * Cc];
__device__ __align__(16) bf g_wkv_hi[2 * Cc * Cc];       // rows 0..255 = Wk^T, 256..511 = Wv^T
__device__ __align__(16) bf g_wkv_lo[2 * Cc * Cc];
__device__ __align__(16) bf g_wp_hi [Cc * Cc];
__device__ __align__(16) bf g_wp_lo [Cc * Cc];
__device__ __align__(16) bf g_w1_hi [HID * Cc];
__device__ __align__(16) bf g_w1_lo [HID * Cc];
__device__ __align__(16) bf g_w2_hi [Cc * HID];
__device__ __align__(16) bf g_w2_lo [Cc * HID];
__device__ __align__(16) float g_bkv[2 * Cc];            // bk | bv

// ---------------------------------------------------------------------------
// PTX helpers (base-ISA only: mma.sync / ldmatrix / cp.async)
// ---------------------------------------------------------------------------
__device__ __forceinline__ uint32_t smem_u32(const void* p) {
    uint32_t a;
    asm("{ .reg .u64 t; cvta.to.shared.u64 t, %1; cvt.u32.u64 %0, t; }" : "=r"(a) : "l"(p));
    return a;
}
__device__ __forceinline__ void ldsm_x4(uint32_t* r, uint32_t addr) {
    asm volatile("ldmatrix.sync.aligned.m8n8.x4.shared.b16 {%0,%1,%2,%3}, [%4];"
        : "=r"(r[0]), "=r"(r[1]), "=r"(r[2]), "=r"(r[3]) : "r"(addr));
}
__device__ __forceinline__ void mma16816(float* d, const uint32_t* a, uint32_t b0, uint32_t b1) {
    asm volatile("mma.sync.aligned.m16n8k16.row.col.f32.bf16.bf16.f32 "
        "{%0,%1,%2,%3}, {%4,%5,%6,%7}, {%8,%9}, {%0,%1,%2,%3};"
        : "+f"(d[0]), "+f"(d[1]), "+f"(d[2]), "+f"(d[3])
        : "r"(a[0]), "r"(a[1]), "r"(a[2]), "r"(a[3]), "r"(b0), "r"(b1));
}
#define CP16(dst, src) \
    asm volatile("cp.async.cg.shared.global [%0], [%1], 16;" :: "r"(dst), "l"(src))
#define CP_COMMIT()  asm volatile("cp.async.commit_group;" ::: "memory")
#define CP_WAITG(n)  asm volatile("cp.async.wait_group %0;" :: "n"(n) : "memory")

// ---------------------------------------------------------------------------
// All-in-one weight transpose + bf16 hi/lo split (coalesced, smem-tiled).
// W[K,N] f32 -> T_hi/T_lo [N,K] bf16.  One 32x32 tile per block.
// ---------------------------------------------------------------------------
__global__ void __launch_bounds__(256) convw_all(
    const float* __restrict__ Wq, const float* __restrict__ Wk,
    const float* __restrict__ Wv, const float* __restrict__ Wp,
    const float* __restrict__ W1, const float* __restrict__ W2,
    bf* qh, bf* ql, bf* kh, bf* kl, bf* vh, bf* vl,
    bf* ph, bf* pl, bf* h1h, bf* h1l, bf* h2h, bf* h2l)
{
    __shared__ float t[32][33];
    int bid = blockIdx.x;
    const float* W; bf* Th; bf* Tl; int K, N, tile;
    if (bid < 256) {
        int w = bid >> 6; tile = bid & 63; K = 256; N = 256;
        if      (w == 0) { W = Wq; Th = qh; Tl = ql; }
        else if (w == 1) { W = Wk; Th = kh; Tl = kl; }
        else if (w == 2) { W = Wv; Th = vh; Tl = vl; }
        else             { W = Wp; Th = ph; Tl = pl; }
    } else if (bid < 512) {
        W = W1; Th = h1h; Tl = h1l; K = 256; N = 1024; tile = bid - 256;
    } else {
        W = W2; Th = h2h; Tl = h2l; K = 1024; N = 256; tile = bid - 512;
    }
    int ntn = N >> 5;
    int tk = tile / ntn, tn = tile % ntn;
    int tx = threadIdx.x & 31, ty = threadIdx.x >> 5;
#pragma unroll
    for (int i = 0; i < 4; i++) {
        int r = ty + i * 8;
        t[r][tx] = W[(size_t)(tk * 32 + r) * N + tn * 32 + tx];
    }
    __syncthreads();
#pragma unroll
    for (int i = 0; i < 4; i++) {
        int r = ty + i * 8;
        float wv = t[tx][r];
        size_t o = (size_t)(tn * 32 + r) * K + tk * 32 + tx;
        bf h = __float2bfloat16(wv);
        Th[o] = h;
        Tl[o] = __float2bfloat16(wv - __bfloat162float(h));
    }
}

// ---------------------------------------------------------------------------
// LayerNorm: one warp per row of 256; emits bf16 hi/lo
// ---------------------------------------------------------------------------
__global__ void ln_kernel(const float* __restrict__ x,
                          const float* __restrict__ g,
                          const float* __restrict__ b,
                          bf* __restrict__ oh, bf* __restrict__ ol, int rows)
{
    int gw   = (blockIdx.x * blockDim.x + threadIdx.x) >> 5;
    int lane = threadIdx.x & 31;
    if (gw >= rows) return;
    const float* xr = x + (size_t)gw * Cc;
    float f[8], s = 0.f, ss = 0.f;
#pragma unroll
    for (int i = 0; i < 8; i++) {
        f[i] = xr[lane + 32 * i];
        s  += f[i];
        ss += f[i] * f[i];
    }
#pragma unroll
    for (int off = 16; off; off >>= 1) {
        s  += __shfl_xor_sync(0xffffffffu, s,  off);
        ss += __shfl_xor_sync(0xffffffffu, ss, off);
    }
    float mu  = s * (1.f / 256.f);
    float var = ss * (1.f / 256.f) - mu * mu;
    float inv = rsqrtf(var + 1e-6f);
    size_t base = (size_t)gw * Cc;
#pragma unroll
    for (int i = 0; i < 8; i++) {
        int c = lane + 32 * i;
        float v = (f[i] - mu) * inv * g[c] + b[c];
        bf hv = __float2bfloat16(v);
        oh[base + c] = hv;
        ol[base + c] = __float2bfloat16(v - __bfloat162float(hv));
    }
}

// ---------------------------------------------------------------------------
// Sparse (radius-3) attention: one warp per (b, n, head); emits bf16 hi/lo.
// k/v come fused from the KV GEMM: row stride 512, k at +0, v at +256.
// ---------------------------------------------------------------------------
__global__ void attn_kernel(const float* __restrict__ q,
                            const float* __restrict__ kv,
                            bf* __restrict__ oh, bf* __restrict__ ol)
{
    int gw   = (blockIdx.x * blockDim.x + threadIdx.x) >> 5;
    int lane = threadIdx.x & 31;
    if (gw >= Bb * Nn * NH) return;

    int h = gw & (NH - 1);
    int n = (gw >> 3) % Nn;
    int b = gw / (NH * Nn);
    int y = n / HS, xq = n % HS;

    size_t qoff = ((size_t)(b * Nn + n)) * Cc + h * HD + lane;
    float qv = q[qoff];

    float mx = -1e30f, l = 0.f, acc = 0.f;
#pragma unroll
    for (int j = 0; j < 29; j++) {
        int ny = y + c_dy[j];
        int nx = xq + c_dx[j];
        if ((unsigned)ny < (unsigned)HS && (unsigned)nx < (unsigned)HS) {
            size_t base = ((size_t)(b * Nn + ny * HS + nx)) * (2 * Cc) + h * HD + lane;
            float s = qv * kv[base];
#pragma unroll
            for (int off = 16; off; off >>= 1)
                s += __shfl_xor_sync(0xffffffffu, s, off);
            s *= SCALE;
            float nm = fmaxf(mx, s);
            float corr = expf(mx - nm);
            float p = expf(s - nm);
            l = l * corr + p;
            acc = acc * corr + p * kv[base + Cc];
            mx = nm;
        }
    }
    float res = acc / l;
    bf hv = __float2bfloat16(res);
    oh[qoff] = hv;
    ol[qoff] = __float2bfloat16(res - __bfloat162float(hv));
}

// ---------------------------------------------------------------------------
// Split-bf16 GEMM via mma.sync (HMMA).
// C[M,N] = (Ah+Al)[M,K] @ (Bh+Bl)^T[N,K]   (Al*Bl dropped)
// CTA tile 128x64, 8 warps (4x2), warp tile 32x32, BK=64,
// cp.async double-buffered smem (2 x 48KB = 96KB -> 2 CTAs/SM with grid>=296),
// XOR-swizzled 128B rows.
// EPI: 0 -> Co = acc+bias ; 1 -> Co = acc+bias+res ; 2 -> gelu -> bf16 hi/lo
// ---------------------------------------------------------------------------
static constexpr int STGB  = 49152;       // Ah 16K | Al 16K | Bh 8K | Bl 8K
static constexpr int SMTOT = 2 * STGB;    // 96 KB

template <int EPI>
__global__ void __launch_bounds__(256, 2) mma_gemm(
    const bf* __restrict__ Ah, const bf* __restrict__ Al,
    const bf* __restrict__ Bh, const bf* __restrict__ Bl,
    const float* __restrict__ bias, const float* __restrict__ res,
    float* __restrict__ Co, bf* __restrict__ oH, bf* __restrict__ oL,
    int M, int N, int K)
{
    extern __shared__ __align__(1024) char smc[];
    const uint32_t sbase = smem_u32(smc);
    const int tid  = threadIdx.x;
    const int lane = tid & 31;
    const int wid  = tid >> 5;
    const int tm = blockIdx.y, tn = blockIdx.x;
    const int wm = wid >> 1, wn = wid & 1;   // 4 x 2 warp grid, warp tile 32x32

    const size_t strK = (size_t)K * 2;       // bytes per row
    const char* pAh = (const char*)Ah + ((size_t)tm * 128) * strK;
    const char* pAl = (const char*)Al + ((size_t)tm * 128) * strK;
    const char* pBh = (const char*)Bh + ((size_t)tn * 64)  * strK;
    const char* pBl = (const char*)Bl + ((size_t)tn * 64)  * strK;

    const int nCh = K >> 6;                  // chunks of 64

    // ---- async stage loader ------------------------------------------------
    auto load_stage = [&](int stg, int ch) {
        uint32_t d0 = sbase + stg * STGB;
        size_t koff = (size_t)ch * 128;      // 64 bf16 = 128 B
        // A: 2048 granules of 16B (hi 1024 then lo 1024)
#pragma unroll
        for (int i = 0; i < 8; i++) {
            int g = i * 256 + tid;
            int prec = g >> 10;
            int gg = g & 1023;
            int r = gg >> 3, c = gg & 7;
            const char* src = (prec ? pAl : pAh) + (size_t)r * strK + koff + (c << 4);
            uint32_t dst = d0 + prec * 16384 + (r << 7) + ((c ^ (r & 7)) << 4);
            CP16(dst, src);
        }
        // B: 1024 granules (hi 512 then lo 512)
#pragma unroll
        for (int i = 0; i < 4; i++) {
            int g = i * 256 + tid;
            int prec = g >> 9;
            int gg = g & 511;
            int r = gg >> 3, c = gg & 7;
            const char* src = (prec ? pBl : pBh) + (size_t)r * strK + koff + (c << 4);
            uint32_t dst = d0 + 32768 + prec * 8192 + (r << 7) + ((c ^ (r & 7)) << 4);
            CP16(dst, src);
        }
        CP_COMMIT();
    };

    const int rl = lane & 15;       // row within 16-row group
    const int kc = lane >> 4;       // k half (0/1) within k16

    float acc[2][4][4] = {};

    load_stage(0, 0);

    for (int ch = 0; ch < nCh; ch++) {
        if (ch + 1 < nCh) { load_stage((ch + 1) & 1, ch + 1); CP_WAITG(1); }
        else              { CP_WAITG(0); }
        __syncthreads();

        uint32_t aB = sbase + (ch & 1) * STGB;
        uint32_t bB = aB + 32768;

#pragma unroll
        for (int k16 = 0; k16 < 4; k16++) {
            const int k2 = k16 * 2 + kc;
            uint32_t ah[2][4], al[2][4], bh[2][4], bl[2][4];
#pragma unroll
            for (int f = 0; f < 2; f++) {
                int rA = wm * 32 + f * 16 + rl;
                uint32_t rb = aB + (rA << 7);
                int rx = rA & 7;
                ldsm_x4(ah[f], rb + ((k2 ^ rx) << 4));
                ldsm_x4(al[f], rb + 16384 + ((k2 ^ rx) << 4));
            }
            {
                int rB0 = wn * 32 + rl, rB1 = wn * 32 + 16 + rl;
                uint32_t rb0 = bB + (rB0 << 7), rb1 = bB + (rB1 << 7);
                int rx0 = rB0 & 7, rx1 = rB1 & 7;
                ldsm_x4(bh[0], rb0 + ((k2 ^ rx0) << 4));
                ldsm_x4(bh[1], rb1 + ((k2 ^ rx1) << 4));
                ldsm_x4(bl[0], rb0 + 8192 + ((k2 ^ rx0) << 4));
                ldsm_x4(bl[1], rb1 + 8192 + ((k2 ^ rx1) << 4));
            }
            // 3 passes so each accumulator's dependent MMAs are well separated
#pragma unroll
            for (int f = 0; f < 2; f++)
#pragma unroll
                for (int j = 0; j < 4; j++)
                    mma16816(acc[f][j], ah[f], bh[j >> 1][j & 1], bh[j >> 1][2 + (j & 1)]);
#pragma unroll
            for (int f = 0; f < 2; f++)
#pragma unroll
                for (int j = 0; j < 4; j++)
                    mma16816(acc[f][j], al[f], bh[j >> 1][j & 1], bh[j >> 1][2 + (j & 1)]);
#pragma unroll
            for (int f = 0; f < 2; f++)
#pragma unroll
                for (int j = 0; j < 4; j++)
                    mma16816(acc[f][j], ah[f], bl[j >> 1][j & 1], bl[j >> 1][2 + (j & 1)]);
        }
        __syncthreads();
    }

    // ---- epilogue -----------------------------------------------------------
    const int rbase = tm * 128 + wm * 32 + (lane >> 2);
    const int cbase = tn * 64 + wn * 32 + (lane & 3) * 2;
#pragma unroll
    for (int f = 0; f < 2; f++) {
#pragma unroll
        for (int j = 0; j < 4; j++) {
            int row0 = rbase + f * 16;
            int col  = cbase + j * 8;
            float b0 = bias[col], b1 = bias[col + 1];
            float v00 = acc[f][j][0] + b0;
            float v01 = acc[f][j][1] + b1;
            float v10 = acc[f][j][2] + b0;
            float v11 = acc[f][j][3] + b1;
            size_t i0 = (size_t)row0 * N + col;
            size_t i1 = (size_t)(row0 + 8) * N + col;
            if (EPI == 0) {
                *(float2*)(Co + i0) = make_float2(v00, v01);
                *(float2*)(Co + i1) = make_float2(v10, v11);
            } else if (EPI == 1) {
                float2 r0 = *(const float2*)(res + i0);
                float2 r1 = *(const float2*)(res + i1);
                *(float2*)(Co + i0) = make_float2(v00 + r0.x, v01 + r0.y);
                *(float2*)(Co + i1) = make_float2(v10 + r1.x, v11 + r1.y);
            } else {
                const float IS2 = 0.70710678118654752f;
                v00 = 0.5f * v00 * (1.f + erff(v00 * IS2));
                v01 = 0.5f * v01 * (1.f + erff(v01 * IS2));
                v10 = 0.5f * v10 * (1.f + erff(v10 * IS2));
                v11 = 0.5f * v11 * (1.f + erff(v11 * IS2));
                bf h00 = __float2bfloat16(v00), h01 = __float2bfloat16(v01);
                bf h10 = __float2bfloat16(v10), h11 = __float2bfloat16(v11);
                __nv_bfloat162 hh0; hh0.x = h00; hh0.y = h01;
                __nv_bfloat162 hh1; hh1.x = h10; hh1.y = h11;
                *(__nv_bfloat162*)(oH + i0) = hh0;
                *(__nv_bfloat162*)(oH + i1) = hh1;
                __nv_bfloat162 ll0, ll1;
                ll0.x = __float2bfloat16(v00 - __bfloat162float(h00));
                ll0.y = __float2bfloat16(v01 - __bfloat162float(h01));
                ll1.x = __float2bfloat16(v10 - __bfloat162float(h10));
                ll1.y = __float2bfloat16(v11 - __bfloat162float(h11));
                *(__nv_bfloat162*)(oL + i0) = ll0;
                *(__nv_bfloat162*)(oL + i1) = ll1;
            }
        }
    }
}

// ---------------------------------------------------------------------------
// Launch
// ---------------------------------------------------------------------------
template <typename T>
static T* symaddr(const void* sym)
{
    void* p = nullptr;
    cudaGetSymbolAddress(&p, sym);
    return (T*)p;
}

extern "C" void kernel_launch(void* const* d_in, const int* in_sizes, int n_in,
                              void* d_out, int out_size)
{
    const float* x    = (const float*)d_in[0];
    const float* x_kv = (const float*)d_in[1];
    const float* Wq   = (const float*)d_in[2];
    const float* bq   = (const float*)d_in[3];
    const float* Wk   = (const float*)d_in[4];
    const float* bk   = (const float*)d_in[5];
    const float* Wv   = (const float*)d_in[6];
    const float* bv   = (const float*)d_in[7];
    const float* Wp   = (const float*)d_in[8];
    const float* bp   = (const float*)d_in[9];
    const float* g1   = (const float*)d_in[10];
    const float* b1   = (const float*)d_in[11];
    const float* g2   = (const float*)d_in[12];
    const float* b2   = (const float*)d_in[13];
    const float* W1   = (const float*)d_in[14];
    const float* bm1  = (const float*)d_in[15];
    const float* W2   = (const float*)d_in[16];
    const float* bm2  = (const float*)d_in[17];
    float* out = (float*)d_out;

    bf* h_hi  = symaddr<bf>(g_h_hi);   bf* h_lo  = symaddr<bf>(g_h_lo);
    bf* hk_hi = symaddr<bf>(g_hk_hi);  bf* hk_lo = symaddr<bf>(g_hk_lo);
    float* qb  = symaddr<float>(g_q);
    float* kvb = symaddr<float>(g_kv);
    bf* at_hi = symaddr<bf>(g_at_hi);  bf* at_lo = symaddr<bf>(g_at_lo);
    float* x2 = symaddr<float>(g_x2);
    bf* m_hi  = symaddr<bf>(g_m_hi);   bf* m_lo  = symaddr<bf>(g_m_lo);
    bf* t_hi  = symaddr<bf>(g_t_hi);   bf* t_lo  = symaddr<bf>(g_t_lo);
    bf* wq_hi  = symaddr<bf>(g_wq_hi);  bf* wq_lo  = symaddr<bf>(g_wq_lo);
    bf* wkv_hi = symaddr<bf>(g_wkv_hi); bf* wkv_lo = symaddr<bf>(g_wkv_lo);
    bf* wp_hi  = symaddr<bf>(g_wp_hi);  bf* wp_lo  = symaddr<bf>(g_wp_lo);
    bf* w1_hi  = symaddr<bf>(g_w1_hi);  bf* w1_lo  = symaddr<bf>(g_w1_lo);
    bf* w2_hi  = symaddr<bf>(g_w2_hi);  bf* w2_lo  = symaddr<bf>(g_w2_lo);
    float* bkv = symaddr<float>(g_bkv);

    static bool attrSet = false;
    if (!attrSet) {
        cudaFuncSetAttribute(mma_gemm<0>, cudaFuncAttributeMaxDynamicSharedMemorySize, SMTOT);
        cudaFuncSetAttribute(mma_gemm<1>, cudaFuncAttributeMaxDynamicSharedMemorySize, SMTOT);
        cudaFuncSetAttribute(mma_gemm<2>, cudaFuncAttributeMaxDynamicSharedMemorySize, SMTOT);
        attrSet = true;
    }

    // Concatenated KV bias (capturable D2D copies)
    cudaMemcpyAsync(bkv,      bk, Cc * sizeof(float), cudaMemcpyDeviceToDevice);
    cudaMemcpyAsync(bkv + Cc, bv, Cc * sizeof(float), cudaMemcpyDeviceToDevice);

    // Weight transpose + split: one launch; Wk/Wv go into fused [512,256] buffer
    convw_all<<<768, 256>>>(Wq, Wk, Wv, Wp, W1, W2,
                            wq_hi, wq_lo,
                            wkv_hi, wkv_lo,                        // Wk -> rows 0..255
                            wkv_hi + Cc * Cc, wkv_lo + Cc * Cc,    // Wv -> rows 256..511
                            wp_hi, wp_lo, w1_hi, w1_lo, w2_hi, w2_lo);

    // LN1 on x and x_kv (-> bf16 hi/lo)
    {
        int blocks = ROWS / 8;
        ln_kernel<<<blocks, 256>>>(x,    g1, b1, h_hi,  h_lo,  ROWS);
        ln_kernel<<<blocks, 256>>>(x_kv, g1, b1, hk_hi, hk_lo, ROWS);
    }

    // Q projection (N=256, grid 4x72=288) and fused KV projection (N=512, 576)
    {
        dim3 gq(Cc / 64, ROWS / 128);
        mma_gemm<0><<<gq, 256, SMTOT>>>(h_hi, h_lo, wq_hi, wq_lo, bq, nullptr, qb, nullptr, nullptr, ROWS, Cc, Cc);
        dim3 gkv(2 * Cc / 64, ROWS / 128);
        mma_gemm<0><<<gkv, 256, SMTOT>>>(hk_hi, hk_lo, wkv_hi, wkv_lo, bkv, nullptr, kvb, nullptr, nullptr, ROWS, 2 * Cc, Cc);
    }

    // Sparse local attention (-> bf16 hi/lo)
    {
        int totalWarps = Bb * Nn * NH;  // 73728
        attn_kernel<<<totalWarps / 8, 256>>>(qb, kvb, at_hi, at_lo);
    }

    // x2 = x + att @ Wp + bp
    {
        dim3 grid(Cc / 64, ROWS / 128);
        mma_gemm<1><<<grid, 256, SMTOT>>>(at_hi, at_lo, wp_hi, wp_lo, bp, x, x2, nullptr, nullptr, ROWS, Cc, Cc);
    }

    // LN2 (-> bf16 hi/lo)
    ln_kernel<<<ROWS / 8, 256>>>(x2, g2, b2, m_hi, m_lo, ROWS);

    // MLP: t = gelu(m @ W1 + bm1) (-> bf16 hi/lo); out = x2 + t @ W2 + bm2
    {
        dim3 grid1(HID / 64, ROWS / 128);
        mma_gemm<2><<<grid1, 256, SMTOT>>>(m_hi, m_lo, w1_hi, w1_lo, bm1, nullptr, nullptr, t_hi, t_lo, ROWS, HID, Cc);
        dim3 grid2(Cc / 64, ROWS / 128);
        mma_gemm<1><<<grid2, 256, SMTOT>>>(t_hi, t_lo, w2_hi, w2_lo, bm2, x2, out, nullptr, nullptr, ROWS, Cc, HID);
    }
}

// round 7
// speedup vs baseline: 1.4598x; 1.3028x over previous
#include <cuda_runtime.h>
#include <cuda_bf16.h>
#include <math.h>
#include <cstdint>

// ---------------------------------------------------------------------------
// Problem constants
// ---------------------------------------------------------------------------
static constexpr int Bb   = 4;
static constexpr int Nn   = 2304;      // 48*48
static constexpr int Cc   = 256;
static constexpr int NH   = 8;
static constexpr int HD   = 32;
static constexpr int HS   = 48;
static constexpr int HID  = 4 * Cc;    // 1024
static constexpr int ROWS = Bb * Nn;   // 9216
static constexpr float SCALE = 0.17677669529663687f; // 32^-0.5

// Neighbor offsets with dy*dy+dx*dx <= 9  (29 of them)
__constant__ int c_dy[29] = {-3,-2,-2,-2,-2,-2,-1,-1,-1,-1,-1, 0,0,0,0,0,0,0, 1,1,1,1,1, 2,2,2,2,2, 3};
__constant__ int c_dx[29] = { 0,-2,-1, 0, 1, 2,-2,-1, 0, 1, 2,-3,-2,-1,0,1,2,3,-2,-1,0,1,2,-2,-1,0,1,2, 0};

// ---------------------------------------------------------------------------
// Scratch (no cudaMalloc allowed)
// ---------------------------------------------------------------------------
using bf = __nv_bfloat16;
__device__ __align__(16) bf g_h_hi  [ROWS * Cc];
__device__ __align__(16) bf g_h_lo  [ROWS * Cc];
__device__ __align__(16) bf g_hk_hi [ROWS * Cc];
__device__ __align__(16) bf g_hk_lo [ROWS * Cc];
__device__ __align__(16) float g_q  [ROWS * Cc];
__device__ __align__(16) float g_kv [ROWS * 2 * Cc];     // fused K|V, stride 512
__device__ __align__(16) bf g_at_hi [ROWS * Cc];
__device__ __align__(16) bf g_at_lo [ROWS * Cc];
__device__ __align__(16) float g_x2 [ROWS * Cc];
__device__ __align__(16) bf g_m_hi  [ROWS * Cc];
__device__ __align__(16) bf g_m_lo  [ROWS * Cc];
__device__ __align__(16) bf g_t_hi  [ROWS * HID];
__device__ __align__(16) bf g_t_lo  [ROWS * HID];
// transposed + split weights: [N, K] layout
__device__ __align__(16) bf g_wq_hi [Cc * Cc];
__device__ __align__(16) bf g_wq_lo [Cc * Cc];
__device__ __align__(16) bf g_wkv_hi[2 * Cc * Cc];       // rows 0..255 = Wk^T, 256..511 = Wv^T
__device__ __align__(16) bf g_wkv_lo[2 * Cc * Cc];
__device__ __align__(16) bf g_wp_hi [Cc * Cc];
__device__ __align__(16) bf g_wp_lo [Cc * Cc];
__device__ __align__(16) bf g_w1_hi [HID * Cc];
__device__ __align__(16) bf g_w1_lo [HID * Cc];
__device__ __align__(16) bf g_w2_hi [Cc * HID];
__device__ __align__(16) bf g_w2_lo [Cc * HID];
__device__ __align__(16) float g_bkv[2 * Cc];            // bk | bv

// ---------------------------------------------------------------------------
// PTX helpers (base-ISA only: mma.sync / ldmatrix / cp.async)
// ---------------------------------------------------------------------------
__device__ __forceinline__ uint32_t smem_u32(const void* p) {
    uint32_t a;
    asm("{ .reg .u64 t; cvta.to.shared.u64 t, %1; cvt.u32.u64 %0, t; }" : "=r"(a) : "l"(p));
    return a;
}
__device__ __forceinline__ void ldsm_x4(uint32_t* r, uint32_t addr) {
    asm volatile("ldmatrix.sync.aligned.m8n8.x4.shared.b16 {%0,%1,%2,%3}, [%4];"
        : "=r"(r[0]), "=r"(r[1]), "=r"(r[2]), "=r"(r[3]) : "r"(addr));
}
__device__ __forceinline__ void mma16816(float* d, const uint32_t* a, uint32_t b0, uint32_t b1) {
    asm volatile("mma.sync.aligned.m16n8k16.row.col.f32.bf16.bf16.f32 "
        "{%0,%1,%2,%3}, {%4,%5,%6,%7}, {%8,%9}, {%0,%1,%2,%3};"
        : "+f"(d[0]), "+f"(d[1]), "+f"(d[2]), "+f"(d[3])
        : "r"(a[0]), "r"(a[1]), "r"(a[2]), "r"(a[3]), "r"(b0), "r"(b1));
}
#define CP16(dst, src) \
    asm volatile("cp.async.cg.shared.global [%0], [%1], 16;" :: "r"(dst), "l"(src))
#define CP_COMMIT()  asm volatile("cp.async.commit_group;" ::: "memory")
#define CP_WAITG(n)  asm volatile("cp.async.wait_group %0;" :: "n"(n) : "memory")

// ---------------------------------------------------------------------------
// All-in-one weight transpose + bf16 hi/lo split (coalesced, smem-tiled).
// ---------------------------------------------------------------------------
__global__ void __launch_bounds__(256) convw_all(
    const float* __restrict__ Wq, const float* __restrict__ Wk,
    const float* __restrict__ Wv, const float* __restrict__ Wp,
    const float* __restrict__ W1, const float* __restrict__ W2,
    bf* qh, bf* ql, bf* kh, bf* kl, bf* vh, bf* vl,
    bf* ph, bf* pl, bf* h1h, bf* h1l, bf* h2h, bf* h2l)
{
    __shared__ float t[32][33];
    int bid = blockIdx.x;
    const float* W; bf* Th; bf* Tl; int K, N, tile;
    if (bid < 256) {
        int w = bid >> 6; tile = bid & 63; K = 256; N = 256;
        if      (w == 0) { W = Wq; Th = qh; Tl = ql; }
        else if (w == 1) { W = Wk; Th = kh; Tl = kl; }
        else if (w == 2) { W = Wv; Th = vh; Tl = vl; }
        else             { W = Wp; Th = ph; Tl = pl; }
    } else if (bid < 512) {
        W = W1; Th = h1h; Tl = h1l; K = 256; N = 1024; tile = bid - 256;
    } else {
        W = W2; Th = h2h; Tl = h2l; K = 1024; N = 256; tile = bid - 512;
    }
    int ntn = N >> 5;
    int tk = tile / ntn, tn = tile % ntn;
    int tx = threadIdx.x & 31, ty = threadIdx.x >> 5;
#pragma unroll
    for (int i = 0; i < 4; i++) {
        int r = ty + i * 8;
        t[r][tx] = W[(size_t)(tk * 32 + r) * N + tn * 32 + tx];
    }
    __syncthreads();
#pragma unroll
    for (int i = 0; i < 4; i++) {
        int r = ty + i * 8;
        float wv = t[tx][r];
        size_t o = (size_t)(tn * 32 + r) * K + tk * 32 + tx;
        bf h = __float2bfloat16(wv);
        Th[o] = h;
        Tl[o] = __float2bfloat16(wv - __bfloat162float(h));
    }
}

// ---------------------------------------------------------------------------
// LayerNorm: one warp per row of 256; emits bf16 hi/lo.
// Dual-source variant: rows [0, rows) -> x/oh/ol, rows [rows, 2*rows) -> x2/oh2/ol2
// ---------------------------------------------------------------------------
__global__ void ln_kernel2(const float* __restrict__ xa,
                           const float* __restrict__ xb,
                           const float* __restrict__ g,
                           const float* __restrict__ b,
                           bf* __restrict__ oha, bf* __restrict__ ola,
                           bf* __restrict__ ohb, bf* __restrict__ olb,
                           int rows)
{
    int gw   = (blockIdx.x * blockDim.x + threadIdx.x) >> 5;
    int lane = threadIdx.x & 31;
    if (gw >= 2 * rows) return;
    const float* x = (gw < rows) ? xa : xb;
    bf* oh = (gw < rows) ? oha : ohb;
    bf* ol = (gw < rows) ? ola : olb;
    int r = (gw < rows) ? gw : gw - rows;

    const float* xr = x + (size_t)r * Cc;
    float f[8], s = 0.f, ss = 0.f;
#pragma unroll
    for (int i = 0; i < 8; i++) {
        f[i] = xr[lane + 32 * i];
        s  += f[i];
        ss += f[i] * f[i];
    }
#pragma unroll
    for (int off = 16; off; off >>= 1) {
        s  += __shfl_xor_sync(0xffffffffu, s,  off);
        ss += __shfl_xor_sync(0xffffffffu, ss, off);
    }
    float mu  = s * (1.f / 256.f);
    float var = ss * (1.f / 256.f) - mu * mu;
    float inv = rsqrtf(var + 1e-6f);
    size_t base = (size_t)r * Cc;
#pragma unroll
    for (int i = 0; i < 8; i++) {
        int c = lane + 32 * i;
        float v = (f[i] - mu) * inv * g[c] + b[c];
        bf hv = __float2bfloat16(v);
        oh[base + c] = hv;
        ol[base + c] = __float2bfloat16(v - __bfloat162float(hv));
    }
}

__global__ void ln_kernel(const float* __restrict__ x,
                          const float* __restrict__ g,
                          const float* __restrict__ b,
                          bf* __restrict__ oh, bf* __restrict__ ol, int rows)
{
    int gw   = (blockIdx.x * blockDim.x + threadIdx.x) >> 5;
    int lane = threadIdx.x & 31;
    if (gw >= rows) return;
    const float* xr = x + (size_t)gw * Cc;
    float f[8], s = 0.f, ss = 0.f;
#pragma unroll
    for (int i = 0; i < 8; i++) {
        f[i] = xr[lane + 32 * i];
        s  += f[i];
        ss += f[i] * f[i];
    }
#pragma unroll
    for (int off = 16; off; off >>= 1) {
        s  += __shfl_xor_sync(0xffffffffu, s,  off);
        ss += __shfl_xor_sync(0xffffffffu, ss, off);
    }
    float mu  = s * (1.f / 256.f);
    float var = ss * (1.f / 256.f) - mu * mu;
    float inv = rsqrtf(var + 1e-6f);
    size_t base = (size_t)gw * Cc;
#pragma unroll
    for (int i = 0; i < 8; i++) {
        int c = lane + 32 * i;
        float v = (f[i] - mu) * inv * g[c] + b[c];
        bf hv = __float2bfloat16(v);
        oh[base + c] = hv;
        ol[base + c] = __float2bfloat16(v - __bfloat162float(hv));
    }
}

// ---------------------------------------------------------------------------
// Tiled sparse attention.
// CTA = (batch z, head y, 8x8 query tile x). Halo 14x14 k/v tile in smem
// (rows padded to 65 floats: [0..31]=k, [32..63]=v). Warp = one query row.
// Phase A: lane = neighbor -> per-lane score, warp-reduce softmax (one exp
// warp-op per query). Phase B: lane = dim, p_j broadcast by shuffle.
// ---------------------------------------------------------------------------
static constexpr int TQ   = 8;
static constexpr int HALO = 3;
static constexpr int SP   = TQ + 2 * HALO;   // 14
static constexpr int NPOS = SP * SP;         // 196
static constexpr int ROWF = 65;              // padded row (k 32 | v 32 | pad)
static constexpr int ATT_SMEM = NPOS * ROWF * 4;  // 50960 B

__global__ void __launch_bounds__(256) attn_tile(
    const float* __restrict__ q, const float* __restrict__ kv,
    bf* __restrict__ oh, bf* __restrict__ ol)
{
    extern __shared__ float kvs[];
    const int tid = threadIdx.x, lane = tid & 31, wid = tid >> 5;
    const int tIdx = blockIdx.x;            // 0..35
    const int h = blockIdx.y, b = blockIdx.z;
    const int ty0 = (tIdx / 6) * TQ, tx0 = (tIdx % 6) * TQ;

    // ---- load halo tile (zero-fill OOB) ----
    for (int i = tid; i < NPOS * 16; i += 256) {
        int sp = i >> 4, c4 = i & 15;
        int ly = sp / SP, lx = sp - ly * SP;
        int ny = ty0 - HALO + ly, nx = tx0 - HALO + lx;
        float4 val = make_float4(0.f, 0.f, 0.f, 0.f);
        if ((unsigned)ny < (unsigned)HS && (unsigned)nx < (unsigned)HS) {
            size_t base = ((size_t)(b * Nn + ny * HS + nx)) * (2 * Cc) + h * HD;
            val = *(const float4*)(kv + base + (c4 < 8 ? c4 * 4 : Cc + (c4 - 8) * 4));
        }
        float* dst = &kvs[sp * ROWF + ((c4 < 8) ? c4 * 4 : 32 + (c4 - 8) * 4)];
        dst[0] = val.x; dst[1] = val.y; dst[2] = val.z; dst[3] = val.w;
    }
    __syncthreads();

    const int qy = ty0 + wid;
    // per-lane neighbor offsets
    int dy = 0, dx = 0;
    if (lane < 29) { dy = c_dy[lane]; dx = c_dx[lane]; }
    const bool rowok = (lane < 29) && ((unsigned)(qy + dy) < (unsigned)HS);

    // q for the 8 queries of this row (lane = dim)
    const size_t qbase = ((size_t)(b * Nn + qy * HS + tx0)) * Cc + h * HD + lane;
    float qv[8];
#pragma unroll
    for (int i = 0; i < 8; i++) qv[i] = q[qbase + i * Cc];

    // per-(query, lane-neighbor) smem row + validity; sp always in [0, NPOS)
    int sp[8]; float s[8];
#pragma unroll
    for (int i = 0; i < 8; i++) {
        sp[i] = (wid + dy + HALO) * SP + (i + dx + HALO);
        s[i] = 0.f;
    }

    // ---- phase A: scores (lane = neighbor) ----
#pragma unroll
    for (int d = 0; d < 32; d++) {
#pragma unroll
        for (int i = 0; i < 8; i++) {
            float qd = __shfl_sync(0xffffffffu, qv[i], d);
            s[i] += kvs[sp[i] * ROWF + d] * qd;
        }
    }
    float p[8], linv[8];
#pragma unroll
    for (int i = 0; i < 8; i++) {
        bool ok = rowok && ((unsigned)(tx0 + i + dx) < (unsigned)HS);
        float sv = ok ? s[i] * SCALE : -1e30f;
        float m = sv;
#pragma unroll
        for (int off = 16; off; off >>= 1)
            m = fmaxf(m, __shfl_xor_sync(0xffffffffu, m, off));
        float e = expf(sv - m);
        float sum = e;
#pragma unroll
        for (int off = 16; off; off >>= 1)
            sum += __shfl_xor_sync(0xffffffffu, sum, off);
        p[i] = e;
        linv[i] = 1.f / sum;
    }

    // ---- phase B: weighted V (lane = dim) ----
    float acc[8] = {};
#pragma unroll
    for (int j = 0; j < 29; j++) {
        int spj = (wid + c_dy[j] + HALO) * SP + (c_dx[j] + HALO);  // + i below
#pragma unroll
        for (int i = 0; i < 8; i++) {
            float pj = __shfl_sync(0xffffffffu, p[i], j);
            acc[i] += pj * kvs[(spj + i) * ROWF + 32 + lane];
        }
    }

    // ---- store (bf16 hi/lo) ----
#pragma unroll
    for (int i = 0; i < 8; i++) {
        float res = acc[i] * linv[i];
        bf hv = __float2bfloat16(res);
        oh[qbase + i * Cc] = hv;
        ol[qbase + i * Cc] = __float2bfloat16(res - __bfloat162float(hv));
    }
}

// ---------------------------------------------------------------------------
// Split-bf16 GEMM via mma.sync (HMMA). (round-6 config: 128x64, BK=64, 2-stage)
// ---------------------------------------------------------------------------
static constexpr int STGB  = 49152;       // Ah 16K | Al 16K | Bh 8K | Bl 8K
static constexpr int SMTOT = 2 * STGB;    // 96 KB

template <int EPI>
__global__ void __launch_bounds__(256, 2) mma_gemm(
    const bf* __restrict__ Ah, const bf* __restrict__ Al,
    const bf* __restrict__ Bh, const bf* __restrict__ Bl,
    const float* __restrict__ bias, const float* __restrict__ res,
    float* __restrict__ Co, bf* __restrict__ oH, bf* __restrict__ oL,
    int M, int N, int K)
{
    extern __shared__ __align__(1024) char smc[];
    const uint32_t sbase = smem_u32(smc);
    const int tid  = threadIdx.x;
    const int lane = tid & 31;
    const int wid  = tid >> 5;
    const int tm = blockIdx.y, tn = blockIdx.x;
    const int wm = wid >> 1, wn = wid & 1;   // 4 x 2 warp grid, warp tile 32x32

    const size_t strK = (size_t)K * 2;
    const char* pAh = (const char*)Ah + ((size_t)tm * 128) * strK;
    const char* pAl = (const char*)Al + ((size_t)tm * 128) * strK;
    const char* pBh = (const char*)Bh + ((size_t)tn * 64)  * strK;
    const char* pBl = (const char*)Bl + ((size_t)tn * 64)  * strK;

    const int nCh = K >> 6;

    auto load_stage = [&](int stg, int ch) {
        uint32_t d0 = sbase + stg * STGB;
        size_t koff = (size_t)ch * 128;
#pragma unroll
        for (int i = 0; i < 8; i++) {
            int g = i * 256 + tid;
            int prec = g >> 10;
            int gg = g & 1023;
            int r = gg >> 3, c = gg & 7;
            const char* src = (prec ? pAl : pAh) + (size_t)r * strK + koff + (c << 4);
            uint32_t dst = d0 + prec * 16384 + (r << 7) + ((c ^ (r & 7)) << 4);
            CP16(dst, src);
        }
#pragma unroll
        for (int i = 0; i < 4; i++) {
            int g = i * 256 + tid;
            int prec = g >> 9;
            int gg = g & 511;
            int r = gg >> 3, c = gg & 7;
            const char* src = (prec ? pBl : pBh) + (size_t)r * strK + koff + (c << 4);
            uint32_t dst = d0 + 32768 + prec * 8192 + (r << 7) + ((c ^ (r & 7)) << 4);
            CP16(dst, src);
        }
        CP_COMMIT();
    };

    const int rl = lane & 15;
    const int kc = lane >> 4;

    float acc[2][4][4] = {};

    load_stage(0, 0);

    for (int ch = 0; ch < nCh; ch++) {
        if (ch + 1 < nCh) { load_stage((ch + 1) & 1, ch + 1); CP_WAITG(1); }
        else              { CP_WAITG(0); }
        __syncthreads();

        uint32_t aB = sbase + (ch & 1) * STGB;
        uint32_t bB = aB + 32768;

#pragma unroll
        for (int k16 = 0; k16 < 4; k16++) {
            const int k2 = k16 * 2 + kc;
            uint32_t ah[2][4], al[2][4], bh[2][4], bl[2][4];
#pragma unroll
            for (int f = 0; f < 2; f++) {
                int rA = wm * 32 + f * 16 + rl;
                uint32_t rb = aB + (rA << 7);
                int rx = rA & 7;
                ldsm_x4(ah[f], rb + ((k2 ^ rx) << 4));
                ldsm_x4(al[f], rb + 16384 + ((k2 ^ rx) << 4));
            }
            {
                int rB0 = wn * 32 + rl, rB1 = wn * 32 + 16 + rl;
                uint32_t rb0 = bB + (rB0 << 7), rb1 = bB + (rB1 << 7);
                int rx0 = rB0 & 7, rx1 = rB1 & 7;
                ldsm_x4(bh[0], rb0 + ((k2 ^ rx0) << 4));
                ldsm_x4(bh[1], rb1 + ((k2 ^ rx1) << 4));
                ldsm_x4(bl[0], rb0 + 8192 + ((k2 ^ rx0) << 4));
                ldsm_x4(bl[1], rb1 + 8192 + ((k2 ^ rx1) << 4));
            }
#pragma unroll
            for (int f = 0; f < 2; f++)
#pragma unroll
                for (int j = 0; j < 4; j++)
                    mma16816(acc[f][j], ah[f], bh[j >> 1][j & 1], bh[j >> 1][2 + (j & 1)]);
#pragma unroll
            for (int f = 0; f < 2; f++)
#pragma unroll
                for (int j = 0; j < 4; j++)
                    mma16816(acc[f][j], al[f], bh[j >> 1][j & 1], bh[j >> 1][2 + (j & 1)]);
#pragma unroll
            for (int f = 0; f < 2; f++)
#pragma unroll
                for (int j = 0; j < 4; j++)
                    mma16816(acc[f][j], ah[f], bl[j >> 1][j & 1], bl[j >> 1][2 + (j & 1)]);
        }
        __syncthreads();
    }

    const int rbase = tm * 128 + wm * 32 + (lane >> 2);
    const int cbase = tn * 64 + wn * 32 + (lane & 3) * 2;
#pragma unroll
    for (int f = 0; f < 2; f++) {
#pragma unroll
        for (int j = 0; j < 4; j++) {
            int row0 = rbase + f * 16;
            int col  = cbase + j * 8;
            float b0 = bias[col], b1 = bias[col + 1];
            float v00 = acc[f][j][0] + b0;
            float v01 = acc[f][j][1] + b1;
            float v10 = acc[f][j][2] + b0;
            float v11 = acc[f][j][3] + b1;
            size_t i0 = (size_t)row0 * N + col;
            size_t i1 = (size_t)(row0 + 8) * N + col;
            if (EPI == 0) {
                *(float2*)(Co + i0) = make_float2(v00, v01);
                *(float2*)(Co + i1) = make_float2(v10, v11);
            } else if (EPI == 1) {
                float2 r0 = *(const float2*)(res + i0);
                float2 r1 = *(const float2*)(res + i1);
                *(float2*)(Co + i0) = make_float2(v00 + r0.x, v01 + r0.y);
                *(float2*)(Co + i1) = make_float2(v10 + r1.x, v11 + r1.y);
            } else {
                const float IS2 = 0.70710678118654752f;
                v00 = 0.5f * v00 * (1.f + erff(v00 * IS2));
                v01 = 0.5f * v01 * (1.f + erff(v01 * IS2));
                v10 = 0.5f * v10 * (1.f + erff(v10 * IS2));
                v11 = 0.5f * v11 * (1.f + erff(v11 * IS2));
                bf h00 = __float2bfloat16(v00), h01 = __float2bfloat16(v01);
                bf h10 = __float2bfloat16(v10), h11 = __float2bfloat16(v11);
                __nv_bfloat162 hh0; hh0.x = h00; hh0.y = h01;
                __nv_bfloat162 hh1; hh1.x = h10; hh1.y = h11;
                *(__nv_bfloat162*)(oH + i0) = hh0;
                *(__nv_bfloat162*)(oH + i1) = hh1;
                __nv_bfloat162 ll0, ll1;
                ll0.x = __float2bfloat16(v00 - __bfloat162float(h00));
                ll0.y = __float2bfloat16(v01 - __bfloat162float(h01));
                ll1.x = __float2bfloat16(v10 - __bfloat162float(h10));
                ll1.y = __float2bfloat16(v11 - __bfloat162float(h11));
                *(__nv_bfloat162*)(oL + i0) = ll0;
                *(__nv_bfloat162*)(oL + i1) = ll1;
            }
        }
    }
}

// ---------------------------------------------------------------------------
// Launch
// ---------------------------------------------------------------------------
template <typename T>
static T* symaddr(const void* sym)
{
    void* p = nullptr;
    cudaGetSymbolAddress(&p, sym);
    return (T*)p;
}

extern "C" void kernel_launch(void* const* d_in, const int* in_sizes, int n_in,
                              void* d_out, int out_size)
{
    const float* x    = (const float*)d_in[0];
    const float* x_kv = (const float*)d_in[1];
    const float* Wq   = (const float*)d_in[2];
    const float* bq   = (const float*)d_in[3];
    const float* Wk   = (const float*)d_in[4];
    const float* bk   = (const float*)d_in[5];
    const float* Wv   = (const float*)d_in[6];
    const float* bv   = (const float*)d_in[7];
    const float* Wp   = (const float*)d_in[8];
    const float* bp   = (const float*)d_in[9];
    const float* g1   = (const float*)d_in[10];
    const float* b1   = (const float*)d_in[11];
    const float* g2   = (const float*)d_in[12];
    const float* b2   = (const float*)d_in[13];
    const float* W1   = (const float*)d_in[14];
    const float* bm1  = (const float*)d_in[15];
    const float* W2   = (const float*)d_in[16];
    const float* bm2  = (const float*)d_in[17];
    float* out = (float*)d_out;

    bf* h_hi  = symaddr<bf>(g_h_hi);   bf* h_lo  = symaddr<bf>(g_h_lo);
    bf* hk_hi = symaddr<bf>(g_hk_hi);  bf* hk_lo = symaddr<bf>(g_hk_lo);
    float* qb  = symaddr<float>(g_q);
    float* kvb = symaddr<float>(g_kv);
    bf* at_hi = symaddr<bf>(g_at_hi);  bf* at_lo = symaddr<bf>(g_at_lo);
    float* x2 = symaddr<float>(g_x2);
    bf* m_hi  = symaddr<bf>(g_m_hi);   bf* m_lo  = symaddr<bf>(g_m_lo);
    bf* t_hi  = symaddr<bf>(g_t_hi);   bf* t_lo  = symaddr<bf>(g_t_lo);
    bf* wq_hi  = symaddr<bf>(g_wq_hi);  bf* wq_lo  = symaddr<bf>(g_wq_lo);
    bf* wkv_hi = symaddr<bf>(g_wkv_hi); bf* wkv_lo = symaddr<bf>(g_wkv_lo);
    bf* wp_hi  = symaddr<bf>(g_wp_hi);  bf* wp_lo  = symaddr<bf>(g_wp_lo);
    bf* w1_hi  = symaddr<bf>(g_w1_hi);  bf* w1_lo  = symaddr<bf>(g_w1_lo);
    bf* w2_hi  = symaddr<bf>(g_w2_hi);  bf* w2_lo  = symaddr<bf>(g_w2_lo);
    float* bkv = symaddr<float>(g_bkv);

    static bool attrSet = false;
    if (!attrSet) {
        cudaFuncSetAttribute(mma_gemm<0>, cudaFuncAttributeMaxDynamicSharedMemorySize, SMTOT);
        cudaFuncSetAttribute(mma_gemm<1>, cudaFuncAttributeMaxDynamicSharedMemorySize, SMTOT);
        cudaFuncSetAttribute(mma_gemm<2>, cudaFuncAttributeMaxDynamicSharedMemorySize, SMTOT);
        cudaFuncSetAttribute(attn_tile, cudaFuncAttributeMaxDynamicSharedMemorySize, ATT_SMEM);
        attrSet = true;
    }

    // Concatenated KV bias (capturable D2D copies)
    cudaMemcpyAsync(bkv,      bk, Cc * sizeof(float), cudaMemcpyDeviceToDevice);
    cudaMemcpyAsync(bkv + Cc, bv, Cc * sizeof(float), cudaMemcpyDeviceToDevice);

    // Weight transpose + split
    convw_all<<<768, 256>>>(Wq, Wk, Wv, Wp, W1, W2,
                            wq_hi, wq_lo,
                            wkv_hi, wkv_lo,
                            wkv_hi + Cc * Cc, wkv_lo + Cc * Cc,
                            wp_hi, wp_lo, w1_hi, w1_lo, w2_hi, w2_lo);

    // LN1 on x and x_kv in one launch
    ln_kernel2<<<(2 * ROWS) / 8, 256>>>(x, x_kv, g1, b1,
                                        h_hi, h_lo, hk_hi, hk_lo, ROWS);

    // Q projection and fused KV projection
    {
        dim3 gq(Cc / 64, ROWS / 128);
        mma_gemm<0><<<gq, 256, SMTOT>>>(h_hi, h_lo, wq_hi, wq_lo, bq, nullptr, qb, nullptr, nullptr, ROWS, Cc, Cc);
        dim3 gkv(2 * Cc / 64, ROWS / 128);
        mma_gemm<0><<<gkv, 256, SMTOT>>>(hk_hi, hk_lo, wkv_hi, wkv_lo, bkv, nullptr, kvb, nullptr, nullptr, ROWS, 2 * Cc, Cc);
    }

    // Tiled sparse attention (-> bf16 hi/lo)
    {
        dim3 ga(36, NH, Bb);
        attn_tile<<<ga, 256, ATT_SMEM>>>(qb, kvb, at_hi, at_lo);
    }

    // x2 = x + att @ Wp + bp
    {
        dim3 grid(Cc / 64, ROWS / 128);
        mma_gemm<1><<<grid, 256, SMTOT>>>(at_hi, at_lo, wp_hi, wp_lo, bp, x, x2, nullptr, nullptr, ROWS, Cc, Cc);
    }

    // LN2 (-> bf16 hi/lo)
    ln_kernel<<<ROWS / 8, 256>>>(x2, g2, b2, m_hi, m_lo, ROWS);

    // MLP
    {
        dim3 grid1(HID / 64, ROWS / 128);
        mma_gemm<2><<<grid1, 256, SMTOT>>>(m_hi, m_lo, w1_hi, w1_lo, bm1, nullptr, nullptr, t_hi, t_lo, ROWS, HID, Cc);
        dim3 grid2(Cc / 64, ROWS / 128);
        mma_gemm<1><<<grid2, 256, SMTOT>>>(t_hi, t_lo, w2_hi, w2_lo, bm2, x2, out, nullptr, nullptr, ROWS, Cc, HID);
    }
}

// round 8
// speedup vs baseline: 1.4894x; 1.0203x over previous
#include <cuda_runtime.h>
#include <cuda_bf16.h>
#include <math.h>
#include <cstdint>

// ---------------------------------------------------------------------------
// Problem constants
// ---------------------------------------------------------------------------
static constexpr int Bb   = 4;
static constexpr int Nn   = 2304;      // 48*48
static constexpr int Cc   = 256;
static constexpr int NH   = 8;
static constexpr int HD   = 32;
static constexpr int HS   = 48;
static constexpr int HID  = 4 * Cc;    // 1024
static constexpr int ROWS = Bb * Nn;   // 9216
static constexpr float SCALE = 0.17677669529663687f; // 32^-0.5

// Neighbor offsets with dy*dy+dx*dx <= 9  (29 of them)
__constant__ int c_dy[29] = {-3,-2,-2,-2,-2,-2,-1,-1,-1,-1,-1, 0,0,0,0,0,0,0, 1,1,1,1,1, 2,2,2,2,2, 3};
__constant__ int c_dx[29] = { 0,-2,-1, 0, 1, 2,-2,-1, 0, 1, 2,-3,-2,-1,0,1,2,3,-2,-1,0,1,2,-2,-1,0,1,2, 0};

// ---------------------------------------------------------------------------
// Scratch (no cudaMalloc allowed)
// ---------------------------------------------------------------------------
using bf = __nv_bfloat16;
__device__ __align__(16) bf g_h_hi  [ROWS * Cc];
__device__ __align__(16) bf g_h_lo  [ROWS * Cc];
__device__ __align__(16) bf g_hk_hi [ROWS * Cc];
__device__ __align__(16) bf g_hk_lo [ROWS * Cc];
__device__ __align__(16) float g_q  [ROWS * Cc];
__device__ __align__(16) float g_kv [ROWS * 2 * Cc];     // fused K|V, stride 512
__device__ __align__(16) bf g_at_hi [ROWS * Cc];
__device__ __align__(16) bf g_at_lo [ROWS * Cc];
__device__ __align__(16) float g_x2 [ROWS * Cc];
__device__ __align__(16) bf g_m_hi  [ROWS * Cc];
__device__ __align__(16) bf g_m_lo  [ROWS * Cc];
__device__ __align__(16) bf g_t_hi  [ROWS * HID];
__device__ __align__(16) bf g_t_lo  [ROWS * HID];
// transposed + split weights: [N, K] layout
__device__ __align__(16) bf g_wq_hi [Cc * Cc];
__device__ __align__(16) bf g_wq_lo [Cc * Cc];
__device__ __align__(16) bf g_wkv_hi[2 * Cc * Cc];       // rows 0..255 = Wk^T, 256..511 = Wv^T
__device__ __align__(16) bf g_wkv_lo[2 * Cc * Cc];
__device__ __align__(16) bf g_wp_hi [Cc * Cc];
__device__ __align__(16) bf g_wp_lo [Cc * Cc];
__device__ __align__(16) bf g_w1_hi [HID * Cc];
__device__ __align__(16) bf g_w1_lo [HID * Cc];
__device__ __align__(16) bf g_w2_hi [Cc * HID];
__device__ __align__(16) bf g_w2_lo [Cc * HID];
__device__ __align__(16) float g_bkv[2 * Cc];            // bk | bv

// ---------------------------------------------------------------------------
// PTX helpers (base-ISA only: mma.sync / ldmatrix / cp.async)
// ---------------------------------------------------------------------------
__device__ __forceinline__ uint32_t smem_u32(const void* p) {
    uint32_t a;
    asm("{ .reg .u64 t; cvta.to.shared.u64 t, %1; cvt.u32.u64 %0, t; }" : "=r"(a) : "l"(p));
    return a;
}
__device__ __forceinline__ void ldsm_x4(uint32_t* r, uint32_t addr) {
    asm volatile("ldmatrix.sync.aligned.m8n8.x4.shared.b16 {%0,%1,%2,%3}, [%4];"
        : "=r"(r[0]), "=r"(r[1]), "=r"(r[2]), "=r"(r[3]) : "r"(addr));
}
__device__ __forceinline__ void mma16816(float* d, const uint32_t* a, uint32_t b0, uint32_t b1) {
    asm volatile("mma.sync.aligned.m16n8k16.row.col.f32.bf16.bf16.f32 "
        "{%0,%1,%2,%3}, {%4,%5,%6,%7}, {%8,%9}, {%0,%1,%2,%3};"
        : "+f"(d[0]), "+f"(d[1]), "+f"(d[2]), "+f"(d[3])
        : "r"(a[0]), "r"(a[1]), "r"(a[2]), "r"(a[3]), "r"(b0), "r"(b1));
}
#define CP16(dst, src) \
    asm volatile("cp.async.cg.shared.global [%0], [%1], 16;" :: "r"(dst), "l"(src))
#define CP_COMMIT()  asm volatile("cp.async.commit_group;" ::: "memory")
#define CP_WAITG(n)  asm volatile("cp.async.wait_group %0;" :: "n"(n) : "memory")

// ---------------------------------------------------------------------------
// Prep kernel: weight transpose/split + LN1(x, x_kv) + bkv concat, one launch.
// Blocks [0,768): convw tiles; [768, 768+2304): LN rows (8 warps/block).
// ---------------------------------------------------------------------------
__global__ void __launch_bounds__(256) prep_all(
    const float* __restrict__ Wq, const float* __restrict__ Wk,
    const float* __restrict__ Wv, const float* __restrict__ Wp,
    const float* __restrict__ W1, const float* __restrict__ W2,
    bf* qh, bf* ql, bf* kh, bf* kl, bf* vh, bf* vl,
    bf* ph, bf* pl, bf* h1h, bf* h1l, bf* h2h, bf* h2l,
    const float* __restrict__ x, const float* __restrict__ x_kv,
    const float* __restrict__ g1, const float* __restrict__ b1,
    bf* __restrict__ oha, bf* __restrict__ ola,
    bf* __restrict__ ohb, bf* __restrict__ olb,
    const float* __restrict__ bk, const float* __restrict__ bv,
    float* __restrict__ bkv)
{
    int bid = blockIdx.x;
    if (bid < 768) {
        // ---- weight transpose + split ----
        __shared__ float t[32][33];
        const float* W; bf* Th; bf* Tl; int K, N, tile;
        if (bid < 256) {
            int w = bid >> 6; tile = bid & 63; K = 256; N = 256;
            if      (w == 0) { W = Wq; Th = qh; Tl = ql; }
            else if (w == 1) { W = Wk; Th = kh; Tl = kl; }
            else if (w == 2) { W = Wv; Th = vh; Tl = vl; }
            else             { W = Wp; Th = ph; Tl = pl; }
        } else if (bid < 512) {
            W = W1; Th = h1h; Tl = h1l; K = 256; N = 1024; tile = bid - 256;
        } else {
            W = W2; Th = h2h; Tl = h2l; K = 1024; N = 256; tile = bid - 512;
        }
        int ntn = N >> 5;
        int tk = tile / ntn, tn = tile % ntn;
        int tx = threadIdx.x & 31, ty = threadIdx.x >> 5;
#pragma unroll
        for (int i = 0; i < 4; i++) {
            int r = ty + i * 8;
            t[r][tx] = W[(size_t)(tk * 32 + r) * N + tn * 32 + tx];
        }
        __syncthreads();
#pragma unroll
        for (int i = 0; i < 4; i++) {
            int r = ty + i * 8;
            float wv = t[tx][r];
            size_t o = (size_t)(tn * 32 + r) * K + tk * 32 + tx;
            bf h = __float2bfloat16(wv);
            Th[o] = h;
            Tl[o] = __float2bfloat16(wv - __bfloat162float(h));
        }
        // block 0 also concatenates the KV bias
        if (bid == 0) {
            bkv[threadIdx.x]       = bk[threadIdx.x];
            bkv[Cc + threadIdx.x]  = bv[threadIdx.x];
        }
    } else {
        // ---- LN1 over x (first ROWS warps) and x_kv (next ROWS warps) ----
        int gw   = (bid - 768) * 8 + ((int)threadIdx.x >> 5);
        int lane = threadIdx.x & 31;
        const float* xs = (gw < ROWS) ? x : x_kv;
        bf* oh = (gw < ROWS) ? oha : ohb;
        bf* ol = (gw < ROWS) ? ola : olb;
        int r = (gw < ROWS) ? gw : gw - ROWS;

        const float* xr = xs + (size_t)r * Cc;
        float f[8], s = 0.f, ss = 0.f;
#pragma unroll
        for (int i = 0; i < 8; i++) {
            f[i] = xr[lane + 32 * i];
            s  += f[i];
            ss += f[i] * f[i];
        }
#pragma unroll
        for (int off = 16; off; off >>= 1) {
            s  += __shfl_xor_sync(0xffffffffu, s,  off);
            ss += __shfl_xor_sync(0xffffffffu, ss, off);
        }
        float mu  = s * (1.f / 256.f);
        float var = ss * (1.f / 256.f) - mu * mu;
        float inv = rsqrtf(var + 1e-6f);
        size_t base = (size_t)r * Cc;
#pragma unroll
        for (int i = 0; i < 8; i++) {
            int c = lane + 32 * i;
            float v = (f[i] - mu) * inv * g1[c] + b1[c];
            bf hv = __float2bfloat16(v);
            oh[base + c] = hv;
            ol[base + c] = __float2bfloat16(v - __bfloat162float(hv));
        }
    }
}

// ---------------------------------------------------------------------------
// LayerNorm (LN2): one warp per row of 256; emits bf16 hi/lo
// ---------------------------------------------------------------------------
__global__ void ln_kernel(const float* __restrict__ x,
                          const float* __restrict__ g,
                          const float* __restrict__ b,
                          bf* __restrict__ oh, bf* __restrict__ ol, int rows)
{
    int gw   = (blockIdx.x * blockDim.x + threadIdx.x) >> 5;
    int lane = threadIdx.x & 31;
    if (gw >= rows) return;
    const float* xr = x + (size_t)gw * Cc;
    float f[8], s = 0.f, ss = 0.f;
#pragma unroll
    for (int i = 0; i < 8; i++) {
        f[i] = xr[lane + 32 * i];
        s  += f[i];
        ss += f[i] * f[i];
    }
#pragma unroll
    for (int off = 16; off; off >>= 1) {
        s  += __shfl_xor_sync(0xffffffffu, s,  off);
        ss += __shfl_xor_sync(0xffffffffu, ss, off);
    }
    float mu  = s * (1.f / 256.f);
    float var = ss * (1.f / 256.f) - mu * mu;
    float inv = rsqrtf(var + 1e-6f);
    size_t base = (size_t)gw * Cc;
#pragma unroll
    for (int i = 0; i < 8; i++) {
        int c = lane + 32 * i;
        float v = (f[i] - mu) * inv * g[c] + b[c];
        bf hv = __float2bfloat16(v);
        oh[base + c] = hv;
        ol[base + c] = __float2bfloat16(v - __bfloat162float(hv));
    }
}

// ---------------------------------------------------------------------------
// Tiled sparse attention (round-7 design, unchanged).
// ---------------------------------------------------------------------------
static constexpr int TQ   = 8;
static constexpr int HALO = 3;
static constexpr int SP   = TQ + 2 * HALO;   // 14
static constexpr int NPOS = SP * SP;         // 196
static constexpr int ROWF = 65;              // padded row (k 32 | v 32 | pad)
static constexpr int ATT_SMEM = NPOS * ROWF * 4;  // 50960 B

__global__ void __launch_bounds__(256) attn_tile(
    const float* __restrict__ q, const float* __restrict__ kv,
    bf* __restrict__ oh, bf* __restrict__ ol)
{
    extern __shared__ float kvs[];
    const int tid = threadIdx.x, lane = tid & 31, wid = tid >> 5;
    const int tIdx = blockIdx.x;            // 0..35
    const int h = blockIdx.y, b = blockIdx.z;
    const int ty0 = (tIdx / 6) * TQ, tx0 = (tIdx % 6) * TQ;

    for (int i = tid; i < NPOS * 16; i += 256) {
        int sp = i >> 4, c4 = i & 15;
        int ly = sp / SP, lx = sp - ly * SP;
        int ny = ty0 - HALO + ly, nx = tx0 - HALO + lx;
        float4 val = make_float4(0.f, 0.f, 0.f, 0.f);
        if ((unsigned)ny < (unsigned)HS && (unsigned)nx < (unsigned)HS) {
            size_t base = ((size_t)(b * Nn + ny * HS + nx)) * (2 * Cc) + h * HD;
            val = *(const float4*)(kv + base + (c4 < 8 ? c4 * 4 : Cc + (c4 - 8) * 4));
        }
        float* dst = &kvs[sp * ROWF + ((c4 < 8) ? c4 * 4 : 32 + (c4 - 8) * 4)];
        dst[0] = val.x; dst[1] = val.y; dst[2] = val.z; dst[3] = val.w;
    }
    __syncthreads();

    const int qy = ty0 + wid;
    int dy = 0, dx = 0;
    if (lane < 29) { dy = c_dy[lane]; dx = c_dx[lane]; }
    const bool rowok = (lane < 29) && ((unsigned)(qy + dy) < (unsigned)HS);

    const size_t qbase = ((size_t)(b * Nn + qy * HS + tx0)) * Cc + h * HD + lane;
    float qv[8];
#pragma unroll
    for (int i = 0; i < 8; i++) qv[i] = q[qbase + i * Cc];

    int sp[8]; float s[8];
#pragma unroll
    for (int i = 0; i < 8; i++) {
        sp[i] = (wid + dy + HALO) * SP + (i + dx + HALO);
        s[i] = 0.f;
    }

#pragma unroll
    for (int d = 0; d < 32; d++) {
#pragma unroll
        for (int i = 0; i < 8; i++) {
            float qd = __shfl_sync(0xffffffffu, qv[i], d);
            s[i] += kvs[sp[i] * ROWF + d] * qd;
        }
    }
    float p[8], linv[8];
#pragma unroll
    for (int i = 0; i < 8; i++) {
        bool ok = rowok && ((unsigned)(tx0 + i + dx) < (unsigned)HS);
        float sv = ok ? s[i] * SCALE : -1e30f;
        float m = sv;
#pragma unroll
        for (int off = 16; off; off >>= 1)
            m = fmaxf(m, __shfl_xor_sync(0xffffffffu, m, off));
        float e = expf(sv - m);
        float sum = e;
#pragma unroll
        for (int off = 16; off; off >>= 1)
            sum += __shfl_xor_sync(0xffffffffu, sum, off);
        p[i] = e;
        linv[i] = 1.f / sum;
    }

    float acc[8] = {};
#pragma unroll
    for (int j = 0; j < 29; j++) {
        int spj = (wid + c_dy[j] + HALO) * SP + (c_dx[j] + HALO);
#pragma unroll
        for (int i = 0; i < 8; i++) {
            float pj = __shfl_sync(0xffffffffu, p[i], j);
            acc[i] += pj * kvs[(spj + i) * ROWF + 32 + lane];
        }
    }

#pragma unroll
    for (int i = 0; i < 8; i++) {
        float res = acc[i] * linv[i];
        bf hv = __float2bfloat16(res);
        oh[qbase + i * Cc] = hv;
        ol[qbase + i * Cc] = __float2bfloat16(res - __bfloat162float(hv));
    }
}

// ---------------------------------------------------------------------------
// Split-bf16 GEMM core (round-6/7 config: 128x64 tile, BK=64, 2-stage).
// ---------------------------------------------------------------------------
static constexpr int STGB  = 49152;       // Ah 16K | Al 16K | Bh 8K | Bl 8K
static constexpr int SMTOT = 2 * STGB;    // 96 KB

template <int EPI>
__device__ __forceinline__ void gemm_core(
    const bf* __restrict__ Ah, const bf* __restrict__ Al,
    const bf* __restrict__ Bh, const bf* __restrict__ Bl,
    const float* __restrict__ bias, const float* __restrict__ res,
    float* __restrict__ Co, bf* __restrict__ oH, bf* __restrict__ oL,
    int N, int K, int tm, int tn)
{
    extern __shared__ __align__(1024) char smc[];
    const uint32_t sbase = smem_u32(smc);
    const int tid  = threadIdx.x;
    const int lane = tid & 31;
    const int wid  = tid >> 5;
    const int wm = wid >> 1, wn = wid & 1;   // 4 x 2 warp grid, warp tile 32x32

    const size_t strK = (size_t)K * 2;
    const char* pAh = (const char*)Ah + ((size_t)tm * 128) * strK;
    const char* pAl = (const char*)Al + ((size_t)tm * 128) * strK;
    const char* pBh = (const char*)Bh + ((size_t)tn * 64)  * strK;
    const char* pBl = (const char*)Bl + ((size_t)tn * 64)  * strK;

    const int nCh = K >> 6;

    auto load_stage = [&](int stg, int ch) {
        uint32_t d0 = sbase + stg * STGB;
        size_t koff = (size_t)ch * 128;
#pragma unroll
        for (int i = 0; i < 8; i++) {
            int g = i * 256 + tid;
            int prec = g >> 10;
            int gg = g & 1023;
            int r = gg >> 3, c = gg & 7;
            const char* src = (prec ? pAl : pAh) + (size_t)r * strK + koff + (c << 4);
            uint32_t dst = d0 + prec * 16384 + (r << 7) + ((c ^ (r & 7)) << 4);
            CP16(dst, src);
        }
#pragma unroll
        for (int i = 0; i < 4; i++) {
            int g = i * 256 + tid;
            int prec = g >> 9;
            int gg = g & 511;
            int r = gg >> 3, c = gg & 7;
            const char* src = (prec ? pBl : pBh) + (size_t)r * strK + koff + (c << 4);
            uint32_t dst = d0 + 32768 + prec * 8192 + (r << 7) + ((c ^ (r & 7)) << 4);
            CP16(dst, src);
        }
        CP_COMMIT();
    };

    const int rl = lane & 15;
    const int kc = lane >> 4;

    float acc[2][4][4] = {};

    load_stage(0, 0);

    for (int ch = 0; ch < nCh; ch++) {
        if (ch + 1 < nCh) { load_stage((ch + 1) & 1, ch + 1); CP_WAITG(1); }
        else              { CP_WAITG(0); }
        __syncthreads();

        uint32_t aB = sbase + (ch & 1) * STGB;
        uint32_t bB = aB + 32768;

#pragma unroll
        for (int k16 = 0; k16 < 4; k16++) {
            const int k2 = k16 * 2 + kc;
            uint32_t ah[2][4], al[2][4], bh[2][4], bl[2][4];
#pragma unroll
            for (int f = 0; f < 2; f++) {
                int rA = wm * 32 + f * 16 + rl;
                uint32_t rb = aB + (rA << 7);
                int rx = rA & 7;
                ldsm_x4(ah[f], rb + ((k2 ^ rx) << 4));
                ldsm_x4(al[f], rb + 16384 + ((k2 ^ rx) << 4));
            }
            {
                int rB0 = wn * 32 + rl, rB1 = wn * 32 + 16 + rl;
                uint32_t rb0 = bB + (rB0 << 7), rb1 = bB + (rB1 << 7);
                int rx0 = rB0 & 7, rx1 = rB1 & 7;
                ldsm_x4(bh[0], rb0 + ((k2 ^ rx0) << 4));
                ldsm_x4(bh[1], rb1 + ((k2 ^ rx1) << 4));
                ldsm_x4(bl[0], rb0 + 8192 + ((k2 ^ rx0) << 4));
                ldsm_x4(bl[1], rb1 + 8192 + ((k2 ^ rx1) << 4));
            }
#pragma unroll
            for (int f = 0; f < 2; f++)
#pragma unroll
                for (int j = 0; j < 4; j++)
                    mma16816(acc[f][j], ah[f], bh[j >> 1][j & 1], bh[j >> 1][2 + (j & 1)]);
#pragma unroll
            for (int f = 0; f < 2; f++)
#pragma unroll
                for (int j = 0; j < 4; j++)
                    mma16816(acc[f][j], al[f], bh[j >> 1][j & 1], bh[j >> 1][2 + (j & 1)]);
#pragma unroll
            for (int f = 0; f < 2; f++)
#pragma unroll
                for (int j = 0; j < 4; j++)
                    mma16816(acc[f][j], ah[f], bl[j >> 1][j & 1], bl[j >> 1][2 + (j & 1)]);
        }
        __syncthreads();
    }

    const int rbase = tm * 128 + wm * 32 + (lane >> 2);
    const int cbase = tn * 64 + wn * 32 + (lane & 3) * 2;
#pragma unroll
    for (int f = 0; f < 2; f++) {
#pragma unroll
        for (int j = 0; j < 4; j++) {
            int row0 = rbase + f * 16;
            int col  = cbase + j * 8;
            float b0 = bias[col], b1 = bias[col + 1];
            float v00 = acc[f][j][0] + b0;
            float v01 = acc[f][j][1] + b1;
            float v10 = acc[f][j][2] + b0;
            float v11 = acc[f][j][3] + b1;
            size_t i0 = (size_t)row0 * N + col;
            size_t i1 = (size_t)(row0 + 8) * N + col;
            if (EPI == 0) {
                *(float2*)(Co + i0) = make_float2(v00, v01);
                *(float2*)(Co + i1) = make_float2(v10, v11);
            } else if (EPI == 1) {
                float2 r0 = *(const float2*)(res + i0);
                float2 r1 = *(const float2*)(res + i1);
                *(float2*)(Co + i0) = make_float2(v00 + r0.x, v01 + r0.y);
                *(float2*)(Co + i1) = make_float2(v10 + r1.x, v11 + r1.y);
            } else {
                const float IS2 = 0.70710678118654752f;
                v00 = 0.5f * v00 * (1.f + erff(v00 * IS2));
                v01 = 0.5f * v01 * (1.f + erff(v01 * IS2));
                v10 = 0.5f * v10 * (1.f + erff(v10 * IS2));
                v11 = 0.5f * v11 * (1.f + erff(v11 * IS2));
                bf h00 = __float2bfloat16(v00), h01 = __float2bfloat16(v01);
                bf h10 = __float2bfloat16(v10), h11 = __float2bfloat16(v11);
                __nv_bfloat162 hh0; hh0.x = h00; hh0.y = h01;
                __nv_bfloat162 hh1; hh1.x = h10; hh1.y = h11;
                *(__nv_bfloat162*)(oH + i0) = hh0;
                *(__nv_bfloat162*)(oH + i1) = hh1;
                __nv_bfloat162 ll0, ll1;
                ll0.x = __float2bfloat16(v00 - __bfloat162float(h00));
                ll0.y = __float2bfloat16(v01 - __bfloat162float(h01));
                ll1.x = __float2bfloat16(v10 - __bfloat162float(h10));
                ll1.y = __float2bfloat16(v11 - __bfloat162float(h11));
                *(__nv_bfloat162*)(oL + i0) = ll0;
                *(__nv_bfloat162*)(oL + i1) = ll1;
            }
        }
    }
}

template <int EPI>
__global__ void __launch_bounds__(256, 2) mma_gemm(
    const bf* __restrict__ Ah, const bf* __restrict__ Al,
    const bf* __restrict__ Bh, const bf* __restrict__ Bl,
    const float* __restrict__ bias, const float* __restrict__ res,
    float* __restrict__ Co, bf* __restrict__ oH, bf* __restrict__ oL,
    int N, int K)
{
    gemm_core<EPI>(Ah, Al, Bh, Bl, bias, res, Co, oH, oL,
                   N, K, blockIdx.y, blockIdx.x);
}

// Merged Q + KV projection: blockIdx.x < 4 -> Q (N=256); else KV (N=512).
__global__ void __launch_bounds__(256, 2) proj_qkv(
    const bf* __restrict__ hh,  const bf* __restrict__ hl,
    const bf* __restrict__ kh,  const bf* __restrict__ kl,
    const bf* __restrict__ wqh, const bf* __restrict__ wql,
    const bf* __restrict__ wkh, const bf* __restrict__ wkl,
    const float* __restrict__ bq, const float* __restrict__ bkv,
    float* __restrict__ qo, float* __restrict__ kvo)
{
    if (blockIdx.x < 4) {
        gemm_core<0>(hh, hl, wqh, wql, bq, nullptr, qo, nullptr, nullptr,
                     Cc, Cc, blockIdx.y, blockIdx.x);
    } else {
        gemm_core<0>(kh, kl, wkh, wkl, bkv, nullptr, kvo, nullptr, nullptr,
                     2 * Cc, Cc, blockIdx.y, blockIdx.x - 4);
    }
}

// ---------------------------------------------------------------------------
// Launch
// ---------------------------------------------------------------------------
template <typename T>
static T* symaddr(const void* sym)
{
    void* p = nullptr;
    cudaGetSymbolAddress(&p, sym);
    return (T*)p;
}

extern "C" void kernel_launch(void* const* d_in, const int* in_sizes, int n_in,
                              void* d_out, int out_size)
{
    const float* x    = (const float*)d_in[0];
    const float* x_kv = (const float*)d_in[1];
    const float* Wq   = (const float*)d_in[2];
    const float* bq   = (const float*)d_in[3];
    const float* Wk   = (const float*)d_in[4];
    const float* bk   = (const float*)d_in[5];
    const float* Wv   = (const float*)d_in[6];
    const float* bv   = (const float*)d_in[7];
    const float* Wp   = (const float*)d_in[8];
    const float* bp   = (const float*)d_in[9];
    const float* g1   = (const float*)d_in[10];
    const float* b1   = (const float*)d_in[11];
    const float* g2   = (const float*)d_in[12];
    const float* b2   = (const float*)d_in[13];
    const float* W1   = (const float*)d_in[14];
    const float* bm1  = (const float*)d_in[15];
    const float* W2   = (const float*)d_in[16];
    const float* bm2  = (const float*)d_in[17];
    float* out = (float*)d_out;

    bf* h_hi  = symaddr<bf>(g_h_hi);   bf* h_lo  = symaddr<bf>(g_h_lo);
    bf* hk_hi = symaddr<bf>(g_hk_hi);  bf* hk_lo = symaddr<bf>(g_hk_lo);
    float* qb  = symaddr<float>(g_q);
    float* kvb = symaddr<float>(g_kv);
    bf* at_hi = symaddr<bf>(g_at_hi);  bf* at_lo = symaddr<bf>(g_at_lo);
    float* x2 = symaddr<float>(g_x2);
    bf* m_hi  = symaddr<bf>(g_m_hi);   bf* m_lo  = symaddr<bf>(g_m_lo);
    bf* t_hi  = symaddr<bf>(g_t_hi);   bf* t_lo  = symaddr<bf>(g_t_lo);
    bf* wq_hi  = symaddr<bf>(g_wq_hi);  bf* wq_lo  = symaddr<bf>(g_wq_lo);
    bf* wkv_hi = symaddr<bf>(g_wkv_hi); bf* wkv_lo = symaddr<bf>(g_wkv_lo);
    bf* wp_hi  = symaddr<bf>(g_wp_hi);  bf* wp_lo  = symaddr<bf>(g_wp_lo);
    bf* w1_hi  = symaddr<bf>(g_w1_hi);  bf* w1_lo  = symaddr<bf>(g_w1_lo);
    bf* w2_hi  = symaddr<bf>(g_w2_hi);  bf* w2_lo  = symaddr<bf>(g_w2_lo);
    float* bkv = symaddr<float>(g_bkv);

    static bool attrSet = false;
    if (!attrSet) {
        cudaFuncSetAttribute(mma_gemm<1>, cudaFuncAttributeMaxDynamicSharedMemorySize, SMTOT);
        cudaFuncSetAttribute(mma_gemm<2>, cudaFuncAttributeMaxDynamicSharedMemorySize, SMTOT);
        cudaFuncSetAttribute(proj_qkv,    cudaFuncAttributeMaxDynamicSharedMemorySize, SMTOT);
        cudaFuncSetAttribute(attn_tile,   cudaFuncAttributeMaxDynamicSharedMemorySize, ATT_SMEM);
        attrSet = true;
    }

    // Prep: weight transpose/split + LN1(x, x_kv) + bkv concat (one launch)
    prep_all<<<768 + 2304, 256>>>(Wq, Wk, Wv, Wp, W1, W2,
                                  wq_hi, wq_lo,
                                  wkv_hi, wkv_lo,
                                  wkv_hi + Cc * Cc, wkv_lo + Cc * Cc,
                                  wp_hi, wp_lo, w1_hi, w1_lo, w2_hi, w2_lo,
                                  x, x_kv, g1, b1,
                                  h_hi, h_lo, hk_hi, hk_lo,
                                  bk, bv, bkv);

    // Q + KV projections merged: grid (4+8) x 72 = 864 CTAs
    {
        dim3 g(12, ROWS / 128);
        proj_qkv<<<g, 256, SMTOT>>>(h_hi, h_lo, hk_hi, hk_lo,
                                    wq_hi, wq_lo, wkv_hi, wkv_lo,
                                    bq, bkv, qb, kvb);
    }

    // Tiled sparse attention
    {
        dim3 ga(36, NH, Bb);
        attn_tile<<<ga, 256, ATT_SMEM>>>(qb, kvb, at_hi, at_lo);
    }

    // x2 = x + att @ Wp + bp
    {
        dim3 grid(Cc / 64, ROWS / 128);
        mma_gemm<1><<<grid, 256, SMTOT>>>(at_hi, at_lo, wp_hi, wp_lo, bp, x, x2, nullptr, nullptr, Cc, Cc);
    }

    // LN2
    ln_kernel<<<ROWS / 8, 256>>>(x2, g2, b2, m_hi, m_lo, ROWS);

    // MLP
    {
        dim3 grid1(HID / 64, ROWS / 128);
        mma_gemm<2><<<grid1, 256, SMTOT>>>(m_hi, m_lo, w1_hi, w1_lo, bm1, nullptr, nullptr, t_hi, t_lo, HID, Cc);
        dim3 grid2(Cc / 64, ROWS / 128);
        mma_gemm<1><<<grid2, 256, SMTOT>>>(t_hi, t_lo, w2_hi, w2_lo, bm2, x2, out, nullptr, nullptr, Cc, HID);
    }
}

// round 9
// speedup vs baseline: 1.7768x; 1.1930x over previous
#include <cuda_runtime.h>
#include <cuda_fp16.h>
#include <math.h>
#include <cstdint>

// ---------------------------------------------------------------------------
// Problem constants
// ---------------------------------------------------------------------------
static constexpr int Bb   = 4;
static constexpr int Nn   = 2304;      // 48*48
static constexpr int Cc   = 256;
static constexpr int NH   = 8;
static constexpr int HD   = 32;
static constexpr int HS   = 48;
static constexpr int HID  = 4 * Cc;    // 1024
static constexpr int ROWS = Bb * Nn;   // 9216
static constexpr float SCALE = 0.17677669529663687f; // 32^-0.5

// Neighbor offsets with dy*dy+dx*dx <= 9  (29 of them)
__constant__ int c_dy[29] = {-3,-2,-2,-2,-2,-2,-1,-1,-1,-1,-1, 0,0,0,0,0,0,0, 1,1,1,1,1, 2,2,2,2,2, 3};
__constant__ int c_dx[29] = { 0,-2,-1, 0, 1, 2,-2,-1, 0, 1, 2,-3,-2,-1,0,1,2,3,-2,-1,0,1,2,-2,-1,0,1,2, 0};

// ---------------------------------------------------------------------------
// Scratch (no cudaMalloc allowed)
// ---------------------------------------------------------------------------
using hf = __half;
__device__ __align__(16) hf g_h_hi  [ROWS * Cc];
__device__ __align__(16) hf g_h_lo  [ROWS * Cc];
__device__ __align__(16) hf g_hk_hi [ROWS * Cc];
__device__ __align__(16) hf g_hk_lo [ROWS * Cc];
__device__ __align__(16) float g_q  [ROWS * Cc];
__device__ __align__(16) float g_kv [ROWS * 2 * Cc];     // fused K|V, stride 512
__device__ __align__(16) hf g_at_hi [ROWS * Cc];
__device__ __align__(16) hf g_at_lo [ROWS * Cc];
__device__ __align__(16) float g_x2 [ROWS * Cc];
__device__ __align__(16) hf g_m_hi  [ROWS * Cc];
__device__ __align__(16) hf g_m_lo  [ROWS * Cc];
__device__ __align__(16) hf g_t_hi  [ROWS * HID];
__device__ __align__(16) hf g_t_lo  [ROWS * HID];
// transposed weights (single fp16): [N, K] layout
__device__ __align__(16) hf g_wq  [Cc * Cc];
__device__ __align__(16) hf g_wkv [2 * Cc * Cc];         // rows 0..255 = Wk^T, 256..511 = Wv^T
__device__ __align__(16) hf g_wp  [Cc * Cc];
__device__ __align__(16) hf g_w1  [HID * Cc];
__device__ __align__(16) hf g_w2  [Cc * HID];
__device__ __align__(16) float g_bkv[2 * Cc];            // bk | bv

// ---------------------------------------------------------------------------
// PTX helpers (base-ISA only: mma.sync / ldmatrix / cp.async)
// ---------------------------------------------------------------------------
__device__ __forceinline__ uint32_t smem_u32(const void* p) {
    uint32_t a;
    asm("{ .reg .u64 t; cvta.to.shared.u64 t, %1; cvt.u32.u64 %0, t; }" : "=r"(a) : "l"(p));
    return a;
}
__device__ __forceinline__ void ldsm_x4(uint32_t* r, uint32_t addr) {
    asm volatile("ldmatrix.sync.aligned.m8n8.x4.shared.b16 {%0,%1,%2,%3}, [%4];"
        : "=r"(r[0]), "=r"(r[1]), "=r"(r[2]), "=r"(r[3]) : "r"(addr));
}
__device__ __forceinline__ void mma16816(float* d, const uint32_t* a, uint32_t b0, uint32_t b1) {
    asm volatile("mma.sync.aligned.m16n8k16.row.col.f32.f16.f16.f32 "
        "{%0,%1,%2,%3}, {%4,%5,%6,%7}, {%8,%9}, {%0,%1,%2,%3};"
        : "+f"(d[0]), "+f"(d[1]), "+f"(d[2]), "+f"(d[3])
        : "r"(a[0]), "r"(a[1]), "r"(a[2]), "r"(a[3]), "r"(b0), "r"(b1));
}
#define CP16(dst, src) \
    asm volatile("cp.async.cg.shared.global [%0], [%1], 16;" :: "r"(dst), "l"(src))
#define CP_COMMIT()  asm volatile("cp.async.commit_group;" ::: "memory")
#define CP_WAITG(n)  asm volatile("cp.async.wait_group %0;" :: "n"(n) : "memory")

__device__ __forceinline__ void split_store(hf* oh, hf* ol, size_t idx, float v) {
    hf h = __float2half_rn(v);
    oh[idx] = h;
    ol[idx] = __float2half_rn(v - __half2float(h));
}

// ---------------------------------------------------------------------------
// Prep kernel: weight transpose (single fp16) + LN1(x, x_kv) + bkv concat.
// Blocks [0,768): weight tiles; [768, 768+2304): LN rows (8 warps/block).
// ---------------------------------------------------------------------------
__global__ void __launch_bounds__(256) prep_all(
    const float* __restrict__ Wq, const float* __restrict__ Wk,
    const float* __restrict__ Wv, const float* __restrict__ Wp,
    const float* __restrict__ W1, const float* __restrict__ W2,
    hf* qT, hf* kT, hf* vT, hf* pT, hf* h1T, hf* h2T,
    const float* __restrict__ x, const float* __restrict__ x_kv,
    const float* __restrict__ g1, const float* __restrict__ b1,
    hf* __restrict__ oha, hf* __restrict__ ola,
    hf* __restrict__ ohb, hf* __restrict__ olb,
    const float* __restrict__ bk, const float* __restrict__ bv,
    float* __restrict__ bkv)
{
    int bid = blockIdx.x;
    if (bid < 768) {
        __shared__ float t[32][33];
        const float* W; hf* Th; int K, N, tile;
        if (bid < 256) {
            int w = bid >> 6; tile = bid & 63; K = 256; N = 256;
            if      (w == 0) { W = Wq; Th = qT; }
            else if (w == 1) { W = Wk; Th = kT; }
            else if (w == 2) { W = Wv; Th = vT; }
            else             { W = Wp; Th = pT; }
        } else if (bid < 512) {
            W = W1; Th = h1T; K = 256; N = 1024; tile = bid - 256;
        } else {
            W = W2; Th = h2T; K = 1024; N = 256; tile = bid - 512;
        }
        int ntn = N >> 5;
        int tk = tile / ntn, tn = tile % ntn;
        int tx = threadIdx.x & 31, ty = threadIdx.x >> 5;
#pragma unroll
        for (int i = 0; i < 4; i++) {
            int r = ty + i * 8;
            t[r][tx] = W[(size_t)(tk * 32 + r) * N + tn * 32 + tx];
        }
        __syncthreads();
#pragma unroll
        for (int i = 0; i < 4; i++) {
            int r = ty + i * 8;
            Th[(size_t)(tn * 32 + r) * K + tk * 32 + tx] = __float2half_rn(t[tx][r]);
        }
        if (bid == 0) {
            bkv[threadIdx.x]      = bk[threadIdx.x];
            bkv[Cc + threadIdx.x] = bv[threadIdx.x];
        }
    } else {
        int gw   = (bid - 768) * 8 + ((int)threadIdx.x >> 5);
        int lane = threadIdx.x & 31;
        const float* xs = (gw < ROWS) ? x : x_kv;
        hf* oh = (gw < ROWS) ? oha : ohb;
        hf* ol = (gw < ROWS) ? ola : olb;
        int r = (gw < ROWS) ? gw : gw - ROWS;

        const float* xr = xs + (size_t)r * Cc;
        float f[8], s = 0.f, ss = 0.f;
#pragma unroll
        for (int i = 0; i < 8; i++) {
            f[i] = xr[lane + 32 * i];
            s  += f[i];
            ss += f[i] * f[i];
        }
#pragma unroll
        for (int off = 16; off; off >>= 1) {
            s  += __shfl_xor_sync(0xffffffffu, s,  off);
            ss += __shfl_xor_sync(0xffffffffu, ss, off);
        }
        float mu  = s * (1.f / 256.f);
        float var = ss * (1.f / 256.f) - mu * mu;
        float inv = rsqrtf(var + 1e-6f);
        size_t base = (size_t)r * Cc;
#pragma unroll
        for (int i = 0; i < 8; i++) {
            int c = lane + 32 * i;
            float v = (f[i] - mu) * inv * g1[c] + b1[c];
            split_store(oh, ol, base + c, v);
        }
    }
}

// ---------------------------------------------------------------------------
// LayerNorm (LN2): one warp per row of 256; emits fp16 hi/lo
// ---------------------------------------------------------------------------
__global__ void ln_kernel(const float* __restrict__ x,
                          const float* __restrict__ g,
                          const float* __restrict__ b,
                          hf* __restrict__ oh, hf* __restrict__ ol, int rows)
{
    int gw   = (blockIdx.x * blockDim.x + threadIdx.x) >> 5;
    int lane = threadIdx.x & 31;
    if (gw >= rows) return;
    const float* xr = x + (size_t)gw * Cc;
    float f[8], s = 0.f, ss = 0.f;
#pragma unroll
    for (int i = 0; i < 8; i++) {
        f[i] = xr[lane + 32 * i];
        s  += f[i];
        ss += f[i] * f[i];
    }
#pragma unroll
    for (int off = 16; off; off >>= 1) {
        s  += __shfl_xor_sync(0xffffffffu, s,  off);
        ss += __shfl_xor_sync(0xffffffffu, ss, off);
    }
    float mu  = s * (1.f / 256.f);
    float var = ss * (1.f / 256.f) - mu * mu;
    float inv = rsqrtf(var + 1e-6f);
    size_t base = (size_t)gw * Cc;
#pragma unroll
    for (int i = 0; i < 8; i++) {
        int c = lane + 32 * i;
        float v = (f[i] - mu) * inv * g[c] + b[c];
        split_store(oh, ol, base + c, v);
    }
}

// ---------------------------------------------------------------------------
// Tiled sparse attention (round-7 design; emits fp16 hi/lo).
// ---------------------------------------------------------------------------
static constexpr int TQ   = 8;
static constexpr int HALO = 3;
static constexpr int SP   = TQ + 2 * HALO;   // 14
static constexpr int NPOS = SP * SP;         // 196
static constexpr int ROWF = 65;              // padded row (k 32 | v 32 | pad)
static constexpr int ATT_SMEM = NPOS * ROWF * 4;  // 50960 B

__global__ void __launch_bounds__(256) attn_tile(
    const float* __restrict__ q, const float* __restrict__ kv,
    hf* __restrict__ oh, hf* __restrict__ ol)
{
    extern __shared__ float kvs[];
    const int tid = threadIdx.x, lane = tid & 31, wid = tid >> 5;
    const int tIdx = blockIdx.x;            // 0..35
    const int h = blockIdx.y, b = blockIdx.z;
    const int ty0 = (tIdx / 6) * TQ, tx0 = (tIdx % 6) * TQ;

    for (int i = tid; i < NPOS * 16; i += 256) {
        int sp = i >> 4, c4 = i & 15;
        int ly = sp / SP, lx = sp - ly * SP;
        int ny = ty0 - HALO + ly, nx = tx0 - HALO + lx;
        float4 val = make_float4(0.f, 0.f, 0.f, 0.f);
        if ((unsigned)ny < (unsigned)HS && (unsigned)nx < (unsigned)HS) {
            size_t base = ((size_t)(b * Nn + ny * HS + nx)) * (2 * Cc) + h * HD;
            val = *(const float4*)(kv + base + (c4 < 8 ? c4 * 4 : Cc + (c4 - 8) * 4));
        }
        float* dst = &kvs[sp * ROWF + ((c4 < 8) ? c4 * 4 : 32 + (c4 - 8) * 4)];
        dst[0] = val.x; dst[1] = val.y; dst[2] = val.z; dst[3] = val.w;
    }
    __syncthreads();

    const int qy = ty0 + wid;
    int dy = 0, dx = 0;
    if (lane < 29) { dy = c_dy[lane]; dx = c_dx[lane]; }
    const bool rowok = (lane < 29) && ((unsigned)(qy + dy) < (unsigned)HS);

    const size_t qbase = ((size_t)(b * Nn + qy * HS + tx0)) * Cc + h * HD + lane;
    float qv[8];
#pragma unroll
    for (int i = 0; i < 8; i++) qv[i] = q[qbase + i * Cc];

    int sp[8]; float s[8];
#pragma unroll
    for (int i = 0; i < 8; i++) {
        sp[i] = (wid + dy + HALO) * SP + (i + dx + HALO);
        s[i] = 0.f;
    }

#pragma unroll
    for (int d = 0; d < 32; d++) {
#pragma unroll
        for (int i = 0; i < 8; i++) {
            float qd = __shfl_sync(0xffffffffu, qv[i], d);
            s[i] += kvs[sp[i] * ROWF + d] * qd;
        }
    }
    float p[8], linv[8];
#pragma unroll
    for (int i = 0; i < 8; i++) {
        bool ok = rowok && ((unsigned)(tx0 + i + dx) < (unsigned)HS);
        float sv = ok ? s[i] * SCALE : -1e30f;
        float m = sv;
#pragma unroll
        for (int off = 16; off; off >>= 1)
            m = fmaxf(m, __shfl_xor_sync(0xffffffffu, m, off));
        float e = expf(sv - m);
        float sum = e;
#pragma unroll
        for (int off = 16; off; off >>= 1)
            sum += __shfl_xor_sync(0xffffffffu, sum, off);
        p[i] = e;
        linv[i] = 1.f / sum;
    }

    float acc[8] = {};
#pragma unroll
    for (int j = 0; j < 29; j++) {
        int spj = (wid + c_dy[j] + HALO) * SP + (c_dx[j] + HALO);
#pragma unroll
        for (int i = 0; i < 8; i++) {
            float pj = __shfl_sync(0xffffffffu, p[i], j);
            acc[i] += pj * kvs[(spj + i) * ROWF + 32 + lane];
        }
    }

#pragma unroll
    for (int i = 0; i < 8; i++)
        split_store(oh, ol, qbase + i * Cc, acc[i] * linv[i]);
}

// ---------------------------------------------------------------------------
// fp16 2-pass GEMM via mma.sync (HMMA).
// C[M,N] = (Ah+Al)[M,K] @ B^T[N,K]   (A residual beyond 22 bits dropped;
// B single fp16, half-ulp 2^-12)
// CTA tile 128x64, 8 warps (4x2), warp tile 32x32, BK=64,
// cp.async 2-stage, XOR-swizzled 128B rows.
// Stage: Ah 16K | Al 16K | B 8K = 40K; 2 stages = 80K -> 2 CTAs/SM.
// EPI: 0 -> Co = acc+bias ; 1 -> Co = acc+bias+res ; 2 -> gelu -> fp16 hi/lo
// ---------------------------------------------------------------------------
static constexpr int STGB  = 40960;
static constexpr int SMTOT = 2 * STGB;    // 80 KB

template <int EPI>
__device__ __forceinline__ void gemm_core(
    const hf* __restrict__ Ah, const hf* __restrict__ Al,
    const hf* __restrict__ B,
    const float* __restrict__ bias, const float* __restrict__ res,
    float* __restrict__ Co, hf* __restrict__ oH, hf* __restrict__ oL,
    int N, int K, int tm, int tn)
{
    extern __shared__ __align__(1024) char smc[];
    const uint32_t sbase = smem_u32(smc);
    const int tid  = threadIdx.x;
    const int lane = tid & 31;
    const int wid  = tid >> 5;
    const int wm = wid >> 1, wn = wid & 1;   // 4 x 2 warp grid, warp tile 32x32

    const size_t strK = (size_t)K * 2;
    const char* pAh = (const char*)Ah + ((size_t)tm * 128) * strK;
    const char* pAl = (const char*)Al + ((size_t)tm * 128) * strK;
    const char* pB  = (const char*)B  + ((size_t)tn * 64)  * strK;

    const int nCh = K >> 6;

    auto load_stage = [&](int stg, int ch) {
        uint32_t d0 = sbase + stg * STGB;
        size_t koff = (size_t)ch * 128;
        // A: 2048 granules of 16B (hi 1024 then lo 1024)
#pragma unroll
        for (int i = 0; i < 8; i++) {
            int g = i * 256 + tid;
            int prec = g >> 10;
            int gg = g & 1023;
            int r = gg >> 3, c = gg & 7;
            const char* src = (prec ? pAl : pAh) + (size_t)r * strK + koff + (c << 4);
            uint32_t dst = d0 + prec * 16384 + (r << 7) + ((c ^ (r & 7)) << 4);
            CP16(dst, src);
        }
        // B: 512 granules
#pragma unroll
        for (int i = 0; i < 2; i++) {
            int g = i * 256 + tid;
            int r = g >> 3, c = g & 7;
            const char* src = pB + (size_t)r * strK + koff + (c << 4);
            uint32_t dst = d0 + 32768 + (r << 7) + ((c ^ (r & 7)) << 4);
            CP16(dst, src);
        }
        CP_COMMIT();
    };

    const int rl = lane & 15;
    const int kc = lane >> 4;

    float acc[2][4][4] = {};

    load_stage(0, 0);

    for (int ch = 0; ch < nCh; ch++) {
        if (ch + 1 < nCh) { load_stage((ch + 1) & 1, ch + 1); CP_WAITG(1); }
        else              { CP_WAITG(0); }
        __syncthreads();

        uint32_t aB = sbase + (ch & 1) * STGB;
        uint32_t bB = aB + 32768;

#pragma unroll
        for (int k16 = 0; k16 < 4; k16++) {
            const int k2 = k16 * 2 + kc;
            uint32_t ah[2][4], al[2][4], bb[2][4];
#pragma unroll
            for (int f = 0; f < 2; f++) {
                int rA = wm * 32 + f * 16 + rl;
                uint32_t rb = aB + (rA << 7);
                int rx = rA & 7;
                ldsm_x4(ah[f], rb + ((k2 ^ rx) << 4));
                ldsm_x4(al[f], rb + 16384 + ((k2 ^ rx) << 4));
            }
            {
                int rB0 = wn * 32 + rl, rB1 = wn * 32 + 16 + rl;
                uint32_t rb0 = bB + (rB0 << 7), rb1 = bB + (rB1 << 7);
                int rx0 = rB0 & 7, rx1 = rB1 & 7;
                ldsm_x4(bb[0], rb0 + ((k2 ^ rx0) << 4));
                ldsm_x4(bb[1], rb1 + ((k2 ^ rx1) << 4));
            }
#pragma unroll
            for (int f = 0; f < 2; f++)
#pragma unroll
                for (int j = 0; j < 4; j++)
                    mma16816(acc[f][j], ah[f], bb[j >> 1][j & 1], bb[j >> 1][2 + (j & 1)]);
#pragma unroll
            for (int f = 0; f < 2; f++)
#pragma unroll
                for (int j = 0; j < 4; j++)
                    mma16816(acc[f][j], al[f], bb[j >> 1][j & 1], bb[j >> 1][2 + (j & 1)]);
        }
        __syncthreads();
    }

    const int rbase = tm * 128 + wm * 32 + (lane >> 2);
    const int cbase = tn * 64 + wn * 32 + (lane & 3) * 2;
#pragma unroll
    for (int f = 0; f < 2; f++) {
#pragma unroll
        for (int j = 0; j < 4; j++) {
            int row0 = rbase + f * 16;
            int col  = cbase + j * 8;
            float b0 = bias[col], b1 = bias[col + 1];
            float v00 = acc[f][j][0] + b0;
            float v01 = acc[f][j][1] + b1;
            float v10 = acc[f][j][2] + b0;
            float v11 = acc[f][j][3] + b1;
            size_t i0 = (size_t)row0 * N + col;
            size_t i1 = (size_t)(row0 + 8) * N + col;
            if (EPI == 0) {
                *(float2*)(Co + i0) = make_float2(v00, v01);
                *(float2*)(Co + i1) = make_float2(v10, v11);
            } else if (EPI == 1) {
                float2 r0 = *(const float2*)(res + i0);
                float2 r1 = *(const float2*)(res + i1);
                *(float2*)(Co + i0) = make_float2(v00 + r0.x, v01 + r0.y);
                *(float2*)(Co + i1) = make_float2(v10 + r1.x, v11 + r1.y);
            } else {
                const float IS2 = 0.70710678118654752f;
                v00 = 0.5f * v00 * (1.f + erff(v00 * IS2));
                v01 = 0.5f * v01 * (1.f + erff(v01 * IS2));
                v10 = 0.5f * v10 * (1.f + erff(v10 * IS2));
                v11 = 0.5f * v11 * (1.f + erff(v11 * IS2));
                hf h00 = __float2half_rn(v00), h01 = __float2half_rn(v01);
                hf h10 = __float2half_rn(v10), h11 = __float2half_rn(v11);
                __half2 hh0; hh0.x = h00; hh0.y = h01;
                __half2 hh1; hh1.x = h10; hh1.y = h11;
                *(__half2*)(oH + i0) = hh0;
                *(__half2*)(oH + i1) = hh1;
                __half2 ll0, ll1;
                ll0.x = __float2half_rn(v00 - __half2float(h00));
                ll0.y = __float2half_rn(v01 - __half2float(h01));
                ll1.x = __float2half_rn(v10 - __half2float(h10));
                ll1.y = __float2half_rn(v11 - __half2float(h11));
                *(__half2*)(oL + i0) = ll0;
                *(__half2*)(oL + i1) = ll1;
            }
        }
    }
}

template <int EPI>
__global__ void __launch_bounds__(256, 2) mma_gemm(
    const hf* __restrict__ Ah, const hf* __restrict__ Al,
    const hf* __restrict__ B,
    const float* __restrict__ bias, const float* __restrict__ res,
    float* __restrict__ Co, hf* __restrict__ oH, hf* __restrict__ oL,
    int N, int K)
{
    gemm_core<EPI>(Ah, Al, B, bias, res, Co, oH, oL,
                   N, K, blockIdx.y, blockIdx.x);
}

// Merged Q + KV projection: blockIdx.x < 4 -> Q (N=256); else KV (N=512).
__global__ void __launch_bounds__(256, 2) proj_qkv(
    const hf* __restrict__ hh,  const hf* __restrict__ hl,
    const hf* __restrict__ kh,  const hf* __restrict__ kl,
    const hf* __restrict__ wq,  const hf* __restrict__ wkv,
    const float* __restrict__ bq, const float* __restrict__ bkv,
    float* __restrict__ qo, float* __restrict__ kvo)
{
    if (blockIdx.x < 4) {
        gemm_core<0>(hh, hl, wq, bq, nullptr, qo, nullptr, nullptr,
                     Cc, Cc, blockIdx.y, blockIdx.x);
    } else {
        gemm_core<0>(kh, kl, wkv, bkv, nullptr, kvo, nullptr, nullptr,
                     2 * Cc, Cc, blockIdx.y, blockIdx.x - 4);
    }
}

// ---------------------------------------------------------------------------
// Launch
// ---------------------------------------------------------------------------
template <typename T>
static T* symaddr(const void* sym)
{
    void* p = nullptr;
    cudaGetSymbolAddress(&p, sym);
    return (T*)p;
}

extern "C" void kernel_launch(void* const* d_in, const int* in_sizes, int n_in,
                              void* d_out, int out_size)
{
    const float* x    = (const float*)d_in[0];
    const float* x_kv = (const float*)d_in[1];
    const float* Wq   = (const float*)d_in[2];
    const float* bq   = (const float*)d_in[3];
    const float* Wk   = (const float*)d_in[4];
    const float* bk   = (const float*)d_in[5];
    const float* Wv   = (const float*)d_in[6];
    const float* bv   = (const float*)d_in[7];
    const float* Wp   = (const float*)d_in[8];
    const float* bp   = (const float*)d_in[9];
    const float* g1   = (const float*)d_in[10];
    const float* b1   = (const float*)d_in[11];
    const float* g2   = (const float*)d_in[12];
    const float* b2   = (const float*)d_in[13];
    const float* W1   = (const float*)d_in[14];
    const float* bm1  = (const float*)d_in[15];
    const float* W2   = (const float*)d_in[16];
    const float* bm2  = (const float*)d_in[17];
    float* out = (float*)d_out;

    hf* h_hi  = symaddr<hf>(g_h_hi);   hf* h_lo  = symaddr<hf>(g_h_lo);
    hf* hk_hi = symaddr<hf>(g_hk_hi);  hf* hk_lo = symaddr<hf>(g_hk_lo);
    float* qb  = symaddr<float>(g_q);
    float* kvb = symaddr<float>(g_kv);
    hf* at_hi = symaddr<hf>(g_at_hi);  hf* at_lo = symaddr<hf>(g_at_lo);
    float* x2 = symaddr<float>(g_x2);
    hf* m_hi  = symaddr<hf>(g_m_hi);   hf* m_lo  = symaddr<hf>(g_m_lo);
    hf* t_hi  = symaddr<hf>(g_t_hi);   hf* t_lo  = symaddr<hf>(g_t_lo);
    hf* wqT  = symaddr<hf>(g_wq);
    hf* wkvT = symaddr<hf>(g_wkv);
    hf* wpT  = symaddr<hf>(g_wp);
    hf* w1T  = symaddr<hf>(g_w1);
    hf* w2T  = symaddr<hf>(g_w2);
    float* bkv = symaddr<float>(g_bkv);

    static bool attrSet = false;
    if (!attrSet) {
        cudaFuncSetAttribute(mma_gemm<1>, cudaFuncAttributeMaxDynamicSharedMemorySize, SMTOT);
        cudaFuncSetAttribute(mma_gemm<2>, cudaFuncAttributeMaxDynamicSharedMemorySize, SMTOT);
        cudaFuncSetAttribute(proj_qkv,    cudaFuncAttributeMaxDynamicSharedMemorySize, SMTOT);
        cudaFuncSetAttribute(attn_tile,   cudaFuncAttributeMaxDynamicSharedMemorySize, ATT_SMEM);
        attrSet = true;
    }

    // Prep: weight transpose (fp16) + LN1(x, x_kv) + bkv concat (one launch)
    prep_all<<<768 + 2304, 256>>>(Wq, Wk, Wv, Wp, W1, W2,
                                  wqT,
                                  wkvT,                // Wk -> rows 0..255
                                  wkvT + Cc * Cc,      // Wv -> rows 256..511
                                  wpT, w1T, w2T,
                                  x, x_kv, g1, b1,
                                  h_hi, h_lo, hk_hi, hk_lo,
                                  bk, bv, bkv);

    // Q + KV projections merged: grid (4+8) x 72 = 864 CTAs
    {
        dim3 g(12, ROWS / 128);
        proj_qkv<<<g, 256, SMTOT>>>(h_hi, h_lo, hk_hi, hk_lo,
                                    wqT, wkvT, bq, bkv, qb, kvb);
    }

    // Tiled sparse attention
    {
        dim3 ga(36, NH, Bb);
        attn_tile<<<ga, 256, ATT_SMEM>>>(qb, kvb, at_hi, at_lo);
    }

    // x2 = x + att @ Wp + bp
    {
        dim3 grid(Cc / 64, ROWS / 128);
        mma_gemm<1><<<grid, 256, SMTOT>>>(at_hi, at_lo, wpT, bp, x, x2, nullptr, nullptr, Cc, Cc);
    }

    // LN2
    ln_kernel<<<ROWS / 8, 256>>>(x2, g2, b2, m_hi, m_lo, ROWS);

    // MLP
    {
        dim3 grid1(HID / 64, ROWS / 128);
        mma_gemm<2><<<grid1, 256, SMTOT>>>(m_hi, m_lo, w1T, bm1, nullptr, nullptr, t_hi, t_lo, HID, Cc);
        dim3 grid2(Cc / 64, ROWS / 128);
        mma_gemm<1><<<grid2, 256, SMTOT>>>(t_hi, t_lo, w2T, bm2, x2, out, nullptr, nullptr, Cc, HID);
    }
}

// round 10
// speedup vs baseline: 2.2924x; 1.2902x over previous
#include <cuda_runtime.h>
#include <cuda_fp16.h>
#include <math.h>
#include <cstdint>

// ---------------------------------------------------------------------------
// Problem constants
// ---------------------------------------------------------------------------
static constexpr int Bb   = 4;
static constexpr int Nn   = 2304;      // 48*48
static constexpr int Cc   = 256;
static constexpr int NH   = 8;
static constexpr int HD   = 32;
static constexpr int HS   = 48;
static constexpr int HID  = 4 * Cc;    // 1024
static constexpr int ROWS = Bb * Nn;   // 9216
static constexpr float SCALE = 0.17677669529663687f; // 32^-0.5

// Neighbor offsets with dy*dy+dx*dx <= 9  (29 of them)
__constant__ int c_dy[29] = {-3,-2,-2,-2,-2,-2,-1,-1,-1,-1,-1, 0,0,0,0,0,0,0, 1,1,1,1,1, 2,2,2,2,2, 3};
__constant__ int c_dx[29] = { 0,-2,-1, 0, 1, 2,-2,-1, 0, 1, 2,-3,-2,-1,0,1,2,3,-2,-1,0,1,2,-2,-1,0,1,2, 0};

// ---------------------------------------------------------------------------
// Scratch (no cudaMalloc allowed) — single fp16 activations now
// ---------------------------------------------------------------------------
using hf = __half;
__device__ __align__(16) hf g_h   [ROWS * Cc];
__device__ __align__(16) hf g_hk  [ROWS * Cc];
__device__ __align__(16) float g_q  [ROWS * Cc];
__device__ __align__(16) float g_kv [ROWS * 2 * Cc];     // fused K|V, stride 512
__device__ __align__(16) hf g_at  [ROWS * Cc];
__device__ __align__(16) float g_x2 [ROWS * Cc];
__device__ __align__(16) hf g_m   [ROWS * Cc];
__device__ __align__(16) hf g_t   [ROWS * HID];
// transposed weights (single fp16): [N, K] layout
__device__ __align__(16) hf g_wq  [Cc * Cc];
__device__ __align__(16) hf g_wkv [2 * Cc * Cc];         // rows 0..255 = Wk^T, 256..511 = Wv^T
__device__ __align__(16) hf g_wp  [Cc * Cc];
__device__ __align__(16) hf g_w1  [HID * Cc];
__device__ __align__(16) hf g_w2  [Cc * HID];
__device__ __align__(16) float g_bkv[2 * Cc];            // bk | bv

// ---------------------------------------------------------------------------
// PTX helpers (base-ISA only: mma.sync / ldmatrix / cp.async)
// ---------------------------------------------------------------------------
__device__ __forceinline__ uint32_t smem_u32(const void* p) {
    uint32_t a;
    asm("{ .reg .u64 t; cvta.to.shared.u64 t, %1; cvt.u32.u64 %0, t; }" : "=r"(a) : "l"(p));
    return a;
}
__device__ __forceinline__ void ldsm_x4(uint32_t* r, uint32_t addr) {
    asm volatile("ldmatrix.sync.aligned.m8n8.x4.shared.b16 {%0,%1,%2,%3}, [%4];"
        : "=r"(r[0]), "=r"(r[1]), "=r"(r[2]), "=r"(r[3]) : "r"(addr));
}
__device__ __forceinline__ void mma16816(float* d, const uint32_t* a, uint32_t b0, uint32_t b1) {
    asm volatile("mma.sync.aligned.m16n8k16.row.col.f32.f16.f16.f32 "
        "{%0,%1,%2,%3}, {%4,%5,%6,%7}, {%8,%9}, {%0,%1,%2,%3};"
        : "+f"(d[0]), "+f"(d[1]), "+f"(d[2]), "+f"(d[3])
        : "r"(a[0]), "r"(a[1]), "r"(a[2]), "r"(a[3]), "r"(b0), "r"(b1));
}
#define CP16(dst, src) \
    asm volatile("cp.async.cg.shared.global [%0], [%1], 16;" :: "r"(dst), "l"(src))
#define CP_COMMIT()  asm volatile("cp.async.commit_group;" ::: "memory")
#define CP_WAITG(n)  asm volatile("cp.async.wait_group %0;" :: "n"(n) : "memory")

// ---------------------------------------------------------------------------
// Prep kernel: weight transpose (fp16) + LN1(x, x_kv) + bkv concat.
// Blocks [0,768): weight tiles; [768, 768+2304): LN rows (8 warps/block).
// ---------------------------------------------------------------------------
__global__ void __launch_bounds__(256) prep_all(
    const float* __restrict__ Wq, const float* __restrict__ Wk,
    const float* __restrict__ Wv, const float* __restrict__ Wp,
    const float* __restrict__ W1, const float* __restrict__ W2,
    hf* qT, hf* kT, hf* vT, hf* pT, hf* h1T, hf* h2T,
    const float* __restrict__ x, const float* __restrict__ x_kv,
    const float* __restrict__ g1, const float* __restrict__ b1,
    hf* __restrict__ oa, hf* __restrict__ ob,
    const float* __restrict__ bk, const float* __restrict__ bv,
    float* __restrict__ bkv)
{
    int bid = blockIdx.x;
    if (bid < 768) {
        __shared__ float t[32][33];
        const float* W; hf* Th; int K, N, tile;
        if (bid < 256) {
            int w = bid >> 6; tile = bid & 63; K = 256; N = 256;
            if      (w == 0) { W = Wq; Th = qT; }
            else if (w == 1) { W = Wk; Th = kT; }
            else if (w == 2) { W = Wv; Th = vT; }
            else             { W = Wp; Th = pT; }
        } else if (bid < 512) {
            W = W1; Th = h1T; K = 256; N = 1024; tile = bid - 256;
        } else {
            W = W2; Th = h2T; K = 1024; N = 256; tile = bid - 512;
        }
        int ntn = N >> 5;
        int tk = tile / ntn, tn = tile % ntn;
        int tx = threadIdx.x & 31, ty = threadIdx.x >> 5;
#pragma unroll
        for (int i = 0; i < 4; i++) {
            int r = ty + i * 8;
            t[r][tx] = W[(size_t)(tk * 32 + r) * N + tn * 32 + tx];
        }
        __syncthreads();
#pragma unroll
        for (int i = 0; i < 4; i++) {
            int r = ty + i * 8;
            Th[(size_t)(tn * 32 + r) * K + tk * 32 + tx] = __float2half_rn(t[tx][r]);
        }
        if (bid == 0) {
            bkv[threadIdx.x]      = bk[threadIdx.x];
            bkv[Cc + threadIdx.x] = bv[threadIdx.x];
        }
    } else {
        int gw   = (bid - 768) * 8 + ((int)threadIdx.x >> 5);
        int lane = threadIdx.x & 31;
        const float* xs = (gw < ROWS) ? x : x_kv;
        hf* oh = (gw < ROWS) ? oa : ob;
        int r = (gw < ROWS) ? gw : gw - ROWS;

        const float* xr = xs + (size_t)r * Cc;
        float f[8], s = 0.f, ss = 0.f;
#pragma unroll
        for (int i = 0; i < 8; i++) {
            f[i] = xr[lane + 32 * i];
            s  += f[i];
            ss += f[i] * f[i];
        }
#pragma unroll
        for (int off = 16; off; off >>= 1) {
            s  += __shfl_xor_sync(0xffffffffu, s,  off);
            ss += __shfl_xor_sync(0xffffffffu, ss, off);
        }
        float mu  = s * (1.f / 256.f);
        float var = ss * (1.f / 256.f) - mu * mu;
        float inv = rsqrtf(var + 1e-6f);
        size_t base = (size_t)r * Cc;
#pragma unroll
        for (int i = 0; i < 8; i++) {
            int c = lane + 32 * i;
            oh[base + c] = __float2half_rn((f[i] - mu) * inv * g1[c] + b1[c]);
        }
    }
}

// ---------------------------------------------------------------------------
// LayerNorm (LN2): one warp per row of 256; emits fp16
// ---------------------------------------------------------------------------
__global__ void ln_kernel(const float* __restrict__ x,
                          const float* __restrict__ g,
                          const float* __restrict__ b,
                          hf* __restrict__ oh, int rows)
{
    int gw   = (blockIdx.x * blockDim.x + threadIdx.x) >> 5;
    int lane = threadIdx.x & 31;
    if (gw >= rows) return;
    const float* xr = x + (size_t)gw * Cc;
    float f[8], s = 0.f, ss = 0.f;
#pragma unroll
    for (int i = 0; i < 8; i++) {
        f[i] = xr[lane + 32 * i];
        s  += f[i];
        ss += f[i] * f[i];
    }
#pragma unroll
    for (int off = 16; off; off >>= 1) {
        s  += __shfl_xor_sync(0xffffffffu, s,  off);
        ss += __shfl_xor_sync(0xffffffffu, ss, off);
    }
    float mu  = s * (1.f / 256.f);
    float var = ss * (1.f / 256.f) - mu * mu;
    float inv = rsqrtf(var + 1e-6f);
    size_t base = (size_t)gw * Cc;
#pragma unroll
    for (int i = 0; i < 8; i++) {
        int c = lane + 32 * i;
        oh[base + c] = __float2half_rn((f[i] - mu) * inv * g[c] + b[c]);
    }
}

// ---------------------------------------------------------------------------
// Tiled sparse attention (round-7 design; emits fp16).
// ---------------------------------------------------------------------------
static constexpr int TQ   = 8;
static constexpr int HALO = 3;
static constexpr int SP   = TQ + 2 * HALO;   // 14
static constexpr int NPOS = SP * SP;         // 196
static constexpr int ROWF = 65;              // padded row (k 32 | v 32 | pad)
static constexpr int ATT_SMEM = NPOS * ROWF * 4;  // 50960 B

__global__ void __launch_bounds__(256) attn_tile(
    const float* __restrict__ q, const float* __restrict__ kv,
    hf* __restrict__ oh)
{
    extern __shared__ float kvs[];
    const int tid = threadIdx.x, lane = tid & 31, wid = tid >> 5;
    const int tIdx = blockIdx.x;            // 0..35
    const int h = blockIdx.y, b = blockIdx.z;
    const int ty0 = (tIdx / 6) * TQ, tx0 = (tIdx % 6) * TQ;

    for (int i = tid; i < NPOS * 16; i += 256) {
        int sp = i >> 4, c4 = i & 15;
        int ly = sp / SP, lx = sp - ly * SP;
        int ny = ty0 - HALO + ly, nx = tx0 - HALO + lx;
        float4 val = make_float4(0.f, 0.f, 0.f, 0.f);
        if ((unsigned)ny < (unsigned)HS && (unsigned)nx < (unsigned)HS) {
            size_t base = ((size_t)(b * Nn + ny * HS + nx)) * (2 * Cc) + h * HD;
            val = *(const float4*)(kv + base + (c4 < 8 ? c4 * 4 : Cc + (c4 - 8) * 4));
        }
        float* dst = &kvs[sp * ROWF + ((c4 < 8) ? c4 * 4 : 32 + (c4 - 8) * 4)];
        dst[0] = val.x; dst[1] = val.y; dst[2] = val.z; dst[3] = val.w;
    }
    __syncthreads();

    const int qy = ty0 + wid;
    int dy = 0, dx = 0;
    if (lane < 29) { dy = c_dy[lane]; dx = c_dx[lane]; }
    const bool rowok = (lane < 29) && ((unsigned)(qy + dy) < (unsigned)HS);

    const size_t qbase = ((size_t)(b * Nn + qy * HS + tx0)) * Cc + h * HD + lane;
    float qv[8];
#pragma unroll
    for (int i = 0; i < 8; i++) qv[i] = q[qbase + i * Cc];

    int sp[8]; float s[8];
#pragma unroll
    for (int i = 0; i < 8; i++) {
        sp[i] = (wid + dy + HALO) * SP + (i + dx + HALO);
        s[i] = 0.f;
    }

#pragma unroll
    for (int d = 0; d < 32; d++) {
#pragma unroll
        for (int i = 0; i < 8; i++) {
            float qd = __shfl_sync(0xffffffffu, qv[i], d);
            s[i] += kvs[sp[i] * ROWF + d] * qd;
        }
    }
    float p[8], linv[8];
#pragma unroll
    for (int i = 0; i < 8; i++) {
        bool ok = rowok && ((unsigned)(tx0 + i + dx) < (unsigned)HS);
        float sv = ok ? s[i] * SCALE : -1e30f;
        float m = sv;
#pragma unroll
        for (int off = 16; off; off >>= 1)
            m = fmaxf(m, __shfl_xor_sync(0xffffffffu, m, off));
        float e = expf(sv - m);
        float sum = e;
#pragma unroll
        for (int off = 16; off; off >>= 1)
            sum += __shfl_xor_sync(0xffffffffu, sum, off);
        p[i] = e;
        linv[i] = 1.f / sum;
    }

    float acc[8] = {};
#pragma unroll
    for (int j = 0; j < 29; j++) {
        int spj = (wid + c_dy[j] + HALO) * SP + (c_dx[j] + HALO);
#pragma unroll
        for (int i = 0; i < 8; i++) {
            float pj = __shfl_sync(0xffffffffu, p[i], j);
            acc[i] += pj * kvs[(spj + i) * ROWF + 32 + lane];
        }
    }

#pragma unroll
    for (int i = 0; i < 8; i++)
        oh[qbase + i * Cc] = __float2half_rn(acc[i] * linv[i]);
}

// ---------------------------------------------------------------------------
// Pure fp16 single-pass GEMM via mma.sync (HMMA).
// C[M,N] = A[M,K] @ B^T[N,K]  (both operands fp16-rounded; fp32 accumulate)
// CTA tile 128x64, 8 warps (4x2), warp tile 32x32, BK=64,
// cp.async 2-stage, XOR-swizzled 128B rows.
// Stage: A 16K | B 8K = 24K; 2 stages = 48K -> 3 CTAs/SM.
// EPI: 0 -> Co = acc+bias ; 1 -> Co = acc+bias+res ; 2 -> gelu -> fp16
// ---------------------------------------------------------------------------
static constexpr int STGB  = 24576;
static constexpr int SMTOT = 2 * STGB;    // 48 KB

template <int EPI>
__device__ __forceinline__ void gemm_core(
    const hf* __restrict__ A, const hf* __restrict__ B,
    const float* __restrict__ bias, const float* __restrict__ res,
    float* __restrict__ Co, hf* __restrict__ oH,
    int N, int K, int tm, int tn)
{
    extern __shared__ __align__(1024) char smc[];
    const uint32_t sbase = smem_u32(smc);
    const int tid  = threadIdx.x;
    const int lane = tid & 31;
    const int wid  = tid >> 5;
    const int wm = wid >> 1, wn = wid & 1;   // 4 x 2 warp grid, warp tile 32x32

    const size_t strK = (size_t)K * 2;
    const char* pA = (const char*)A + ((size_t)tm * 128) * strK;
    const char* pB = (const char*)B + ((size_t)tn * 64)  * strK;

    const int nCh = K >> 6;

    auto load_stage = [&](int stg, int ch) {
        uint32_t d0 = sbase + stg * STGB;
        size_t koff = (size_t)ch * 128;
        // A: 1024 granules of 16B
#pragma unroll
        for (int i = 0; i < 4; i++) {
            int g = i * 256 + tid;
            int r = g >> 3, c = g & 7;
            const char* src = pA + (size_t)r * strK + koff + (c << 4);
            uint32_t dst = d0 + (r << 7) + ((c ^ (r & 7)) << 4);
            CP16(dst, src);
        }
        // B: 512 granules
#pragma unroll
        for (int i = 0; i < 2; i++) {
            int g = i * 256 + tid;
            int r = g >> 3, c = g & 7;
            const char* src = pB + (size_t)r * strK + koff + (c << 4);
            uint32_t dst = d0 + 16384 + (r << 7) + ((c ^ (r & 7)) << 4);
            CP16(dst, src);
        }
        CP_COMMIT();
    };

    const int rl = lane & 15;
    const int kc = lane >> 4;

    float acc[2][4][4] = {};

    load_stage(0, 0);

    for (int ch = 0; ch < nCh; ch++) {
        if (ch + 1 < nCh) { load_stage((ch + 1) & 1, ch + 1); CP_WAITG(1); }
        else              { CP_WAITG(0); }
        __syncthreads();

        uint32_t aB = sbase + (ch & 1) * STGB;
        uint32_t bB = aB + 16384;

#pragma unroll
        for (int k16 = 0; k16 < 4; k16++) {
            const int k2 = k16 * 2 + kc;
            uint32_t aa[2][4], bb[2][4];
#pragma unroll
            for (int f = 0; f < 2; f++) {
                int rA = wm * 32 + f * 16 + rl;
                ldsm_x4(aa[f], aB + (rA << 7) + ((k2 ^ (rA & 7)) << 4));
            }
            {
                int rB0 = wn * 32 + rl, rB1 = wn * 32 + 16 + rl;
                ldsm_x4(bb[0], bB + (rB0 << 7) + ((k2 ^ (rB0 & 7)) << 4));
                ldsm_x4(bb[1], bB + (rB1 << 7) + ((k2 ^ (rB1 & 7)) << 4));
            }
#pragma unroll
            for (int f = 0; f < 2; f++)
#pragma unroll
                for (int j = 0; j < 4; j++)
                    mma16816(acc[f][j], aa[f], bb[j >> 1][j & 1], bb[j >> 1][2 + (j & 1)]);
        }
        __syncthreads();
    }

    const int rbase = tm * 128 + wm * 32 + (lane >> 2);
    const int cbase = tn * 64 + wn * 32 + (lane & 3) * 2;
#pragma unroll
    for (int f = 0; f < 2; f++) {
#pragma unroll
        for (int j = 0; j < 4; j++) {
            int row0 = rbase + f * 16;
            int col  = cbase + j * 8;
            float b0 = bias[col], b1 = bias[col + 1];
            float v00 = acc[f][j][0] + b0;
            float v01 = acc[f][j][1] + b1;
            float v10 = acc[f][j][2] + b0;
            float v11 = acc[f][j][3] + b1;
            size_t i0 = (size_t)row0 * N + col;
            size_t i1 = (size_t)(row0 + 8) * N + col;
            if (EPI == 0) {
                *(float2*)(Co + i0) = make_float2(v00, v01);
                *(float2*)(Co + i1) = make_float2(v10, v11);
            } else if (EPI == 1) {
                float2 r0 = *(const float2*)(res + i0);
                float2 r1 = *(const float2*)(res + i1);
                *(float2*)(Co + i0) = make_float2(v00 + r0.x, v01 + r0.y);
                *(float2*)(Co + i1) = make_float2(v10 + r1.x, v11 + r1.y);
            } else {
                const float IS2 = 0.70710678118654752f;
                v00 = 0.5f * v00 * (1.f + erff(v00 * IS2));
                v01 = 0.5f * v01 * (1.f + erff(v01 * IS2));
                v10 = 0.5f * v10 * (1.f + erff(v10 * IS2));
                v11 = 0.5f * v11 * (1.f + erff(v11 * IS2));
                __half2 hh0; hh0.x = __float2half_rn(v00); hh0.y = __float2half_rn(v01);
                __half2 hh1; hh1.x = __float2half_rn(v10); hh1.y = __float2half_rn(v11);
                *(__half2*)(oH + i0) = hh0;
                *(__half2*)(oH + i1) = hh1;
            }
        }
    }
}

template <int EPI>
__global__ void __launch_bounds__(256, 3) mma_gemm(
    const hf* __restrict__ A, const hf* __restrict__ B,
    const float* __restrict__ bias, const float* __restrict__ res,
    float* __restrict__ Co, hf* __restrict__ oH,
    int N, int K)
{
    gemm_core<EPI>(A, B, bias, res, Co, oH, N, K, blockIdx.y, blockIdx.x);
}

// Merged Q + KV projection: blockIdx.x < 4 -> Q (N=256); else KV (N=512).
__global__ void __launch_bounds__(256, 3) proj_qkv(
    const hf* __restrict__ hh, const hf* __restrict__ kh,
    const hf* __restrict__ wq, const hf* __restrict__ wkv,
    const float* __restrict__ bq, const float* __restrict__ bkv,
    float* __restrict__ qo, float* __restrict__ kvo)
{
    if (blockIdx.x < 4) {
        gemm_core<0>(hh, wq, bq, nullptr, qo, nullptr,
                     Cc, Cc, blockIdx.y, blockIdx.x);
    } else {
        gemm_core<0>(kh, wkv, bkv, nullptr, kvo, nullptr,
                     2 * Cc, Cc, blockIdx.y, blockIdx.x - 4);
    }
}

// ---------------------------------------------------------------------------
// Launch
// ---------------------------------------------------------------------------
template <typename T>
static T* symaddr(const void* sym)
{
    void* p = nullptr;
    cudaGetSymbolAddress(&p, sym);
    return (T*)p;
}

extern "C" void kernel_launch(void* const* d_in, const int* in_sizes, int n_in,
                              void* d_out, int out_size)
{
    const float* x    = (const float*)d_in[0];
    const float* x_kv = (const float*)d_in[1];
    const float* Wq   = (const float*)d_in[2];
    const float* bq   = (const float*)d_in[3];
    const float* Wk   = (const float*)d_in[4];
    const float* bk   = (const float*)d_in[5];
    const float* Wv   = (const float*)d_in[6];
    const float* bv   = (const float*)d_in[7];
    const float* Wp   = (const float*)d_in[8];
    const float* bp   = (const float*)d_in[9];
    const float* g1   = (const float*)d_in[10];
    const float* b1   = (const float*)d_in[11];
    const float* g2   = (const float*)d_in[12];
    const float* b2   = (const float*)d_in[13];
    const float* W1   = (const float*)d_in[14];
    const float* bm1  = (const float*)d_in[15];
    const float* W2   = (const float*)d_in[16];
    const float* bm2  = (const float*)d_in[17];
    float* out = (float*)d_out;

    hf* hb  = symaddr<hf>(g_h);
    hf* hkb = symaddr<hf>(g_hk);
    float* qb  = symaddr<float>(g_q);
    float* kvb = symaddr<float>(g_kv);
    hf* atb = symaddr<hf>(g_at);
    float* x2 = symaddr<float>(g_x2);
    hf* mb  = symaddr<hf>(g_m);
    hf* tb  = symaddr<hf>(g_t);
    hf* wqT  = symaddr<hf>(g_wq);
    hf* wkvT = symaddr<hf>(g_wkv);
    hf* wpT  = symaddr<hf>(g_wp);
    hf* w1T  = symaddr<hf>(g_w1);
    hf* w2T  = symaddr<hf>(g_w2);
    float* bkv = symaddr<float>(g_bkv);

    static bool attrSet = false;
    if (!attrSet) {
        cudaFuncSetAttribute(mma_gemm<1>, cudaFuncAttributeMaxDynamicSharedMemorySize, SMTOT);
        cudaFuncSetAttribute(mma_gemm<2>, cudaFuncAttributeMaxDynamicSharedMemorySize, SMTOT);
        cudaFuncSetAttribute(proj_qkv,    cudaFuncAttributeMaxDynamicSharedMemorySize, SMTOT);
        cudaFuncSetAttribute(attn_tile,   cudaFuncAttributeMaxDynamicSharedMemorySize, ATT_SMEM);
        attrSet = true;
    }

    // Prep: weight transpose (fp16) + LN1(x, x_kv) + bkv concat (one launch)
    prep_all<<<768 + 2304, 256>>>(Wq, Wk, Wv, Wp, W1, W2,
                                  wqT,
                                  wkvT,                // Wk -> rows 0..255
                                  wkvT + Cc * Cc,      // Wv -> rows 256..511
                                  wpT, w1T, w2T,
                                  x, x_kv, g1, b1,
                                  hb, hkb,
                                  bk, bv, bkv);

    // Q + KV projections merged: grid (4+8) x 72 = 864 CTAs
    {
        dim3 g(12, ROWS / 128);
        proj_qkv<<<g, 256, SMTOT>>>(hb, hkb, wqT, wkvT, bq, bkv, qb, kvb);
    }

    // Tiled sparse attention
    {
        dim3 ga(36, NH, Bb);
        attn_tile<<<ga, 256, ATT_SMEM>>>(qb, kvb, atb);
    }

    // x2 = x + att @ Wp + bp
    {
        dim3 grid(Cc / 64, ROWS / 128);
        mma_gemm<1><<<grid, 256, SMTOT>>>(atb, wpT, bp, x, x2, nullptr, Cc, Cc);
    }

    // LN2
    ln_kernel<<<ROWS / 8, 256>>>(x2, g2, b2, mb, ROWS);

    // MLP
    {
        dim3 grid1(HID / 64, ROWS / 128);
        mma_gemm<2><<<grid1, 256, SMTOT>>>(mb, w1T, bm1, nullptr, nullptr, tb, HID, Cc);
        dim3 grid2(Cc / 64, ROWS / 128);
        mma_gemm<1><<<grid2, 256, SMTOT>>>(tb, w2T, bm2, x2, out, nullptr, Cc, HID);
    }
}

// round 11
// speedup vs baseline: 2.3176x; 1.0110x over previous
#include <cuda_runtime.h>
#include <cuda_fp16.h>
#include <math.h>
#include <cstdint>

// ---------------------------------------------------------------------------
// Problem constants
// ---------------------------------------------------------------------------
static constexpr int Bb   = 4;
static constexpr int Nn   = 2304;      // 48*48
static constexpr int Cc   = 256;
static constexpr int NH   = 8;
static constexpr int HD   = 32;
static constexpr int HS   = 48;
static constexpr int HID  = 4 * Cc;    // 1024
static constexpr int ROWS = Bb * Nn;   // 9216
static constexpr float SCALE = 0.17677669529663687f; // 32^-0.5

// Neighbor offsets with dy*dy+dx*dx <= 9  (29 of them)
__constant__ int c_dy[29] = {-3,-2,-2,-2,-2,-2,-1,-1,-1,-1,-1, 0,0,0,0,0,0,0, 1,1,1,1,1, 2,2,2,2,2, 3};
__constant__ int c_dx[29] = { 0,-2,-1, 0, 1, 2,-2,-1, 0, 1, 2,-3,-2,-1,0,1,2,3,-2,-1,0,1,2,-2,-1,0,1,2, 0};

// ---------------------------------------------------------------------------
// Scratch (no cudaMalloc allowed) — fp16 activations everywhere except the
// residual stream (x2 stays fp32 for exact residual adds)
// ---------------------------------------------------------------------------
using hf = __half;
__device__ __align__(16) hf g_h   [ROWS * Cc];
__device__ __align__(16) hf g_hk  [ROWS * Cc];
__device__ __align__(16) hf g_q   [ROWS * Cc];
__device__ __align__(16) hf g_kv  [ROWS * 2 * Cc];       // fused K|V, stride 512
__device__ __align__(16) hf g_at  [ROWS * Cc];
__device__ __align__(16) float g_x2 [ROWS * Cc];
__device__ __align__(16) hf g_m   [ROWS * Cc];
__device__ __align__(16) hf g_t   [ROWS * HID];
// transposed weights (single fp16): [N, K] layout
__device__ __align__(16) hf g_wq  [Cc * Cc];
__device__ __align__(16) hf g_wkv [2 * Cc * Cc];         // rows 0..255 = Wk^T, 256..511 = Wv^T
__device__ __align__(16) hf g_wp  [Cc * Cc];
__device__ __align__(16) hf g_w1  [HID * Cc];
__device__ __align__(16) hf g_w2  [Cc * HID];
__device__ __align__(16) float g_bkv[2 * Cc];            // bk | bv

// ---------------------------------------------------------------------------
// PTX helpers (base-ISA only: mma.sync / ldmatrix / cp.async)
// ---------------------------------------------------------------------------
__device__ __forceinline__ uint32_t smem_u32(const void* p) {
    uint32_t a;
    asm("{ .reg .u64 t; cvta.to.shared.u64 t, %1; cvt.u32.u64 %0, t; }" : "=r"(a) : "l"(p));
    return a;
}
__device__ __forceinline__ void ldsm_x4(uint32_t* r, uint32_t addr) {
    asm volatile("ldmatrix.sync.aligned.m8n8.x4.shared.b16 {%0,%1,%2,%3}, [%4];"
        : "=r"(r[0]), "=r"(r[1]), "=r"(r[2]), "=r"(r[3]) : "r"(addr));
}
__device__ __forceinline__ void mma16816(float* d, const uint32_t* a, uint32_t b0, uint32_t b1) {
    asm volatile("mma.sync.aligned.m16n8k16.row.col.f32.f16.f16.f32 "
        "{%0,%1,%2,%3}, {%4,%5,%6,%7}, {%8,%9}, {%0,%1,%2,%3};"
        : "+f"(d[0]), "+f"(d[1]), "+f"(d[2]), "+f"(d[3])
        : "r"(a[0]), "r"(a[1]), "r"(a[2]), "r"(a[3]), "r"(b0), "r"(b1));
}
#define CP16(dst, src) \
    asm volatile("cp.async.cg.shared.global [%0], [%1], 16;" :: "r"(dst), "l"(src))
#define CP_COMMIT()  asm volatile("cp.async.commit_group;" ::: "memory")
#define CP_WAITG(n)  asm volatile("cp.async.wait_group %0;" :: "n"(n) : "memory")

// ---------------------------------------------------------------------------
// Prep kernel: weight transpose (fp16) + LN1(x, x_kv) + bkv concat.
// Blocks [0,768): weight tiles; [768, 768+2304): LN rows (8 warps/block).
// ---------------------------------------------------------------------------
__global__ void __launch_bounds__(256) prep_all(
    const float* __restrict__ Wq, const float* __restrict__ Wk,
    const float* __restrict__ Wv, const float* __restrict__ Wp,
    const float* __restrict__ W1, const float* __restrict__ W2,
    hf* qT, hf* kT, hf* vT, hf* pT, hf* h1T, hf* h2T,
    const float* __restrict__ x, const float* __restrict__ x_kv,
    const float* __restrict__ g1, const float* __restrict__ b1,
    hf* __restrict__ oa, hf* __restrict__ ob,
    const float* __restrict__ bk, const float* __restrict__ bv,
    float* __restrict__ bkv)
{
    int bid = blockIdx.x;
    if (bid < 768) {
        __shared__ float t[32][33];
        const float* W; hf* Th; int K, N, tile;
        if (bid < 256) {
            int w = bid >> 6; tile = bid & 63; K = 256; N = 256;
            if      (w == 0) { W = Wq; Th = qT; }
            else if (w == 1) { W = Wk; Th = kT; }
            else if (w == 2) { W = Wv; Th = vT; }
            else             { W = Wp; Th = pT; }
        } else if (bid < 512) {
            W = W1; Th = h1T; K = 256; N = 1024; tile = bid - 256;
        } else {
            W = W2; Th = h2T; K = 1024; N = 256; tile = bid - 512;
        }
        int ntn = N >> 5;
        int tk = tile / ntn, tn = tile % ntn;
        int tx = threadIdx.x & 31, ty = threadIdx.x >> 5;
#pragma unroll
        for (int i = 0; i < 4; i++) {
            int r = ty + i * 8;
            t[r][tx] = W[(size_t)(tk * 32 + r) * N + tn * 32 + tx];
        }
        __syncthreads();
#pragma unroll
        for (int i = 0; i < 4; i++) {
            int r = ty + i * 8;
            Th[(size_t)(tn * 32 + r) * K + tk * 32 + tx] = __float2half_rn(t[tx][r]);
        }
        if (bid == 0) {
            bkv[threadIdx.x]      = bk[threadIdx.x];
            bkv[Cc + threadIdx.x] = bv[threadIdx.x];
        }
    } else {
        int gw   = (bid - 768) * 8 + ((int)threadIdx.x >> 5);
        int lane = threadIdx.x & 31;
        const float* xs = (gw < ROWS) ? x : x_kv;
        hf* oh = (gw < ROWS) ? oa : ob;
        int r = (gw < ROWS) ? gw : gw - ROWS;

        const float* xr = xs + (size_t)r * Cc;
        float2 f[4];
        float s = 0.f, ss = 0.f;
#pragma unroll
        for (int i = 0; i < 4; i++) {
            f[i] = *(const float2*)(xr + lane * 2 + i * 64);
            s  += f[i].x + f[i].y;
            ss += f[i].x * f[i].x + f[i].y * f[i].y;
        }
#pragma unroll
        for (int off = 16; off; off >>= 1) {
            s  += __shfl_xor_sync(0xffffffffu, s,  off);
            ss += __shfl_xor_sync(0xffffffffu, ss, off);
        }
        float mu  = s * (1.f / 256.f);
        float var = ss * (1.f / 256.f) - mu * mu;
        float inv = rsqrtf(var + 1e-6f);
        size_t base = (size_t)r * Cc;
#pragma unroll
        for (int i = 0; i < 4; i++) {
            int c = lane * 2 + i * 64;
            __half2 o;
            o.x = __float2half_rn((f[i].x - mu) * inv * g1[c]     + b1[c]);
            o.y = __float2half_rn((f[i].y - mu) * inv * g1[c + 1] + b1[c + 1]);
            *(__half2*)(oh + base + c) = o;
        }
    }
}

// ---------------------------------------------------------------------------
// LayerNorm (LN2): one warp per row of 256; emits fp16 (half2 stores)
// ---------------------------------------------------------------------------
__global__ void ln_kernel(const float* __restrict__ x,
                          const float* __restrict__ g,
                          const float* __restrict__ b,
                          hf* __restrict__ oh, int rows)
{
    int gw   = (blockIdx.x * blockDim.x + threadIdx.x) >> 5;
    int lane = threadIdx.x & 31;
    if (gw >= rows) return;
    const float* xr = x + (size_t)gw * Cc;
    float2 f[4];
    float s = 0.f, ss = 0.f;
#pragma unroll
    for (int i = 0; i < 4; i++) {
        f[i] = *(const float2*)(xr + lane * 2 + i * 64);
        s  += f[i].x + f[i].y;
        ss += f[i].x * f[i].x + f[i].y * f[i].y;
    }
#pragma unroll
    for (int off = 16; off; off >>= 1) {
        s  += __shfl_xor_sync(0xffffffffu, s,  off);
        ss += __shfl_xor_sync(0xffffffffu, ss, off);
    }
    float mu  = s * (1.f / 256.f);
    float var = ss * (1.f / 256.f) - mu * mu;
    float inv = rsqrtf(var + 1e-6f);
    size_t base = (size_t)gw * Cc;
#pragma unroll
    for (int i = 0; i < 4; i++) {
        int c = lane * 2 + i * 64;
        __half2 o;
        o.x = __float2half_rn((f[i].x - mu) * inv * g[c]     + b[c]);
        o.y = __float2half_rn((f[i].y - mu) * inv * g[c + 1] + b[c + 1]);
        *(__half2*)(oh + base + c) = o;
    }
}

// ---------------------------------------------------------------------------
// Tiled sparse attention: q/kv now fp16 in gmem; smem stays padded fp32.
// ---------------------------------------------------------------------------
static constexpr int TQ   = 8;
static constexpr int HALO = 3;
static constexpr int SP   = TQ + 2 * HALO;   // 14
static constexpr int NPOS = SP * SP;         // 196
static constexpr int ROWF = 65;              // padded row (k 32 | v 32 | pad)
static constexpr int ATT_SMEM = NPOS * ROWF * 4;  // 50960 B

__global__ void __launch_bounds__(256) attn_tile(
    const hf* __restrict__ q, const hf* __restrict__ kv,
    hf* __restrict__ oh)
{
    extern __shared__ float kvs[];
    const int tid = threadIdx.x, lane = tid & 31, wid = tid >> 5;
    const int tIdx = blockIdx.x;            // 0..35
    const int h = blockIdx.y, b = blockIdx.z;
    const int ty0 = (tIdx / 6) * TQ, tx0 = (tIdx % 6) * TQ;

    // halo load: per position 2 x 64B fp16 (k | v), 8 granules of 16B (8 halves)
    for (int i = tid; i < NPOS * 8; i += 256) {
        int sp = i >> 3, c4 = i & 7;
        int ly = sp / SP, lx = sp - ly * SP;
        int ny = ty0 - HALO + ly, nx = tx0 - HALO + lx;
        uint4 raw = make_uint4(0u, 0u, 0u, 0u);
        if ((unsigned)ny < (unsigned)HS && (unsigned)nx < (unsigned)HS) {
            size_t base = ((size_t)(b * Nn + ny * HS + nx)) * (2 * Cc) + h * HD;
            raw = *(const uint4*)(kv + base + (c4 < 4 ? c4 * 8 : Cc + (c4 - 4) * 8));
        }
        const __half2* hp = (const __half2*)&raw;
        float* dst = &kvs[sp * ROWF + ((c4 < 4) ? c4 * 8 : 32 + (c4 - 4) * 8)];
#pragma unroll
        for (int j = 0; j < 4; j++) {
            float2 f2 = __half22float2(hp[j]);
            dst[2 * j]     = f2.x;
            dst[2 * j + 1] = f2.y;
        }
    }
    __syncthreads();

    const int qy = ty0 + wid;
    int dy = 0, dx = 0;
    if (lane < 29) { dy = c_dy[lane]; dx = c_dx[lane]; }
    const bool rowok = (lane < 29) && ((unsigned)(qy + dy) < (unsigned)HS);

    const size_t qbase = ((size_t)(b * Nn + qy * HS + tx0)) * Cc + h * HD + lane;
    float qv[8];
#pragma unroll
    for (int i = 0; i < 8; i++) qv[i] = __half2float(q[qbase + i * Cc]);

    int sp[8]; float s[8];
#pragma unroll
    for (int i = 0; i < 8; i++) {
        sp[i] = (wid + dy + HALO) * SP + (i + dx + HALO);
        s[i] = 0.f;
    }

#pragma unroll
    for (int d = 0; d < 32; d++) {
#pragma unroll
        for (int i = 0; i < 8; i++) {
            float qd = __shfl_sync(0xffffffffu, qv[i], d);
            s[i] += kvs[sp[i] * ROWF + d] * qd;
        }
    }
    float p[8], linv[8];
#pragma unroll
    for (int i = 0; i < 8; i++) {
        bool ok = rowok && ((unsigned)(tx0 + i + dx) < (unsigned)HS);
        float sv = ok ? s[i] * SCALE : -1e30f;
        float m = sv;
#pragma unroll
        for (int off = 16; off; off >>= 1)
            m = fmaxf(m, __shfl_xor_sync(0xffffffffu, m, off));
        float e = expf(sv - m);
        float sum = e;
#pragma unroll
        for (int off = 16; off; off >>= 1)
            sum += __shfl_xor_sync(0xffffffffu, sum, off);
        p[i] = e;
        linv[i] = 1.f / sum;
    }

    float acc[8] = {};
#pragma unroll
    for (int j = 0; j < 29; j++) {
        int spj = (wid + c_dy[j] + HALO) * SP + (c_dx[j] + HALO);
#pragma unroll
        for (int i = 0; i < 8; i++) {
            float pj = __shfl_sync(0xffffffffu, p[i], j);
            acc[i] += pj * kvs[(spj + i) * ROWF + 32 + lane];
        }
    }

#pragma unroll
    for (int i = 0; i < 8; i++)
        oh[qbase + i * Cc] = __float2half_rn(acc[i] * linv[i]);
}

// ---------------------------------------------------------------------------
// Pure fp16 single-pass GEMM via mma.sync (HMMA).
// CTA tile 128x64, 8 warps (4x2), warp tile 32x32, BK=64, cp.async 2-stage.
// Stage: A 16K | B 8K = 24K; 2 stages = 48K -> 3 CTAs/SM.
// EPI: 1 -> Co = acc+bias+res ; 2 -> gelu -> fp16 ; 3 -> fp16 (acc+bias)
// ---------------------------------------------------------------------------
static constexpr int STGB  = 24576;
static constexpr int SMTOT = 2 * STGB;    // 48 KB

template <int EPI>
__device__ __forceinline__ void gemm_core(
    const hf* __restrict__ A, const hf* __restrict__ B,
    const float* __restrict__ bias, const float* __restrict__ res,
    float* __restrict__ Co, hf* __restrict__ oH,
    int N, int K, int tm, int tn)
{
    extern __shared__ __align__(1024) char smc[];
    const uint32_t sbase = smem_u32(smc);
    const int tid  = threadIdx.x;
    const int lane = tid & 31;
    const int wid  = tid >> 5;
    const int wm = wid >> 1, wn = wid & 1;   // 4 x 2 warp grid, warp tile 32x32

    const size_t strK = (size_t)K * 2;
    const char* pA = (const char*)A + ((size_t)tm * 128) * strK;
    const char* pB = (const char*)B + ((size_t)tn * 64)  * strK;

    const int nCh = K >> 6;

    auto load_stage = [&](int stg, int ch) {
        uint32_t d0 = sbase + stg * STGB;
        size_t koff = (size_t)ch * 128;
#pragma unroll
        for (int i = 0; i < 4; i++) {
            int g = i * 256 + tid;
            int r = g >> 3, c = g & 7;
            const char* src = pA + (size_t)r * strK + koff + (c << 4);
            uint32_t dst = d0 + (r << 7) + ((c ^ (r & 7)) << 4);
            CP16(dst, src);
        }
#pragma unroll
        for (int i = 0; i < 2; i++) {
            int g = i * 256 + tid;
            int r = g >> 3, c = g & 7;
            const char* src = pB + (size_t)r * strK + koff + (c << 4);
            uint32_t dst = d0 + 16384 + (r << 7) + ((c ^ (r & 7)) << 4);
            CP16(dst, src);
        }
        CP_COMMIT();
    };

    const int rl = lane & 15;
    const int kc = lane >> 4;

    float acc[2][4][4] = {};

    load_stage(0, 0);

    for (int ch = 0; ch < nCh; ch++) {
        if (ch + 1 < nCh) { load_stage((ch + 1) & 1, ch + 1); CP_WAITG(1); }
        else              { CP_WAITG(0); }
        __syncthreads();

        uint32_t aB = sbase + (ch & 1) * STGB;
        uint32_t bB = aB + 16384;

#pragma unroll
        for (int k16 = 0; k16 < 4; k16++) {
            const int k2 = k16 * 2 + kc;
            uint32_t aa[2][4], bb[2][4];
#pragma unroll
            for (int f = 0; f < 2; f++) {
                int rA = wm * 32 + f * 16 + rl;
                ldsm_x4(aa[f], aB + (rA << 7) + ((k2 ^ (rA & 7)) << 4));
            }
            {
                int rB0 = wn * 32 + rl, rB1 = wn * 32 + 16 + rl;
                ldsm_x4(bb[0], bB + (rB0 << 7) + ((k2 ^ (rB0 & 7)) << 4));
                ldsm_x4(bb[1], bB + (rB1 << 7) + ((k2 ^ (rB1 & 7)) << 4));
            }
#pragma unroll
            for (int f = 0; f < 2; f++)
#pragma unroll
                for (int j = 0; j < 4; j++)
                    mma16816(acc[f][j], aa[f], bb[j >> 1][j & 1], bb[j >> 1][2 + (j & 1)]);
        }
        __syncthreads();
    }

    const int rbase = tm * 128 + wm * 32 + (lane >> 2);
    const int cbase = tn * 64 + wn * 32 + (lane & 3) * 2;
#pragma unroll
    for (int f = 0; f < 2; f++) {
#pragma unroll
        for (int j = 0; j < 4; j++) {
            int row0 = rbase + f * 16;
            int col  = cbase + j * 8;
            float b0 = bias[col], b1 = bias[col + 1];
            float v00 = acc[f][j][0] + b0;
            float v01 = acc[f][j][1] + b1;
            float v10 = acc[f][j][2] + b0;
            float v11 = acc[f][j][3] + b1;
            size_t i0 = (size_t)row0 * N + col;
            size_t i1 = (size_t)(row0 + 8) * N + col;
            if (EPI == 1) {
                float2 r0 = *(const float2*)(res + i0);
                float2 r1 = *(const float2*)(res + i1);
                *(float2*)(Co + i0) = make_float2(v00 + r0.x, v01 + r0.y);
                *(float2*)(Co + i1) = make_float2(v10 + r1.x, v11 + r1.y);
            } else if (EPI == 3) {
                __half2 hh0; hh0.x = __float2half_rn(v00); hh0.y = __float2half_rn(v01);
                __half2 hh1; hh1.x = __float2half_rn(v10); hh1.y = __float2half_rn(v11);
                *(__half2*)(oH + i0) = hh0;
                *(__half2*)(oH + i1) = hh1;
            } else {  // EPI == 2, gelu -> fp16
                const float IS2 = 0.70710678118654752f;
                v00 = 0.5f * v00 * (1.f + erff(v00 * IS2));
                v01 = 0.5f * v01 * (1.f + erff(v01 * IS2));
                v10 = 0.5f * v10 * (1.f + erff(v10 * IS2));
                v11 = 0.5f * v11 * (1.f + erff(v11 * IS2));
                __half2 hh0; hh0.x = __float2half_rn(v00); hh0.y = __float2half_rn(v01);
                __half2 hh1; hh1.x = __float2half_rn(v10); hh1.y = __float2half_rn(v11);
                *(__half2*)(oH + i0) = hh0;
                *(__half2*)(oH + i1) = hh1;
            }
        }
    }
}

template <int EPI>
__global__ void __launch_bounds__(256, 3) mma_gemm(
    const hf* __restrict__ A, const hf* __restrict__ B,
    const float* __restrict__ bias, const float* __restrict__ res,
    float* __restrict__ Co, hf* __restrict__ oH,
    int N, int K)
{
    gemm_core<EPI>(A, B, bias, res, Co, oH, N, K, blockIdx.y, blockIdx.x);
}

// Merged Q + KV projection: blockIdx.x < 4 -> Q (N=256); else KV (N=512).
// Both write fp16 outputs now.
__global__ void __launch_bounds__(256, 3) proj_qkv(
    const hf* __restrict__ hh, const hf* __restrict__ kh,
    const hf* __restrict__ wq, const hf* __restrict__ wkv,
    const float* __restrict__ bq, const float* __restrict__ bkv,
    hf* __restrict__ qo, hf* __restrict__ kvo)
{
    if (blockIdx.x < 4) {
        gemm_core<3>(hh, wq, bq, nullptr, nullptr, qo,
                     Cc, Cc, blockIdx.y, blockIdx.x);
    } else {
        gemm_core<3>(kh, wkv, bkv, nullptr, nullptr, kvo,
                     2 * Cc, Cc, blockIdx.y, blockIdx.x - 4);
    }
}

// ---------------------------------------------------------------------------
// Launch
// ---------------------------------------------------------------------------
template <typename T>
static T* symaddr(const void* sym)
{
    void* p = nullptr;
    cudaGetSymbolAddress(&p, sym);
    return (T*)p;
}

extern "C" void kernel_launch(void* const* d_in, const int* in_sizes, int n_in,
                              void* d_out, int out_size)
{
    const float* x    = (const float*)d_in[0];
    const float* x_kv = (const float*)d_in[1];
    const float* Wq   = (const float*)d_in[2];
    const float* bq   = (const float*)d_in[3];
    const float* Wk   = (const float*)d_in[4];
    const float* bk   = (const float*)d_in[5];
    const float* Wv   = (const float*)d_in[6];
    const float* bv   = (const float*)d_in[7];
    const float* Wp   = (const float*)d_in[8];
    const float* bp   = (const float*)d_in[9];
    const float* g1   = (const float*)d_in[10];
    const float* b1   = (const float*)d_in[11];
    const float* g2   = (const float*)d_in[12];
    const float* b2   = (const float*)d_in[13];
    const float* W1   = (const float*)d_in[14];
    const float* bm1  = (const float*)d_in[15];
    const float* W2   = (const float*)d_in[16];
    const float* bm2  = (const float*)d_in[17];
    float* out = (float*)d_out;

    hf* hb  = symaddr<hf>(g_h);
    hf* hkb = symaddr<hf>(g_hk);
    hf* qb  = symaddr<hf>(g_q);
    hf* kvb = symaddr<hf>(g_kv);
    hf* atb = symaddr<hf>(g_at);
    float* x2 = symaddr<float>(g_x2);
    hf* mb  = symaddr<hf>(g_m);
    hf* tb  = symaddr<hf>(g_t);
    hf* wqT  = symaddr<hf>(g_wq);
    hf* wkvT = symaddr<hf>(g_wkv);
    hf* wpT  = symaddr<hf>(g_wp);
    hf* w1T  = symaddr<hf>(g_w1);
    hf* w2T  = symaddr<hf>(g_w2);
    float* bkv = symaddr<float>(g_bkv);

    static bool attrSet = false;
    if (!attrSet) {
        cudaFuncSetAttribute(mma_gemm<1>, cudaFuncAttributeMaxDynamicSharedMemorySize, SMTOT);
        cudaFuncSetAttribute(mma_gemm<2>, cudaFuncAttributeMaxDynamicSharedMemorySize, SMTOT);
        cudaFuncSetAttribute(proj_qkv,    cudaFuncAttributeMaxDynamicSharedMemorySize, SMTOT);
        cudaFuncSetAttribute(attn_tile,   cudaFuncAttributeMaxDynamicSharedMemorySize, ATT_SMEM);
        attrSet = true;
    }

    // Prep: weight transpose (fp16) + LN1(x, x_kv) + bkv concat (one launch)
    prep_all<<<768 + 2304, 256>>>(Wq, Wk, Wv, Wp, W1, W2,
                                  wqT,
                                  wkvT,                // Wk -> rows 0..255
                                  wkvT + Cc * Cc,      // Wv -> rows 256..511
                                  wpT, w1T, w2T,
                                  x, x_kv, g1, b1,
                                  hb, hkb,
                                  bk, bv, bkv);

    // Q + KV projections merged: grid (4+8) x 72 = 864 CTAs (fp16 out)
    {
        dim3 g(12, ROWS / 128);
        proj_qkv<<<g, 256, SMTOT>>>(hb, hkb, wqT, wkvT, bq, bkv, qb, kvb);
    }

    // Tiled sparse attention (fp16 in/out)
    {
        dim3 ga(36, NH, Bb);
        attn_tile<<<ga, 256, ATT_SMEM>>>(qb, kvb, atb);
    }

    // x2 = x + att @ Wp + bp
    {
        dim3 grid(Cc / 64, ROWS / 128);
        mma_gemm<1><<<grid, 256, SMTOT>>>(atb, wpT, bp, x, x2, nullptr, Cc, Cc);
    }

    // LN2
    ln_kernel<<<ROWS / 8, 256>>>(x2, g2, b2, mb, ROWS);

    // MLP
    {
        dim3 grid1(HID / 64, ROWS / 128);
        mma_gemm<2><<<grid1, 256, SMTOT>>>(mb, w1T, bm1, nullptr, nullptr, tb, HID, Cc);
        dim3 grid2(Cc / 64, ROWS / 128);
        mma_gemm<1><<<grid2, 256, SMTOT>>>(tb, w2T, bm2, x2, out, nullptr, Cc, HID);
    }
}

// round 12
// speedup vs baseline: 2.3887x; 1.0307x over previous
#include <cuda_runtime.h>
#include <cuda_fp16.h>
#include <math.h>
#include <cstdint>

// ---------------------------------------------------------------------------
// Problem constants
// ---------------------------------------------------------------------------
static constexpr int Bb   = 4;
static constexpr int Nn   = 2304;      // 48*48
static constexpr int Cc   = 256;
static constexpr int NH   = 8;
static constexpr int HD   = 32;
static constexpr int HS   = 48;
static constexpr int HID  = 4 * Cc;    // 1024
static constexpr int ROWS = Bb * Nn;   // 9216
static constexpr float SCALE = 0.17677669529663687f; // 32^-0.5

// Neighbor offsets with dy*dy+dx*dx <= 9  (29 of them)
__constant__ int c_dy[29] = {-3,-2,-2,-2,-2,-2,-1,-1,-1,-1,-1, 0,0,0,0,0,0,0, 1,1,1,1,1, 2,2,2,2,2, 3};
__constant__ int c_dx[29] = { 0,-2,-1, 0, 1, 2,-2,-1, 0, 1, 2,-3,-2,-1,0,1,2,3,-2,-1,0,1,2,-2,-1,0,1,2, 0};

// ---------------------------------------------------------------------------
// Scratch (no cudaMalloc allowed)
// ---------------------------------------------------------------------------
using hf = __half;
__device__ __align__(16) hf g_h   [ROWS * Cc];
__device__ __align__(16) hf g_hk  [ROWS * Cc];
__device__ __align__(16) hf g_q   [ROWS * Cc];
__device__ __align__(16) hf g_kv  [ROWS * 2 * Cc];       // fused K|V, stride 512
__device__ __align__(16) hf g_at  [ROWS * Cc];
__device__ __align__(16) float g_x2 [ROWS * Cc];
__device__ __align__(16) hf g_m   [ROWS * Cc];
__device__ __align__(16) hf g_t   [ROWS * HID];
// transposed weights (single fp16): [N, K] layout
__device__ __align__(16) hf g_wq  [Cc * Cc];
__device__ __align__(16) hf g_wkv [2 * Cc * Cc];         // rows 0..255 = Wk^T, 256..511 = Wv^T
__device__ __align__(16) hf g_wp  [Cc * Cc];
__device__ __align__(16) hf g_w1  [HID * Cc];
__device__ __align__(16) hf g_w2  [Cc * HID];
__device__ __align__(16) float g_bkv[2 * Cc];            // bk | bv

// ---------------------------------------------------------------------------
// PTX helpers (base-ISA only: mma.sync / ldmatrix / cp.async)
// ---------------------------------------------------------------------------
__device__ __forceinline__ uint32_t smem_u32(const void* p) {
    uint32_t a;
    asm("{ .reg .u64 t; cvta.to.shared.u64 t, %1; cvt.u32.u64 %0, t; }" : "=r"(a) : "l"(p));
    return a;
}
__device__ __forceinline__ void ldsm_x4(uint32_t* r, uint32_t addr) {
    asm volatile("ldmatrix.sync.aligned.m8n8.x4.shared.b16 {%0,%1,%2,%3}, [%4];"
        : "=r"(r[0]), "=r"(r[1]), "=r"(r[2]), "=r"(r[3]) : "r"(addr));
}
__device__ __forceinline__ void mma16816(float* d, const uint32_t* a, uint32_t b0, uint32_t b1) {
    asm volatile("mma.sync.aligned.m16n8k16.row.col.f32.f16.f16.f32 "
        "{%0,%1,%2,%3}, {%4,%5,%6,%7}, {%8,%9}, {%0,%1,%2,%3};"
        : "+f"(d[0]), "+f"(d[1]), "+f"(d[2]), "+f"(d[3])
        : "r"(a[0]), "r"(a[1]), "r"(a[2]), "r"(a[3]), "r"(b0), "r"(b1));
}
#define CP16(dst, src) \
    asm volatile("cp.async.cg.shared.global [%0], [%1], 16;" :: "r"(dst), "l"(src))
#define CP_COMMIT()  asm volatile("cp.async.commit_group;" ::: "memory")
#define CP_WAITG(n)  asm volatile("cp.async.wait_group %0;" :: "n"(n) : "memory")

// ---------------------------------------------------------------------------
// Prep kernel: weight transpose (fp16) + LN1(x, x_kv) + bkv concat.
// Blocks [0,768): weight tiles; [768, 768+2304): LN rows (8 warps/block).
// ---------------------------------------------------------------------------
__global__ void __launch_bounds__(256) prep_all(
    const float* __restrict__ Wq, const float* __restrict__ Wk,
    const float* __restrict__ Wv, const float* __restrict__ Wp,
    const float* __restrict__ W1, const float* __restrict__ W2,
    hf* qT, hf* kT, hf* vT, hf* pT, hf* h1T, hf* h2T,
    const float* __restrict__ x, const float* __restrict__ x_kv,
    const float* __restrict__ g1, const float* __restrict__ b1,
    hf* __restrict__ oa, hf* __restrict__ ob,
    const float* __restrict__ bk, const float* __restrict__ bv,
    float* __restrict__ bkv)
{
    int bid = blockIdx.x;
    if (bid < 768) {
        __shared__ float t[32][33];
        const float* W; hf* Th; int K, N, tile;
        if (bid < 256) {
            int w = bid >> 6; tile = bid & 63; K = 256; N = 256;
            if      (w == 0) { W = Wq; Th = qT; }
            else if (w == 1) { W = Wk; Th = kT; }
            else if (w == 2) { W = Wv; Th = vT; }
            else             { W = Wp; Th = pT; }
        } else if (bid < 512) {
            W = W1; Th = h1T; K = 256; N = 1024; tile = bid - 256;
        } else {
            W = W2; Th = h2T; K = 1024; N = 256; tile = bid - 512;
        }
        int ntn = N >> 5;
        int tk = tile / ntn, tn = tile % ntn;
        int tx = threadIdx.x & 31, ty = threadIdx.x >> 5;
#pragma unroll
        for (int i = 0; i < 4; i++) {
            int r = ty + i * 8;
            t[r][tx] = W[(size_t)(tk * 32 + r) * N + tn * 32 + tx];
        }
        __syncthreads();
#pragma unroll
        for (int i = 0; i < 4; i++) {
            int r = ty + i * 8;
            Th[(size_t)(tn * 32 + r) * K + tk * 32 + tx] = __float2half_rn(t[tx][r]);
        }
        if (bid == 0) {
            bkv[threadIdx.x]      = bk[threadIdx.x];
            bkv[Cc + threadIdx.x] = bv[threadIdx.x];
        }
    } else {
        int gw   = (bid - 768) * 8 + ((int)threadIdx.x >> 5);
        int lane = threadIdx.x & 31;
        const float* xs = (gw < ROWS) ? x : x_kv;
        hf* oh = (gw < ROWS) ? oa : ob;
        int r = (gw < ROWS) ? gw : gw - ROWS;

        const float* xr = xs + (size_t)r * Cc;
        float2 f[4];
        float s = 0.f, ss = 0.f;
#pragma unroll
        for (int i = 0; i < 4; i++) {
            f[i] = *(const float2*)(xr + lane * 2 + i * 64);
            s  += f[i].x + f[i].y;
            ss += f[i].x * f[i].x + f[i].y * f[i].y;
        }
#pragma unroll
        for (int off = 16; off; off >>= 1) {
            s  += __shfl_xor_sync(0xffffffffu, s,  off);
            ss += __shfl_xor_sync(0xffffffffu, ss, off);
        }
        float mu  = s * (1.f / 256.f);
        float var = ss * (1.f / 256.f) - mu * mu;
        float inv = rsqrtf(var + 1e-6f);
        size_t base = (size_t)r * Cc;
#pragma unroll
        for (int i = 0; i < 4; i++) {
            int c = lane * 2 + i * 64;
            __half2 o;
            o.x = __float2half_rn((f[i].x - mu) * inv * g1[c]     + b1[c]);
            o.y = __float2half_rn((f[i].y - mu) * inv * g1[c + 1] + b1[c + 1]);
            *(__half2*)(oh + base + c) = o;
        }
    }
}

// ---------------------------------------------------------------------------
// LayerNorm (LN2): one warp per row of 256; emits fp16 (half2 stores)
// ---------------------------------------------------------------------------
__global__ void ln_kernel(const float* __restrict__ x,
                          const float* __restrict__ g,
                          const float* __restrict__ b,
                          hf* __restrict__ oh, int rows)
{
    int gw   = (blockIdx.x * blockDim.x + threadIdx.x) >> 5;
    int lane = threadIdx.x & 31;
    if (gw >= rows) return;
    const float* xr = x + (size_t)gw * Cc;
    float2 f[4];
    float s = 0.f, ss = 0.f;
#pragma unroll
    for (int i = 0; i < 4; i++) {
        f[i] = *(const float2*)(xr + lane * 2 + i * 64);
        s  += f[i].x + f[i].y;
        ss += f[i].x * f[i].x + f[i].y * f[i].y;
    }
#pragma unroll
    for (int off = 16; off; off >>= 1) {
        s  += __shfl_xor_sync(0xffffffffu, s,  off);
        ss += __shfl_xor_sync(0xffffffffu, ss, off);
    }
    float mu  = s * (1.f / 256.f);
    float var = ss * (1.f / 256.f) - mu * mu;
    float inv = rsqrtf(var + 1e-6f);
    size_t base = (size_t)gw * Cc;
#pragma unroll
    for (int i = 0; i < 4; i++) {
        int c = lane * 2 + i * 64;
        __half2 o;
        o.x = __float2half_rn((f[i].x - mu) * inv * g[c]     + b[c]);
        o.y = __float2half_rn((f[i].y - mu) * inv * g[c + 1] + b[c + 1]);
        *(__half2*)(oh + base + c) = o;
    }
}

// ---------------------------------------------------------------------------
// Tiled sparse attention: q/kv fp16 in gmem; smem padded fp32.
// ---------------------------------------------------------------------------
static constexpr int TQ   = 8;
static constexpr int HALO = 3;
static constexpr int SP   = TQ + 2 * HALO;   // 14
static constexpr int NPOS = SP * SP;         // 196
static constexpr int ROWF = 65;              // padded row (k 32 | v 32 | pad)
static constexpr int ATT_SMEM = NPOS * ROWF * 4;  // 50960 B

__global__ void __launch_bounds__(256) attn_tile(
    const hf* __restrict__ q, const hf* __restrict__ kv,
    hf* __restrict__ oh)
{
    extern __shared__ float kvs[];
    const int tid = threadIdx.x, lane = tid & 31, wid = tid >> 5;
    const int tIdx = blockIdx.x;            // 0..35
    const int h = blockIdx.y, b = blockIdx.z;
    const int ty0 = (tIdx / 6) * TQ, tx0 = (tIdx % 6) * TQ;

    for (int i = tid; i < NPOS * 8; i += 256) {
        int sp = i >> 3, c4 = i & 7;
        int ly = sp / SP, lx = sp - ly * SP;
        int ny = ty0 - HALO + ly, nx = tx0 - HALO + lx;
        uint4 raw = make_uint4(0u, 0u, 0u, 0u);
        if ((unsigned)ny < (unsigned)HS && (unsigned)nx < (unsigned)HS) {
            size_t base = ((size_t)(b * Nn + ny * HS + nx)) * (2 * Cc) + h * HD;
            raw = *(const uint4*)(kv + base + (c4 < 4 ? c4 * 8 : Cc + (c4 - 4) * 8));
        }
        const __half2* hp = (const __half2*)&raw;
        float* dst = &kvs[sp * ROWF + ((c4 < 4) ? c4 * 8 : 32 + (c4 - 4) * 8)];
#pragma unroll
        for (int j = 0; j < 4; j++) {
            float2 f2 = __half22float2(hp[j]);
            dst[2 * j]     = f2.x;
            dst[2 * j + 1] = f2.y;
        }
    }
    __syncthreads();

    const int qy = ty0 + wid;
    int dy = 0, dx = 0;
    if (lane < 29) { dy = c_dy[lane]; dx = c_dx[lane]; }
    const bool rowok = (lane < 29) && ((unsigned)(qy + dy) < (unsigned)HS);

    const size_t qbase = ((size_t)(b * Nn + qy * HS + tx0)) * Cc + h * HD + lane;
    float qv[8];
#pragma unroll
    for (int i = 0; i < 8; i++) qv[i] = __half2float(q[qbase + i * Cc]);

    int sp[8]; float s[8];
#pragma unroll
    for (int i = 0; i < 8; i++) {
        sp[i] = (wid + dy + HALO) * SP + (i + dx + HALO);
        s[i] = 0.f;
    }

#pragma unroll
    for (int d = 0; d < 32; d++) {
#pragma unroll
        for (int i = 0; i < 8; i++) {
            float qd = __shfl_sync(0xffffffffu, qv[i], d);
            s[i] += kvs[sp[i] * ROWF + d] * qd;
        }
    }
    float p[8], linv[8];
#pragma unroll
    for (int i = 0; i < 8; i++) {
        bool ok = rowok && ((unsigned)(tx0 + i + dx) < (unsigned)HS);
        float sv = ok ? s[i] * SCALE : -1e30f;
        float m = sv;
#pragma unroll
        for (int off = 16; off; off >>= 1)
            m = fmaxf(m, __shfl_xor_sync(0xffffffffu, m, off));
        float e = expf(sv - m);
        float sum = e;
#pragma unroll
        for (int off = 16; off; off >>= 1)
            sum += __shfl_xor_sync(0xffffffffu, sum, off);
        p[i] = e;
        linv[i] = 1.f / sum;
    }

    float acc[8] = {};
#pragma unroll
    for (int j = 0; j < 29; j++) {
        int spj = (wid + c_dy[j] + HALO) * SP + (c_dx[j] + HALO);
#pragma unroll
        for (int i = 0; i < 8; i++) {
            float pj = __shfl_sync(0xffffffffu, p[i], j);
            acc[i] += pj * kvs[(spj + i) * ROWF + 32 + lane];
        }
    }

#pragma unroll
    for (int i = 0; i < 8; i++)
        oh[qbase + i * Cc] = __float2half_rn(acc[i] * linv[i]);
}

// ---------------------------------------------------------------------------
// Pure fp16 single-pass GEMM via mma.sync (HMMA).
// CTA tile 64x64, 4 warps (2x2), warp tile 32x32, BK=64, cp.async 2-stage.
// Stage: A 8K | B 8K = 16K; 2 stages = 32K -> up to 6 CTAs/SM (24 warps).
// EPI: 1 -> Co = acc+bias+res ; 2 -> gelu -> fp16 ; 3 -> fp16 (acc+bias)
// ---------------------------------------------------------------------------
static constexpr int STGB  = 16384;
static constexpr int SMTOT = 2 * STGB;    // 32 KB

template <int EPI>
__device__ __forceinline__ void gemm_core(
    const hf* __restrict__ A, const hf* __restrict__ B,
    const float* __restrict__ bias, const float* __restrict__ res,
    float* __restrict__ Co, hf* __restrict__ oH,
    int N, int K, int tm, int tn)
{
    extern __shared__ __align__(1024) char smc[];
    const uint32_t sbase = smem_u32(smc);
    const int tid  = threadIdx.x;
    const int lane = tid & 31;
    const int wid  = tid >> 5;
    const int wm = wid >> 1, wn = wid & 1;   // 2 x 2 warp grid, warp tile 32x32

    const size_t strK = (size_t)K * 2;
    const char* pA = (const char*)A + ((size_t)tm * 64) * strK;
    const char* pB = (const char*)B + ((size_t)tn * 64) * strK;

    const int nCh = K >> 6;

    auto load_stage = [&](int stg, int ch) {
        uint32_t d0 = sbase + stg * STGB;
        size_t koff = (size_t)ch * 128;
        // A: 512 granules of 16B
#pragma unroll
        for (int i = 0; i < 4; i++) {
            int g = i * 128 + tid;
            int r = g >> 3, c = g & 7;
            const char* src = pA + (size_t)r * strK + koff + (c << 4);
            uint32_t dst = d0 + (r << 7) + ((c ^ (r & 7)) << 4);
            CP16(dst, src);
        }
        // B: 512 granules
#pragma unroll
        for (int i = 0; i < 4; i++) {
            int g = i * 128 + tid;
            int r = g >> 3, c = g & 7;
            const char* src = pB + (size_t)r * strK + koff + (c << 4);
            uint32_t dst = d0 + 8192 + (r << 7) + ((c ^ (r & 7)) << 4);
            CP16(dst, src);
        }
        CP_COMMIT();
    };

    const int rl = lane & 15;
    const int kc = lane >> 4;

    float acc[2][4][4] = {};

    load_stage(0, 0);

    for (int ch = 0; ch < nCh; ch++) {
        if (ch + 1 < nCh) { load_stage((ch + 1) & 1, ch + 1); CP_WAITG(1); }
        else              { CP_WAITG(0); }
        __syncthreads();

        uint32_t aB = sbase + (ch & 1) * STGB;
        uint32_t bB = aB + 8192;

#pragma unroll
        for (int k16 = 0; k16 < 4; k16++) {
            const int k2 = k16 * 2 + kc;
            uint32_t aa[2][4], bb[2][4];
#pragma unroll
            for (int f = 0; f < 2; f++) {
                int rA = wm * 32 + f * 16 + rl;
                ldsm_x4(aa[f], aB + (rA << 7) + ((k2 ^ (rA & 7)) << 4));
            }
            {
                int rB0 = wn * 32 + rl, rB1 = wn * 32 + 16 + rl;
                ldsm_x4(bb[0], bB + (rB0 << 7) + ((k2 ^ (rB0 & 7)) << 4));
                ldsm_x4(bb[1], bB + (rB1 << 7) + ((k2 ^ (rB1 & 7)) << 4));
            }
#pragma unroll
            for (int f = 0; f < 2; f++)
#pragma unroll
                for (int j = 0; j < 4; j++)
                    mma16816(acc[f][j], aa[f], bb[j >> 1][j & 1], bb[j >> 1][2 + (j & 1)]);
        }
        __syncthreads();
    }

    const int rbase = tm * 64 + wm * 32 + (lane >> 2);
    const int cbase = tn * 64 + wn * 32 + (lane & 3) * 2;
#pragma unroll
    for (int f = 0; f < 2; f++) {
#pragma unroll
        for (int j = 0; j < 4; j++) {
            int row0 = rbase + f * 16;
            int col  = cbase + j * 8;
            float b0 = bias[col], b1 = bias[col + 1];
            float v00 = acc[f][j][0] + b0;
            float v01 = acc[f][j][1] + b1;
            float v10 = acc[f][j][2] + b0;
            float v11 = acc[f][j][3] + b1;
            size_t i0 = (size_t)row0 * N + col;
            size_t i1 = (size_t)(row0 + 8) * N + col;
            if (EPI == 1) {
                float2 r0 = *(const float2*)(res + i0);
                float2 r1 = *(const float2*)(res + i1);
                *(float2*)(Co + i0) = make_float2(v00 + r0.x, v01 + r0.y);
                *(float2*)(Co + i1) = make_float2(v10 + r1.x, v11 + r1.y);
            } else if (EPI == 3) {
                __half2 hh0; hh0.x = __float2half_rn(v00); hh0.y = __float2half_rn(v01);
                __half2 hh1; hh1.x = __float2half_rn(v10); hh1.y = __float2half_rn(v11);
                *(__half2*)(oH + i0) = hh0;
                *(__half2*)(oH + i1) = hh1;
            } else {  // EPI == 2, gelu -> fp16
                const float IS2 = 0.70710678118654752f;
                v00 = 0.5f * v00 * (1.f + erff(v00 * IS2));
                v01 = 0.5f * v01 * (1.f + erff(v01 * IS2));
                v10 = 0.5f * v10 * (1.f + erff(v10 * IS2));
                v11 = 0.5f * v11 * (1.f + erff(v11 * IS2));
                __half2 hh0; hh0.x = __float2half_rn(v00); hh0.y = __float2half_rn(v01);
                __half2 hh1; hh1.x = __float2half_rn(v10); hh1.y = __float2half_rn(v11);
                *(__half2*)(oH + i0) = hh0;
                *(__half2*)(oH + i1) = hh1;
            }
        }
    }
}

template <int EPI>
__global__ void __launch_bounds__(128, 6) mma_gemm(
    const hf* __restrict__ A, const hf* __restrict__ B,
    const float* __restrict__ bias, const float* __restrict__ res,
    float* __restrict__ Co, hf* __restrict__ oH,
    int N, int K)
{
    gemm_core<EPI>(A, B, bias, res, Co, oH, N, K, blockIdx.y, blockIdx.x);
}

// Merged Q + KV projection: blockIdx.x < 4 -> Q (N=256); else KV (N=512).
__global__ void __launch_bounds__(128, 6) proj_qkv(
    const hf* __restrict__ hh, const hf* __restrict__ kh,
    const hf* __restrict__ wq, const hf* __restrict__ wkv,
    const float* __restrict__ bq, const float* __restrict__ bkv,
    hf* __restrict__ qo, hf* __restrict__ kvo)
{
    if (blockIdx.x < 4) {
        gemm_core<3>(hh, wq, bq, nullptr, nullptr, qo,
                     Cc, Cc, blockIdx.y, blockIdx.x);
    } else {
        gemm_core<3>(kh, wkv, bkv, nullptr, nullptr, kvo,
                     2 * Cc, Cc, blockIdx.y, blockIdx.x - 4);
    }
}

// ---------------------------------------------------------------------------
// Launch
// ---------------------------------------------------------------------------
template <typename T>
static T* symaddr(const void* sym)
{
    void* p = nullptr;
    cudaGetSymbolAddress(&p, sym);
    return (T*)p;
}

extern "C" void kernel_launch(void* const* d_in, const int* in_sizes, int n_in,
                              void* d_out, int out_size)
{
    const float* x    = (const float*)d_in[0];
    const float* x_kv = (const float*)d_in[1];
    const float* Wq   = (const float*)d_in[2];
    const float* bq   = (const float*)d_in[3];
    const float* Wk   = (const float*)d_in[4];
    const float* bk   = (const float*)d_in[5];
    const float* Wv   = (const float*)d_in[6];
    const float* bv   = (const float*)d_in[7];
    const float* Wp   = (const float*)d_in[8];
    const float* bp   = (const float*)d_in[9];
    const float* g1   = (const float*)d_in[10];
    const float* b1   = (const float*)d_in[11];
    const float* g2   = (const float*)d_in[12];
    const float* b2   = (const float*)d_in[13];
    const float* W1   = (const float*)d_in[14];
    const float* bm1  = (const float*)d_in[15];
    const float* W2   = (const float*)d_in[16];
    const float* bm2  = (const float*)d_in[17];
    float* out = (float*)d_out;

    hf* hb  = symaddr<hf>(g_h);
    hf* hkb = symaddr<hf>(g_hk);
    hf* qb  = symaddr<hf>(g_q);
    hf* kvb = symaddr<hf>(g_kv);
    hf* atb = symaddr<hf>(g_at);
    float* x2 = symaddr<float>(g_x2);
    hf* mb  = symaddr<hf>(g_m);
    hf* tb  = symaddr<hf>(g_t);
    hf* wqT  = symaddr<hf>(g_wq);
    hf* wkvT = symaddr<hf>(g_wkv);
    hf* wpT  = symaddr<hf>(g_wp);
    hf* w1T  = symaddr<hf>(g_w1);
    hf* w2T  = symaddr<hf>(g_w2);
    float* bkv = symaddr<float>(g_bkv);

    static bool attrSet = false;
    if (!attrSet) {
        cudaFuncSetAttribute(mma_gemm<1>, cudaFuncAttributeMaxDynamicSharedMemorySize, SMTOT);
        cudaFuncSetAttribute(mma_gemm<2>, cudaFuncAttributeMaxDynamicSharedMemorySize, SMTOT);
        cudaFuncSetAttribute(proj_qkv,    cudaFuncAttributeMaxDynamicSharedMemorySize, SMTOT);
        cudaFuncSetAttribute(attn_tile,   cudaFuncAttributeMaxDynamicSharedMemorySize, ATT_SMEM);
        attrSet = true;
    }

    // Prep: weight transpose (fp16) + LN1(x, x_kv) + bkv concat (one launch)
    prep_all<<<768 + 2304, 256>>>(Wq, Wk, Wv, Wp, W1, W2,
                                  wqT,
                                  wkvT,                // Wk -> rows 0..255
                                  wkvT + Cc * Cc,      // Wv -> rows 256..511
                                  wpT, w1T, w2T,
                                  x, x_kv, g1, b1,
                                  hb, hkb,
                                  bk, bv, bkv);

    // Q + KV projections merged: grid (4+8) x 144 = 1728 CTAs (fp16 out)
    {
        dim3 g(12, ROWS / 64);
        proj_qkv<<<g, 128, SMTOT>>>(hb, hkb, wqT, wkvT, bq, bkv, qb, kvb);
    }

    // Tiled sparse attention (fp16 in/out)
    {
        dim3 ga(36, NH, Bb);
        attn_tile<<<ga, 256, ATT_SMEM>>>(qb, kvb, atb);
    }

    // x2 = x + att @ Wp + bp : grid 4 x 144 = 576 CTAs
    {
        dim3 grid(Cc / 64, ROWS / 64);
        mma_gemm<1><<<grid, 128, SMTOT>>>(atb, wpT, bp, x, x2, nullptr, Cc, Cc);
    }

    // LN2
    ln_kernel<<<ROWS / 8, 256>>>(x2, g2, b2, mb, ROWS);

    // MLP
    {
        dim3 grid1(HID / 64, ROWS / 64);
        mma_gemm<2><<<grid1, 128, SMTOT>>>(mb, w1T, bm1, nullptr, nullptr, tb, HID, Cc);
        dim3 grid2(Cc / 64, ROWS / 64);
        mma_gemm<1><<<grid2, 128, SMTOT>>>(tb, w2T, bm2, x2, out, nullptr, Cc, HID);
    }
}